// round 7
// baseline (speedup 1.0000x reference)
#include <cuda_runtime.h>
#include <cuda_bf16.h>
#include <cstdint>

#define NN   30
#define HH   4
#define CC   64
#define HC   256
#define FIN  64
#define NB   1024
#define EPG  240
#define NE   (NB*EPG)
#define NL   (NB*NN)
#define ET   (NE+NL)
#define EG   (EPG+NN)
#define OUT_LEN   (NB*144)
#define ALPHA_OFF OUT_LEN
#define ALPHA_LEN (ET*HH)
#define EI_OFF    (ALPHA_OFF+ALPHA_LEN)
#define EI_LEN    (2*ET)
#define LN_EPS 1e-5f
#define NSLOPE 0.2f
#define RS 40

typedef unsigned long long u64;

__device__ __forceinline__ u64 pk2(float a, float b){
    u64 r; asm("mov.b64 %0,{%1,%2};":"=l"(r):"f"(a),"f"(b)); return r;
}
__device__ __forceinline__ u64 f2fma(u64 a, u64 b, u64 c){
    u64 d; asm("fma.rn.f32x2 %0,%1,%2,%3;":"=l"(d):"l"(a),"l"(b),"l"(c)); return d;
}
__device__ __forceinline__ void upk(u64 v, float& lo, float& hi){
    asm("mov.b64 {%0,%1},%2;":"=f"(lo),"=f"(hi):"l"(v));
}

__device__ __forceinline__ void mma16816(float c[4], uint4 a, uint32_t b0, uint32_t b1){
    asm volatile("mma.sync.aligned.m16n8k16.row.col.f32.bf16.bf16.f32 "
        "{%0,%1,%2,%3},{%4,%5,%6,%7},{%8,%9},{%0,%1,%2,%3};"
        : "+f"(c[0]),"+f"(c[1]),"+f"(c[2]),"+f"(c[3])
        : "r"(a.x),"r"(a.y),"r"(a.z),"r"(a.w),"r"(b0),"r"(b1));
}

// ---------------- device scratch ----------------
__device__ float g_WlT[FIN*HC];
__device__ float g_WrT[FIN*HC];
__device__ float g_xl[NL*HC];
__device__ float g_xr[NL*HC];
__device__ float g_h [(size_t)NB*HC*RS];
__device__ float g_y0[(size_t)NB*256*RS];
__device__ float g_y1[(size_t)NB*512*RS];
__device__ float g_z [NB*HC*NN];
__device__ float g_z1[NB*512];
__device__ float g_z2[NB*256];
#define SK 4
__device__ float g_p1[SK*1024*512];

// A-fragment-packed weights (uint4 per lane per fragment)
__device__ uint4 g_A0H[24576], g_A0L[24576];   // L0 conv: 48 ksteps * 16 mtiles * 32 lanes
__device__ uint4 g_A1H[49152], g_A1L[49152];   // L1 conv: 48 * 32 * 32
__device__ uint4 g_D1H[16384], g_D1L[16384];   // ds1:     16 * 32 * 32
__device__ uint4 g_A2H[49152], g_A2L[49152];   // L2 conv: 96 * 16 * 32
__device__ uint4 g_D2H[16384], g_D2L[16384];   // ds2:     32 * 16 * 32

__device__ __forceinline__ uint32_t packbf(float v0, float v1, int lo){
    __nv_bfloat16 h0=__float2bfloat16(v0), h1=__float2bfloat16(v1);
    if (lo){ h0=__float2bfloat16(v0-__bfloat162float(h0)); h1=__float2bfloat16(v1-__bfloat162float(h1)); }
    return (uint32_t)__bfloat16_as_ushort(h0) | ((uint32_t)__bfloat16_as_ushort(h1)<<16);
}

__device__ void fill_convA(uint32_t* H, uint32_t* L, const float* w, int Cin, int MT, int nslots,
                           int t0, int stride)
{
    for (int i=t0;i<nslots;i+=stride){
        int q=i&3, lane=(i>>2)&31, mtg=(i>>7)%MT, kstep=i/(MT*128);
        int g=lane>>2, tc=lane&3;
        int m=mtg*16 + g + (q&1)*8;
        int kk=kstep*16 + (q>>1)*8 + tc*2;
        int t=kk/Cin, cin=kk-t*Cin;
        float v0=w[(m*Cin+cin)*3+t], v1=w[(m*Cin+cin+1)*3+t];
        H[i]=packbf(v0,v1,0); L[i]=packbf(v0,v1,1);
    }
}
__device__ void fill_dsA(uint32_t* H, uint32_t* L, const float* w, int Cin, int MT, int nslots,
                         int t0, int stride)
{
    for (int i=t0;i<nslots;i+=stride){
        int q=i&3, lane=(i>>2)&31, mtg=(i>>7)%MT, kstep=i/(MT*128);
        int g=lane>>2, tc=lane&3;
        int m=mtg*16 + g + (q&1)*8;
        int cin=kstep*16 + (q>>1)*8 + tc*2;
        float v0=w[m*Cin+cin], v1=w[m*Cin+cin+1];
        H[i]=packbf(v0,v1,0); L[i]=packbf(v0,v1,1);
    }
}

__global__ void prep_kernel(const float* __restrict__ Wl, const float* __restrict__ Wr,
                            const float* __restrict__ w0, const float* __restrict__ w1,
                            const float* __restrict__ w2, const float* __restrict__ d1,
                            const float* __restrict__ d2)
{
    int t0 = blockIdx.x*blockDim.x + threadIdx.x;
    int stride = gridDim.x*blockDim.x;
    for (int i=t0;i<FIN*HC;i+=stride){ int j=i%HC,k=i/HC; g_WlT[i]=Wl[j*FIN+k]; g_WrT[i]=Wr[j*FIN+k]; }
    fill_convA((uint32_t*)g_A0H,(uint32_t*)g_A0L, w0, 256, 16,  98304, t0, stride);
    fill_convA((uint32_t*)g_A1H,(uint32_t*)g_A1L, w1, 256, 32, 196608, t0, stride);
    fill_convA((uint32_t*)g_A2H,(uint32_t*)g_A2L, w2, 512, 16, 196608, t0, stride);
    fill_dsA  ((uint32_t*)g_D1H,(uint32_t*)g_D1L, d1, 256, 32,  65536, t0, stride);
    fill_dsA  ((uint32_t*)g_D2H,(uint32_t*)g_D2L, d2, 512, 16,  65536, t0, stride);
}

__global__ void __launch_bounds__(256) xform_kernel(const float* __restrict__ x,
                                                    const float* __restrict__ bl,
                                                    const float* __restrict__ br)
{
    __shared__ float xs[32*FIN];
    const int base = blockIdx.x*32;
    const int tid = threadIdx.x;
    for (int i=tid;i<32*FIN;i+=256) xs[i]=x[base*FIN+i];
    __syncthreads();
    float accl[32], accr[32];
#pragma unroll
    for (int n=0;n<32;n++){ accl[n]=0.f; accr[n]=0.f; }
    const int j = tid;
    for (int k=0;k<FIN;k++){
        float wl=g_WlT[k*HC+j], wr=g_WrT[k*HC+j];
#pragma unroll
        for (int n=0;n<32;n++){ float xv=xs[n*FIN+k]; accl[n]=fmaf(wl,xv,accl[n]); accr[n]=fmaf(wr,xv,accr[n]); }
    }
    float blv=bl[j], brv=br[j];
#pragma unroll
    for (int n=0;n<32;n++){
        g_xl[(base+n)*HC+j]=accl[n]+blv;
        g_xr[(base+n)*HC+j]=accr[n]+brv;
    }
}

#define ATTN_SMEM_BYTES (18272*4 + 901*4 + 16)
__global__ void __launch_bounds__(256) attn_kernel(const int* __restrict__ eidx,
                                                   const float* __restrict__ att,
                                                   const float* __restrict__ gbias,
                                                   float* __restrict__ out,
                                                   int write_alpha)
{
    extern __shared__ char smemraw[];
    float* xl_s   = (float*)smemraw;
    float* xr_s   = xl_s + 7680;
    float* att_s  = xr_s + 7680;
    float* bias_s = att_s + 256;
    float* esc    = bias_s + 256;
    float* alp    = esc + 1080;
    float* mmax   = alp + 1080;
    float* ssum   = mmax + 120;
    int*   srcl   = (int*)(ssum + 120);
    int*   dstl   = srcl + 270;
    int*   deg    = dstl + 270;
    int*   off    = deg + 30;
    int*   pos    = off + 31;
    int*   order  = pos + 30;
    const int b = blockIdx.x, tid = threadIdx.x;

    for (int i=tid;i<7680;i+=256){ xl_s[i]=g_xl[b*7680+i]; xr_s[i]=g_xr[b*7680+i]; }
    for (int i=tid;i<256;i+=256){ att_s[i]=att[i]; bias_s[i]=gbias[i]; }
    if (tid<30) deg[tid]=0;
    __syncthreads();
    for (int e=tid;e<EG;e+=256){
        int s,d;
        if (e<EPG){ s=eidx[b*EPG+e]-b*NN; d=eidx[NE+b*EPG+e]-b*NN; }
        else      { s=e-EPG; d=e-EPG; }
        srcl[e]=s; dstl[e]=d;
        atomicAdd(&deg[d],1);
    }
    __syncthreads();
    if (tid==0){ off[0]=0; for (int n=0;n<NN;n++) off[n+1]=off[n]+deg[n]; }
    __syncthreads();
    if (tid<30) pos[tid]=off[tid];
    __syncthreads();
    for (int e=tid;e<EG;e+=256){ int slot=atomicAdd(&pos[dstl[e]],1); order[slot]=e; }
    __syncthreads();
    for (int idx=tid; idx<EG*HH; idx+=256){
        int e=idx>>2, h=idx&3;
        const float* ps=&xl_s[srcl[e]*HC + h*CC];
        const float* pd=&xr_s[dstl[e]*HC + h*CC];
        const float* pa=&att_s[h*CC];
        float acc=0.f;
#pragma unroll 8
        for (int c=0;c<CC;c++){
            float v=ps[c]+pd[c];
            v = v>0.f ? v : NSLOPE*v;
            acc = fmaf(v, pa[c], acc);
        }
        esc[e*HH+h]=acc;
    }
    __syncthreads();
    for (int idx=tid; idx<NN*HH; idx+=256){
        int n=idx>>2, h=idx&3;
        float m=-1e30f;
        for (int i=off[n];i<off[n+1];i++) m=fmaxf(m, esc[order[i]*HH+h]);
        float s=0.f;
        for (int i=off[n];i<off[n+1];i++) s+=__expf(esc[order[i]*HH+h]-m);
        mmax[idx]=m; ssum[idx]=s;
    }
    __syncthreads();
    for (int idx=tid; idx<EG*HH; idx+=256){
        int e=idx>>2, h=idx&3;
        int d=dstl[e];
        float a=__expf(esc[e*HH+h]-mmax[d*HH+h])/ssum[d*HH+h];
        alp[e*HH+h]=a;
        if (write_alpha){
            int gid = (e<EPG) ? (b*EPG+e) : (NE + b*NN + (e-EPG));
            out[ALPHA_OFF + gid*HH + h]=a;
        }
    }
    __syncthreads();
    {
        const int j = tid;
        const int h = j>>6;
        for (int n=0;n<NN;n++){
            float acc=0.f;
            for (int i=off[n];i<off[n+1];i++){
                int e=order[i];
                acc = fmaf(alp[e*HH+h], xl_s[srcl[e]*HC+j], acc);
            }
            float v=acc+bias_s[j];
            xr_s[j*NN+n]=fmaxf(v,0.f);
        }
    }
    __syncthreads();
    for (int i=tid;i<256*RS;i+=256){
        int c=i/RS, col=i-c*RS;
        float v = (col>=4 && col<34) ? xr_s[c*NN + col-4] : 0.f;
        g_h[(size_t)b*256*RS + i]=v;
    }
}

// ================= mma.sync TCN conv layer (512 threads) =================
// CTA = 2 graphs. Warp w: graph nhalf=w&1 (4 n-fragments), mtile pair mtp=w>>1 (2 mtiles).
// MODE 0: Cin256->M256 d1 (+res). MODE 1: Cin256->M512 d2 (+ds). MODE 2: Cin512->M256 d4 (+ds), compact out.
#define CS 270
#define CONV_SMEM (2*2*40*CS*2)   // 86400B

template<int MODE>
__global__ void __launch_bounds__(512,1) conv_mma(
    const float* __restrict__ in,
    const uint4* __restrict__ AH, const uint4* __restrict__ AL,
    const uint4* __restrict__ DH, const uint4* __restrict__ DL,
    const float* __restrict__ db,
    const float* __restrict__ lnw, const float* __restrict__ lnb,
    float* __restrict__ outp)
{
    constexpr int Cin   = (MODE==2)?512:256;
    constexpr int COUT  = (MODE==1)?512:256;
    constexpr int MT    = (MODE==1)?32:16;
    constexpr int MP    = (MODE==1)?2:1;
    constexpr int PH    = (MODE==2)?2:1;
    constexpr int DIL   = (MODE==0)?1:((MODE==1)?2:4);
    constexpr bool HASDS= (MODE>=1);
    constexpr int KS_T  = Cin/16;
    constexpr int NT    = HASDS?4:3;

    extern __shared__ __nv_bfloat16 sm_bf[];
    __nv_bfloat16* sH = sm_bf;
    __nv_bfloat16* sL = sm_bf + 2*40*CS;
    __shared__ float s_lnw[32], s_lnb[32];

    const int tid=threadIdx.x, lane=tid&31, wid=tid>>5;
    const int g=lane>>2, tc=lane&3;
    const int b0=blockIdx.x*2;
    const int nhalf = wid&1;     // graph within CTA
    const int mtp   = wid>>1;    // mtile pair 0..7

    if (tid<30){ s_lnw[tid]=lnw[tid]; s_lnb[tid]=lnb[tid]; }

    for (int mp=0; mp<MP; mp++){
        float acc[2][4][4];
        float dsacc[2][4][4];
#pragma unroll
        for (int a=0;a<2;a++)
#pragma unroll
            for (int f=0;f<4;f++)
#pragma unroll
                for (int q=0;q<4;q++){ acc[a][f][q]=0.f; dsacc[a][f][q]=0.f; }

        for (int ph=0; ph<PH; ph++){
            if (mp==0){
                if (ph>0) __syncthreads();
                for (int idx=tid; idx<2*256*RS; idx+=512){
                    int gr = idx/(256*RS);
                    int r  = idx - gr*256*RS;
                    int c  = r/RS;
                    int l  = r - c*RS;
                    float v = in[(((size_t)(b0+gr))*Cin + ph*256 + c)*RS + l];
                    __nv_bfloat16 h=__float2bfloat16(v);
                    int sidx=(gr*40+l)*CS+c;
                    sH[sidx]=h;
                    sL[sidx]=__float2bfloat16(v-__bfloat162float(h));
                }
            }
            __syncthreads();

            const int mtile0 = mp*16 + mtp*2;
            for (int ch=0; ch<16; ch++){
                const int cin0 = ch*16;
#pragma unroll
                for (int t=0;t<NT;t++){
                    const bool isds = HASDS && (t==3);
                    uint4 ah0,ah1,al0,al1;
                    if (!isds){
                        const int kstep = t*KS_T + ph*16 + ch;
                        const int abase = (kstep*MT + mtile0)*32 + lane;
                        ah0=AH[abase]; ah1=AH[abase+32];
                        al0=AL[abase]; al1=AL[abase+32];
                    } else {
                        const int dbase = ((ph*16+ch)*MT + mtile0)*32 + lane;
                        ah0=DH[dbase]; ah1=DH[dbase+32];
                        al0=DL[dbase]; al1=DL[dbase+32];
                    }
                    const int shift = isds ? 0 : DIL*(t-1);
                    const int rowbase = nhalf*40 + 4 + shift;
#pragma unroll
                    for (int f=0; f<4; f++){
                        int row = rowbase + f*8 + g;
                        int sidx = row*CS + cin0 + tc*2;
                        uint32_t bh0=*(const uint32_t*)(sH+sidx);
                        uint32_t bh1=*(const uint32_t*)(sH+sidx+8);
                        uint32_t bl0=*(const uint32_t*)(sL+sidx);
                        uint32_t bl1=*(const uint32_t*)(sL+sidx+8);
                        if (!isds){
                            mma16816(acc[0][f], ah0, bh0,bh1);
                            mma16816(acc[1][f], ah1, bh0,bh1);
                            mma16816(acc[0][f], al0, bh0,bh1);
                            mma16816(acc[1][f], al1, bh0,bh1);
                            mma16816(acc[0][f], ah0, bl0,bl1);
                            mma16816(acc[1][f], ah1, bl0,bl1);
                        } else {
                            mma16816(dsacc[0][f], ah0, bh0,bh1);
                            mma16816(dsacc[1][f], ah1, bh0,bh1);
                            mma16816(dsacc[0][f], al0, bh0,bh1);
                            mma16816(dsacc[1][f], al1, bh0,bh1);
                            mma16816(dsacc[0][f], ah0, bl0,bl1);
                            mma16816(dsacc[1][f], ah1, bl0,bl1);
                        }
                    }
                }
            }
        }

        // ---- epilogue ----
        const int gr = nhalf;
#pragma unroll
        for (int mt=0; mt<2; mt++){
            const int mrow0 = mp*256 + (mtp*2+mt)*16 + g;
#pragma unroll
            for (int half=0; half<2; half++){
                const int mrow = mrow0 + half*8;
                float dbv = 0.f;
                if constexpr(HASDS) dbv = __ldg(&db[mrow]);
                float s=0.f;
#pragma unroll
                for (int f=0; f<4; f++)
#pragma unroll
                    for (int i=0;i<2;i++){
                        int l=f*8+tc*2+i;
                        if (l<30) s+=acc[mt][f][half*2+i];
                    }
                s += __shfl_xor_sync(0xffffffffu,s,1);
                s += __shfl_xor_sync(0xffffffffu,s,2);
                float mean = s*(1.f/30.f);
                float qv=0.f;
#pragma unroll
                for (int f=0; f<4; f++)
#pragma unroll
                    for (int i=0;i<2;i++){
                        int l=f*8+tc*2+i;
                        if (l<30){ float d=acc[mt][f][half*2+i]-mean; qv=fmaf(d,d,qv); }
                    }
                qv += __shfl_xor_sync(0xffffffffu,qv,1);
                qv += __shfl_xor_sync(0xffffffffu,qv,2);
                float rsn = rsqrtf(qv*(1.f/30.f)+LN_EPS);

                size_t rb;
                if constexpr(MODE==2) rb = (((size_t)(b0+gr))*256 + mrow)*(size_t)NN;
                else                  rb = (((size_t)(b0+gr))*COUT + mrow)*(size_t)RS;
#pragma unroll
                for (int f=0; f<4; f++){
                    int l0=f*8+tc*2;
                    if (l0>=30) continue;
                    float o0,o1;
                    {
                        float v=(acc[mt][f][half*2+0]-mean)*rsn*s_lnw[l0]+s_lnb[l0];
                        o0=fmaxf(v,0.f);
                        v=(acc[mt][f][half*2+1]-mean)*rsn*s_lnw[l0+1]+s_lnb[l0+1];
                        o1=fmaxf(v,0.f);
                    }
                    if constexpr(MODE==0){
                        float2 res=*(const float2*)&in[(((size_t)(b0+gr))*256 + mrow)*RS + 4 + l0];
                        o0+=res.x; o1+=res.y;
                    } else {
                        o0 += dsacc[mt][f][half*2+0] + dbv;
                        o1 += dsacc[mt][f][half*2+1] + dbv;
                    }
                    if constexpr(MODE==2) *(float2*)&outp[rb+l0]   = make_float2(o0,o1);
                    else                  *(float2*)&outp[rb+4+l0] = make_float2(o0,o1);
                }
                if constexpr(MODE!=2){
                    if (tc==0) *(float4*)&outp[rb] = make_float4(0.f,0.f,0.f,0.f);
                    if (tc==3){
                        *(float2*)&outp[rb+34]=make_float2(0.f,0.f);
                        *(float4*)&outp[rb+36]=make_float4(0.f,0.f,0.f,0.f);
                    }
                }
            }
        }
    }
}

// ================= fc1: split-K f32x2 GEMM =================
__global__ void __launch_bounds__(256,2) fc1_kernel(const float* __restrict__ A,
                                                    const float* __restrict__ W)
{
    __shared__ float2 sA[128][17];
    __shared__ float2 sW[64][17];
    const int tid=threadIdx.x;
    const int n0=blockIdx.x*64, m0=blockIdx.y*128, kz=blockIdx.z;
    const int ty=tid>>4, tx=tid&15;
    u64 acc[8][4];
    u64 z=pk2(0.f,0.f);
#pragma unroll
    for (int i=0;i<8;i++)
#pragma unroll
        for (int j=0;j<4;j++) acc[i][j]=z;
    const int kbase = kz*(7680/SK);
    for (int k0=0;k0<7680/SK;k0+=32){
#pragma unroll
        for (int q=0;q<4;q++){
            int idx=tid+q*256; int m=idx>>3, kq=idx&7;
            float4 v=*(const float4*)&A[(m0+m)*7680 + kbase+k0+4*kq];
            sA[m][2*kq]  =make_float2(v.x,v.y);
            sA[m][2*kq+1]=make_float2(v.z,v.w);
        }
#pragma unroll
        for (int q=0;q<2;q++){
            int idx=tid+q*256; int m=idx>>3, kq=idx&7;
            float4 v=*(const float4*)&W[(n0+m)*7680 + kbase+k0+4*kq];
            sW[m][2*kq]  =make_float2(v.x,v.y);
            sW[m][2*kq+1]=make_float2(v.z,v.w);
        }
        __syncthreads();
#pragma unroll
        for (int p=0;p<16;p++){
            u64 av[8], wv[4];
#pragma unroll
            for (int i=0;i<8;i++) av[i]=*(const u64*)&sA[ty+16*i][p];
#pragma unroll
            for (int j=0;j<4;j++) wv[j]=*(const u64*)&sW[tx+16*j][p];
#pragma unroll
            for (int i=0;i<8;i++)
#pragma unroll
                for (int j=0;j<4;j++) acc[i][j]=f2fma(av[i],wv[j],acc[i][j]);
        }
        __syncthreads();
    }
#pragma unroll
    for (int i=0;i<8;i++){
        int gm=m0+ty+16*i;
#pragma unroll
        for (int j=0;j<4;j++){
            int gn=n0+tx+16*j;
            float lo,hi; upk(acc[i][j],lo,hi);
            g_p1[(kz*1024+gm)*512+gn]=lo+hi;
        }
    }
}

__global__ void fc1red_kernel(const float* __restrict__ bias)
{
    int i=blockIdx.x*blockDim.x+threadIdx.x;
    float s=g_p1[i]+g_p1[524288+i]+g_p1[2*524288+i]+g_p1[3*524288+i];
    s+=bias[i&511];
    g_z1[i]=fmaxf(s,0.f);
}

__global__ void __launch_bounds__(256) gemm_kernel(const float* __restrict__ A,
                                                   const float* __restrict__ W,
                                                   const float* __restrict__ bias,
                                                   float* __restrict__ C,
                                                   int M, int N, int K, int relu)
{
    __shared__ float sA[64][17];
    __shared__ float sW[64][17];
    const int tid=threadIdx.x;
    const int m0=blockIdx.y*64, n0=blockIdx.x*64;
    const int tr=(tid/16)*4, tc=(tid%16)*4;
    float acc[4][4];
#pragma unroll
    for (int i=0;i<4;i++)
#pragma unroll
        for (int j=0;j<4;j++) acc[i][j]=0.f;
    for (int k0=0;k0<K;k0+=16){
        for (int i=tid;i<1024;i+=256){
            int k=i&15, r=i>>4;
            int gm=m0+r, gk=k0+k;
            sA[r][k]=(gm<M && gk<K)? A[gm*K+gk] : 0.f;
            int gn=n0+r;
            sW[r][k]=(gn<N && gk<K)? W[gn*K+gk] : 0.f;
        }
        __syncthreads();
#pragma unroll
        for (int k=0;k<16;k++){
            float a[4], w[4];
#pragma unroll
            for (int i=0;i<4;i++) a[i]=sA[tr+i][k];
#pragma unroll
            for (int j=0;j<4;j++) w[j]=sW[tc+j][k];
#pragma unroll
            for (int i=0;i<4;i++)
#pragma unroll
                for (int j=0;j<4;j++) acc[i][j]=fmaf(a[i],w[j],acc[i][j]);
        }
        __syncthreads();
    }
#pragma unroll
    for (int i=0;i<4;i++){
        int gm=m0+tr+i;
        if (gm>=M) continue;
#pragma unroll
        for (int j=0;j<4;j++){
            int gn=n0+tc+j;
            if (gn>=N) continue;
            float v=acc[i][j]+bias[gn];
            if (relu) v=fmaxf(v,0.f);
            C[gm*N+gn]=v;
        }
    }
}

__global__ void ei_kernel(const int* __restrict__ eidx, float* __restrict__ out)
{
    int e=blockIdx.x*blockDim.x+threadIdx.x;
    if (e>=ET) return;
    int s,d;
    if (e<NE){ s=eidx[e]; d=eidx[NE+e]; }
    else { s=e-NE; d=e-NE; }
    out[EI_OFF+e]    =(float)s;
    out[EI_OFF+ET+e] =(float)d;
}

extern "C" void kernel_launch(void* const* d_in, const int* in_sizes, int n_in,
                              void* d_out, int out_size)
{
    const float* x      =(const float*)d_in[0];
    const float* gat_Wl =(const float*)d_in[1];
    const float* gat_bl =(const float*)d_in[2];
    const float* gat_Wr =(const float*)d_in[3];
    const float* gat_br =(const float*)d_in[4];
    const float* gat_att=(const float*)d_in[5];
    const float* gat_bias=(const float*)d_in[6];
    const float* tcn0_w =(const float*)d_in[7];
    const float* ln0_w  =(const float*)d_in[9];
    const float* ln0_b  =(const float*)d_in[10];
    const float* tcn1_w =(const float*)d_in[11];
    const float* ln1_w  =(const float*)d_in[13];
    const float* ln1_b  =(const float*)d_in[14];
    const float* ds1_w  =(const float*)d_in[15];
    const float* ds1_b  =(const float*)d_in[16];
    const float* tcn2_w =(const float*)d_in[17];
    const float* ln2_w  =(const float*)d_in[19];
    const float* ln2_b  =(const float*)d_in[20];
    const float* ds2_w  =(const float*)d_in[21];
    const float* ds2_b  =(const float*)d_in[22];
    const float* fc1_w  =(const float*)d_in[23];
    const float* fc1_b  =(const float*)d_in[24];
    const float* fc2_w  =(const float*)d_in[25];
    const float* fc2_b  =(const float*)d_in[26];
    const float* fc3_w  =(const float*)d_in[27];
    const float* fc3_b  =(const float*)d_in[28];
    const int*   edge   =(const int*)d_in[29];
    float* out=(float*)d_out;

    cudaFuncSetAttribute(attn_kernel, cudaFuncAttributeMaxDynamicSharedMemorySize, ATTN_SMEM_BYTES);
    cudaFuncSetAttribute(conv_mma<0>, cudaFuncAttributeMaxDynamicSharedMemorySize, CONV_SMEM);
    cudaFuncSetAttribute(conv_mma<1>, cudaFuncAttributeMaxDynamicSharedMemorySize, CONV_SMEM);
    cudaFuncSetAttribute(conv_mma<2>, cudaFuncAttributeMaxDynamicSharedMemorySize, CONV_SMEM);

    prep_kernel<<<1024,256>>>(gat_Wl, gat_Wr, tcn0_w, tcn1_w, tcn2_w, ds1_w, ds2_w);
    xform_kernel<<<NL/32,256>>>(x, gat_bl, gat_br);

    int write_alpha = (out_size >= ALPHA_OFF + ALPHA_LEN) ? 1 : 0;
    attn_kernel<<<NB,256,ATTN_SMEM_BYTES>>>(edge, gat_att, gat_bias, out, write_alpha);

    void *ph=nullptr,*py0=nullptr,*py1=nullptr,*pz=nullptr,*pz1=nullptr,*pz2=nullptr;
    void *a0h,*a0l,*a1h,*a1l,*a2h,*a2l,*d1h,*d1l,*d2h,*d2l;
    cudaGetSymbolAddress(&ph,  g_h);  cudaGetSymbolAddress(&py0, g_y0);
    cudaGetSymbolAddress(&py1, g_y1); cudaGetSymbolAddress(&pz,  g_z);
    cudaGetSymbolAddress(&pz1, g_z1); cudaGetSymbolAddress(&pz2, g_z2);
    cudaGetSymbolAddress(&a0h, g_A0H); cudaGetSymbolAddress(&a0l, g_A0L);
    cudaGetSymbolAddress(&a1h, g_A1H); cudaGetSymbolAddress(&a1l, g_A1L);
    cudaGetSymbolAddress(&a2h, g_A2H); cudaGetSymbolAddress(&a2l, g_A2L);
    cudaGetSymbolAddress(&d1h, g_D1H); cudaGetSymbolAddress(&d1l, g_D1L);
    cudaGetSymbolAddress(&d2h, g_D2H); cudaGetSymbolAddress(&d2l, g_D2L);

    conv_mma<0><<<NB/2,512,CONV_SMEM>>>((const float*)ph,
        (const uint4*)a0h,(const uint4*)a0l,(const uint4*)a0h,(const uint4*)a0l,
        nullptr, ln0_w, ln0_b, (float*)py0);
    conv_mma<1><<<NB/2,512,CONV_SMEM>>>((const float*)py0,
        (const uint4*)a1h,(const uint4*)a1l,(const uint4*)d1h,(const uint4*)d1l,
        ds1_b, ln1_w, ln1_b, (float*)py1);
    conv_mma<2><<<NB/2,512,CONV_SMEM>>>((const float*)py1,
        (const uint4*)a2h,(const uint4*)a2l,(const uint4*)d2h,(const uint4*)d2l,
        ds2_b, ln2_w, ln2_b, (float*)pz);

    fc1_kernel<<<dim3(8,8,SK),256>>>((const float*)pz, fc1_w);
    fc1red_kernel<<<(1024*512)/256,256>>>(fc1_b);

    gemm_kernel<<<dim3(256/64, NB/64),256>>>((const float*)pz1, fc2_w, fc2_b, (float*)pz2, NB, 256, 512, 1);
    gemm_kernel<<<dim3((144+63)/64, NB/64),256>>>((const float*)pz2, fc3_w, fc3_b, out, NB, 144, 256, 0);

    if (out_size >= EI_OFF + EI_LEN)
        ei_kernel<<<(ET+255)/256,256>>>(edge, out);
}

// round 8
// speedup vs baseline: 1.0221x; 1.0221x over previous
#include <cuda_runtime.h>
#include <cuda_bf16.h>
#include <cstdint>

#define NN   30
#define HH   4
#define CC   64
#define HC   256
#define FIN  64
#define NB   1024
#define EPG  240
#define NE   (NB*EPG)
#define NL   (NB*NN)
#define ET   (NE+NL)
#define EG   (EPG+NN)
#define OUT_LEN   (NB*144)
#define ALPHA_OFF OUT_LEN
#define ALPHA_LEN (ET*HH)
#define EI_OFF    (ALPHA_OFF+ALPHA_LEN)
#define EI_LEN    (2*ET)
#define LN_EPS 1e-5f
#define NSLOPE 0.2f
#define RS 40

typedef unsigned long long u64;

__device__ __forceinline__ u64 pk2(float a, float b){
    u64 r; asm("mov.b64 %0,{%1,%2};":"=l"(r):"f"(a),"f"(b)); return r;
}
__device__ __forceinline__ u64 f2fma(u64 a, u64 b, u64 c){
    u64 d; asm("fma.rn.f32x2 %0,%1,%2,%3;":"=l"(d):"l"(a),"l"(b),"l"(c)); return d;
}
__device__ __forceinline__ void upk(u64 v, float& lo, float& hi){
    asm("mov.b64 {%0,%1},%2;":"=f"(lo),"=f"(hi):"l"(v));
}

__device__ __forceinline__ void mma16816(float c[4], uint4 a, uint32_t b0, uint32_t b1){
    asm volatile("mma.sync.aligned.m16n8k16.row.col.f32.bf16.bf16.f32 "
        "{%0,%1,%2,%3},{%4,%5,%6,%7},{%8,%9},{%0,%1,%2,%3};"
        : "+f"(c[0]),"+f"(c[1]),"+f"(c[2]),"+f"(c[3])
        : "r"(a.x),"r"(a.y),"r"(a.z),"r"(a.w),"r"(b0),"r"(b1));
}

// ---------------- device scratch ----------------
__device__ float g_WlT[FIN*HC];
__device__ float g_WrT[FIN*HC];
__device__ float g_xl[NL*HC];
__device__ float g_xr[NL*HC];
__device__ float g_h [(size_t)NB*HC*RS];
__device__ float g_y0[(size_t)NB*256*RS];
__device__ float g_y1[(size_t)NB*512*RS];
__device__ float g_z [NB*HC*NN];
__device__ float g_z1[NB*512];
__device__ float g_z2[NB*256];
#define SK 4
__device__ float g_p1[SK*1024*512];

// A-fragment-packed weights (uint4 per lane per fragment)
__device__ uint4 g_A0H[24576], g_A0L[24576];
__device__ uint4 g_A1H[49152], g_A1L[49152];
__device__ uint4 g_D1H[16384], g_D1L[16384];
__device__ uint4 g_A2H[49152], g_A2L[49152];
__device__ uint4 g_D2H[16384], g_D2L[16384];

__device__ __forceinline__ uint32_t packbf(float v0, float v1, int lo){
    __nv_bfloat16 h0=__float2bfloat16(v0), h1=__float2bfloat16(v1);
    if (lo){ h0=__float2bfloat16(v0-__bfloat162float(h0)); h1=__float2bfloat16(v1-__bfloat162float(h1)); }
    return (uint32_t)__bfloat16_as_ushort(h0) | ((uint32_t)__bfloat16_as_ushort(h1)<<16);
}

__device__ void fill_convA(uint32_t* H, uint32_t* L, const float* w, int Cin, int MT, int nslots,
                           int t0, int stride)
{
    for (int i=t0;i<nslots;i+=stride){
        int q=i&3, lane=(i>>2)&31, mtg=(i>>7)%MT, kstep=i/(MT*128);
        int g=lane>>2, tc=lane&3;
        int m=mtg*16 + g + (q&1)*8;
        int kk=kstep*16 + (q>>1)*8 + tc*2;
        int t=kk/Cin, cin=kk-t*Cin;
        float v0=w[(m*Cin+cin)*3+t], v1=w[(m*Cin+cin+1)*3+t];
        H[i]=packbf(v0,v1,0); L[i]=packbf(v0,v1,1);
    }
}
__device__ void fill_dsA(uint32_t* H, uint32_t* L, const float* w, int Cin, int MT, int nslots,
                         int t0, int stride)
{
    for (int i=t0;i<nslots;i+=stride){
        int q=i&3, lane=(i>>2)&31, mtg=(i>>7)%MT, kstep=i/(MT*128);
        int g=lane>>2, tc=lane&3;
        int m=mtg*16 + g + (q&1)*8;
        int cin=kstep*16 + (q>>1)*8 + tc*2;
        float v0=w[m*Cin+cin], v1=w[m*Cin+cin+1];
        H[i]=packbf(v0,v1,0); L[i]=packbf(v0,v1,1);
    }
}

__global__ void prep_kernel(const float* __restrict__ Wl, const float* __restrict__ Wr,
                            const float* __restrict__ w0, const float* __restrict__ w1,
                            const float* __restrict__ w2, const float* __restrict__ d1,
                            const float* __restrict__ d2)
{
    int t0 = blockIdx.x*blockDim.x + threadIdx.x;
    int stride = gridDim.x*blockDim.x;
    for (int i=t0;i<FIN*HC;i+=stride){ int j=i%HC,k=i/HC; g_WlT[i]=Wl[j*FIN+k]; g_WrT[i]=Wr[j*FIN+k]; }
    fill_convA((uint32_t*)g_A0H,(uint32_t*)g_A0L, w0, 256, 16,  98304, t0, stride);
    fill_convA((uint32_t*)g_A1H,(uint32_t*)g_A1L, w1, 256, 32, 196608, t0, stride);
    fill_convA((uint32_t*)g_A2H,(uint32_t*)g_A2L, w2, 512, 16, 196608, t0, stride);
    fill_dsA  ((uint32_t*)g_D1H,(uint32_t*)g_D1L, d1, 256, 32,  65536, t0, stride);
    fill_dsA  ((uint32_t*)g_D2H,(uint32_t*)g_D2L, d2, 512, 16,  65536, t0, stride);
}

__global__ void __launch_bounds__(256) xform_kernel(const float* __restrict__ x,
                                                    const float* __restrict__ bl,
                                                    const float* __restrict__ br)
{
    __shared__ float xs[32*FIN];
    const int base = blockIdx.x*32;
    const int tid = threadIdx.x;
    for (int i=tid;i<32*FIN;i+=256) xs[i]=x[base*FIN+i];
    __syncthreads();
    float accl[32], accr[32];
#pragma unroll
    for (int n=0;n<32;n++){ accl[n]=0.f; accr[n]=0.f; }
    const int j = tid;
    for (int k=0;k<FIN;k++){
        float wl=g_WlT[k*HC+j], wr=g_WrT[k*HC+j];
#pragma unroll
        for (int n=0;n<32;n++){ float xv=xs[n*FIN+k]; accl[n]=fmaf(wl,xv,accl[n]); accr[n]=fmaf(wr,xv,accr[n]); }
    }
    float blv=bl[j], brv=br[j];
#pragma unroll
    for (int n=0;n<32;n++){
        g_xl[(base+n)*HC+j]=accl[n]+blv;
        g_xr[(base+n)*HC+j]=accr[n]+brv;
    }
}

#define ATTN_SMEM_BYTES (18272*4 + 901*4 + 16)
__global__ void __launch_bounds__(256) attn_kernel(const int* __restrict__ eidx,
                                                   const float* __restrict__ att,
                                                   const float* __restrict__ gbias,
                                                   float* __restrict__ out,
                                                   int write_alpha)
{
    extern __shared__ char smemraw[];
    float* xl_s   = (float*)smemraw;
    float* xr_s   = xl_s + 7680;
    float* att_s  = xr_s + 7680;
    float* bias_s = att_s + 256;
    float* esc    = bias_s + 256;
    float* alp    = esc + 1080;
    float* mmax   = alp + 1080;
    float* ssum   = mmax + 120;
    int*   srcl   = (int*)(ssum + 120);
    int*   dstl   = srcl + 270;
    int*   deg    = dstl + 270;
    int*   off    = deg + 30;
    int*   pos    = off + 31;
    int*   order  = pos + 30;
    const int b = blockIdx.x, tid = threadIdx.x;

    for (int i=tid;i<7680;i+=256){ xl_s[i]=g_xl[b*7680+i]; xr_s[i]=g_xr[b*7680+i]; }
    for (int i=tid;i<256;i+=256){ att_s[i]=att[i]; bias_s[i]=gbias[i]; }
    if (tid<30) deg[tid]=0;
    __syncthreads();
    for (int e=tid;e<EG;e+=256){
        int s,d;
        if (e<EPG){ s=eidx[b*EPG+e]-b*NN; d=eidx[NE+b*EPG+e]-b*NN; }
        else      { s=e-EPG; d=e-EPG; }
        srcl[e]=s; dstl[e]=d;
        atomicAdd(&deg[d],1);
    }
    __syncthreads();
    if (tid==0){ off[0]=0; for (int n=0;n<NN;n++) off[n+1]=off[n]+deg[n]; }
    __syncthreads();
    if (tid<30) pos[tid]=off[tid];
    __syncthreads();
    for (int e=tid;e<EG;e+=256){ int slot=atomicAdd(&pos[dstl[e]],1); order[slot]=e; }
    __syncthreads();
    for (int idx=tid; idx<EG*HH; idx+=256){
        int e=idx>>2, h=idx&3;
        const float* ps=&xl_s[srcl[e]*HC + h*CC];
        const float* pd=&xr_s[dstl[e]*HC + h*CC];
        const float* pa=&att_s[h*CC];
        float acc=0.f;
#pragma unroll 8
        for (int c=0;c<CC;c++){
            float v=ps[c]+pd[c];
            v = v>0.f ? v : NSLOPE*v;
            acc = fmaf(v, pa[c], acc);
        }
        esc[e*HH+h]=acc;
    }
    __syncthreads();
    for (int idx=tid; idx<NN*HH; idx+=256){
        int n=idx>>2, h=idx&3;
        float m=-1e30f;
        for (int i=off[n];i<off[n+1];i++) m=fmaxf(m, esc[order[i]*HH+h]);
        float s=0.f;
        for (int i=off[n];i<off[n+1];i++) s+=__expf(esc[order[i]*HH+h]-m);
        mmax[idx]=m; ssum[idx]=s;
    }
    __syncthreads();
    for (int idx=tid; idx<EG*HH; idx+=256){
        int e=idx>>2, h=idx&3;
        int d=dstl[e];
        float a=__expf(esc[e*HH+h]-mmax[d*HH+h])/ssum[d*HH+h];
        alp[e*HH+h]=a;
        if (write_alpha){
            int gid = (e<EPG) ? (b*EPG+e) : (NE + b*NN + (e-EPG));
            out[ALPHA_OFF + gid*HH + h]=a;
        }
    }
    __syncthreads();
    {
        const int j = tid;
        const int h = j>>6;
        for (int n=0;n<NN;n++){
            float acc=0.f;
            for (int i=off[n];i<off[n+1];i++){
                int e=order[i];
                acc = fmaf(alp[e*HH+h], xl_s[srcl[e]*HC+j], acc);
            }
            float v=acc+bias_s[j];
            xr_s[j*NN+n]=fmaxf(v,0.f);
        }
    }
    __syncthreads();
    for (int i=tid;i<256*RS;i+=256){
        int c=i/RS, col=i-c*RS;
        float v = (col>=4 && col<34) ? xr_s[c*NN + col-4] : 0.f;
        g_h[(size_t)b*256*RS + i]=v;
    }
}

// ================= mma.sync TCN conv layer (512 threads, A-prefetch) =================
#define CS 270
#define CONV_SMEM (2*2*40*CS*2)   // 86400B

template<int MODE>
__global__ void __launch_bounds__(512,1) conv_mma(
    const float* __restrict__ in,
    const uint4* __restrict__ AH, const uint4* __restrict__ AL,
    const uint4* __restrict__ DH, const uint4* __restrict__ DL,
    const float* __restrict__ db,
    const float* __restrict__ lnw, const float* __restrict__ lnb,
    float* __restrict__ outp)
{
    constexpr int Cin   = (MODE==2)?512:256;
    constexpr int COUT  = (MODE==1)?512:256;
    constexpr int MT    = (MODE==1)?32:16;
    constexpr int MP    = (MODE==1)?2:1;
    constexpr int PH    = (MODE==2)?2:1;
    constexpr int DIL   = (MODE==0)?1:((MODE==1)?2:4);
    constexpr bool HASDS= (MODE>=1);
    constexpr int KS_T  = Cin/16;
    constexpr int NT    = HASDS?4:3;
    constexpr int NIT   = 16*NT;
    constexpr bool SPLITC = (MODE==0);   // separate correction accumulators

    extern __shared__ __nv_bfloat16 sm_bf[];
    __nv_bfloat16* sH = sm_bf;
    __nv_bfloat16* sL = sm_bf + 2*40*CS;
    __shared__ float s_lnw[32], s_lnb[32];

    const int tid=threadIdx.x, lane=tid&31, wid=tid>>5;
    const int g=lane>>2, tc=lane&3;
    const int b0=blockIdx.x*2;
    const int nhalf = wid&1;
    const int mtp   = wid>>1;

    if (tid<30){ s_lnw[tid]=lnw[tid]; s_lnb[tid]=lnb[tid]; }

    for (int mp=0; mp<MP; mp++){
        float acc[2][4][4];
        float acl[SPLITC?2:1][SPLITC?4:1][SPLITC?4:1];
        float dsacc[2][4][4];
#pragma unroll
        for (int a=0;a<2;a++)
#pragma unroll
            for (int f=0;f<4;f++)
#pragma unroll
                for (int q=0;q<4;q++){ acc[a][f][q]=0.f; dsacc[a][f][q]=0.f; }
        if constexpr(SPLITC){
#pragma unroll
            for (int a=0;a<2;a++)
#pragma unroll
                for (int f=0;f<4;f++)
#pragma unroll
                    for (int q=0;q<4;q++) acl[a][f][q]=0.f;
        }

        for (int ph=0; ph<PH; ph++){
            if (mp==0){
                if (ph>0) __syncthreads();
                for (int idx=tid; idx<2*256*RS; idx+=512){
                    int gr = idx/(256*RS);
                    int r  = idx - gr*256*RS;
                    int c  = r/RS;
                    int l  = r - c*RS;
                    float v = in[(((size_t)(b0+gr))*Cin + ph*256 + c)*RS + l];
                    __nv_bfloat16 h=__float2bfloat16(v);
                    int sidx=(gr*40+l)*CS+c;
                    sH[sidx]=h;
                    sL[sidx]=__float2bfloat16(v-__bfloat162float(h));
                }
            }
            __syncthreads();

            const int mtile0 = mp*16 + mtp*2;

            auto afetch = [&](int it, uint4&h0, uint4&h1, uint4&l0, uint4&l1){
                int ch = it/NT, t = it-ch*NT;
                bool isds = HASDS && (t==3);
                const uint4 *PHp, *PLp; int base;
                if (!isds){
                    int kstep = t*KS_T + ph*16 + ch;
                    base = (kstep*MT + mtile0)*32 + lane;
                    PHp=AH; PLp=AL;
                } else {
                    base = ((ph*16+ch)*MT + mtile0)*32 + lane;
                    PHp=DH; PLp=DL;
                }
                h0=PHp[base]; h1=PHp[base+32]; l0=PLp[base]; l1=PLp[base+32];
            };

            uint4 ah0,ah1,al0,al1, nh0,nh1,nl0,nl1;
            afetch(0, ah0,ah1,al0,al1);

            for (int it=0; it<NIT; it++){
                if (it+1<NIT) afetch(it+1, nh0,nh1,nl0,nl1);
                int ch = it/NT, t = it-ch*NT;
                bool isds = HASDS && (t==3);
                const int shift = isds ? 0 : DIL*(t-1);
                const int rowbase = nhalf*40 + 4 + shift;
                const int cin0 = ch*16;
#pragma unroll
                for (int f=0; f<4; f++){
                    int row = rowbase + f*8 + g;
                    int sidx = row*CS + cin0 + tc*2;
                    uint32_t bh0=*(const uint32_t*)(sH+sidx);
                    uint32_t bh1=*(const uint32_t*)(sH+sidx+8);
                    uint32_t bl0=*(const uint32_t*)(sL+sidx);
                    uint32_t bl1=*(const uint32_t*)(sL+sidx+8);
                    if (!isds){
                        mma16816(acc[0][f], ah0, bh0,bh1);
                        mma16816(acc[1][f], ah1, bh0,bh1);
                        if constexpr(SPLITC){
                            mma16816(acl[0][f], al0, bh0,bh1);
                            mma16816(acl[1][f], al1, bh0,bh1);
                            mma16816(acl[0][f], ah0, bl0,bl1);
                            mma16816(acl[1][f], ah1, bl0,bl1);
                        } else {
                            mma16816(acc[0][f], al0, bh0,bh1);
                            mma16816(acc[1][f], al1, bh0,bh1);
                            mma16816(acc[0][f], ah0, bl0,bl1);
                            mma16816(acc[1][f], ah1, bl0,bl1);
                        }
                    } else {
                        mma16816(dsacc[0][f], ah0, bh0,bh1);
                        mma16816(dsacc[1][f], ah1, bh0,bh1);
                        mma16816(dsacc[0][f], al0, bh0,bh1);
                        mma16816(dsacc[1][f], al1, bh0,bh1);
                        mma16816(dsacc[0][f], ah0, bl0,bl1);
                        mma16816(dsacc[1][f], ah1, bl0,bl1);
                    }
                }
                ah0=nh0; ah1=nh1; al0=nl0; al1=nl1;
            }
        }

        // ---- epilogue ----
        if constexpr(SPLITC){
#pragma unroll
            for (int a=0;a<2;a++)
#pragma unroll
                for (int f=0;f<4;f++)
#pragma unroll
                    for (int q=0;q<4;q++) acc[a][f][q]+=acl[a][f][q];
        }
        const int gr = nhalf;
#pragma unroll
        for (int mt=0; mt<2; mt++){
            const int mrow0 = mp*256 + (mtp*2+mt)*16 + g;
#pragma unroll
            for (int half=0; half<2; half++){
                const int mrow = mrow0 + half*8;
                float dbv = 0.f;
                if constexpr(HASDS) dbv = __ldg(&db[mrow]);
                float s=0.f;
#pragma unroll
                for (int f=0; f<4; f++)
#pragma unroll
                    for (int i=0;i<2;i++){
                        int l=f*8+tc*2+i;
                        if (l<30) s+=acc[mt][f][half*2+i];
                    }
                s += __shfl_xor_sync(0xffffffffu,s,1);
                s += __shfl_xor_sync(0xffffffffu,s,2);
                float mean = s*(1.f/30.f);
                float qv=0.f;
#pragma unroll
                for (int f=0; f<4; f++)
#pragma unroll
                    for (int i=0;i<2;i++){
                        int l=f*8+tc*2+i;
                        if (l<30){ float d=acc[mt][f][half*2+i]-mean; qv=fmaf(d,d,qv); }
                    }
                qv += __shfl_xor_sync(0xffffffffu,qv,1);
                qv += __shfl_xor_sync(0xffffffffu,qv,2);
                float rsn = rsqrtf(qv*(1.f/30.f)+LN_EPS);

                size_t rb;
                if constexpr(MODE==2) rb = (((size_t)(b0+gr))*256 + mrow)*(size_t)NN;
                else                  rb = (((size_t)(b0+gr))*COUT + mrow)*(size_t)RS;
#pragma unroll
                for (int f=0; f<4; f++){
                    int l0=f*8+tc*2;
                    if (l0>=30) continue;
                    float o0,o1;
                    {
                        float v=(acc[mt][f][half*2+0]-mean)*rsn*s_lnw[l0]+s_lnb[l0];
                        o0=fmaxf(v,0.f);
                        v=(acc[mt][f][half*2+1]-mean)*rsn*s_lnw[l0+1]+s_lnb[l0+1];
                        o1=fmaxf(v,0.f);
                    }
                    if constexpr(MODE==0){
                        float2 res=*(const float2*)&in[(((size_t)(b0+gr))*256 + mrow)*RS + 4 + l0];
                        o0+=res.x; o1+=res.y;
                    } else {
                        o0 += dsacc[mt][f][half*2+0] + dbv;
                        o1 += dsacc[mt][f][half*2+1] + dbv;
                    }
                    if constexpr(MODE==2) *(float2*)&outp[rb+l0]   = make_float2(o0,o1);
                    else                  *(float2*)&outp[rb+4+l0] = make_float2(o0,o1);
                }
                if constexpr(MODE!=2){
                    if (tc==0) *(float4*)&outp[rb] = make_float4(0.f,0.f,0.f,0.f);
                    if (tc==3){
                        *(float2*)&outp[rb+34]=make_float2(0.f,0.f);
                        *(float4*)&outp[rb+36]=make_float4(0.f,0.f,0.f,0.f);
                    }
                }
            }
        }
    }
}

// ================= fc1: split-K f32x2 GEMM =================
__global__ void __launch_bounds__(256,2) fc1_kernel(const float* __restrict__ A,
                                                    const float* __restrict__ W)
{
    __shared__ float2 sA[128][17];
    __shared__ float2 sW[64][17];
    const int tid=threadIdx.x;
    const int n0=blockIdx.x*64, m0=blockIdx.y*128, kz=blockIdx.z;
    const int ty=tid>>4, tx=tid&15;
    u64 acc[8][4];
    u64 z=pk2(0.f,0.f);
#pragma unroll
    for (int i=0;i<8;i++)
#pragma unroll
        for (int j=0;j<4;j++) acc[i][j]=z;
    const int kbase = kz*(7680/SK);
    for (int k0=0;k0<7680/SK;k0+=32){
#pragma unroll
        for (int q=0;q<4;q++){
            int idx=tid+q*256; int m=idx>>3, kq=idx&7;
            float4 v=*(const float4*)&A[(m0+m)*7680 + kbase+k0+4*kq];
            sA[m][2*kq]  =make_float2(v.x,v.y);
            sA[m][2*kq+1]=make_float2(v.z,v.w);
        }
#pragma unroll
        for (int q=0;q<2;q++){
            int idx=tid+q*256; int m=idx>>3, kq=idx&7;
            float4 v=*(const float4*)&W[(n0+m)*7680 + kbase+k0+4*kq];
            sW[m][2*kq]  =make_float2(v.x,v.y);
            sW[m][2*kq+1]=make_float2(v.z,v.w);
        }
        __syncthreads();
#pragma unroll
        for (int p=0;p<16;p++){
            u64 av[8], wv[4];
#pragma unroll
            for (int i=0;i<8;i++) av[i]=*(const u64*)&sA[ty+16*i][p];
#pragma unroll
            for (int j=0;j<4;j++) wv[j]=*(const u64*)&sW[tx+16*j][p];
#pragma unroll
            for (int i=0;i<8;i++)
#pragma unroll
                for (int j=0;j<4;j++) acc[i][j]=f2fma(av[i],wv[j],acc[i][j]);
        }
        __syncthreads();
    }
#pragma unroll
    for (int i=0;i<8;i++){
        int gm=m0+ty+16*i;
#pragma unroll
        for (int j=0;j<4;j++){
            int gn=n0+tx+16*j;
            float lo,hi; upk(acc[i][j],lo,hi);
            g_p1[(kz*1024+gm)*512+gn]=lo+hi;
        }
    }
}

__global__ void fc1red_kernel(const float* __restrict__ bias)
{
    int i=blockIdx.x*blockDim.x+threadIdx.x;
    float s=g_p1[i]+g_p1[524288+i]+g_p1[2*524288+i]+g_p1[3*524288+i];
    s+=bias[i&511];
    g_z1[i]=fmaxf(s,0.f);
}

__global__ void __launch_bounds__(256) gemm_kernel(const float* __restrict__ A,
                                                   const float* __restrict__ W,
                                                   const float* __restrict__ bias,
                                                   float* __restrict__ C,
                                                   int M, int N, int K, int relu)
{
    __shared__ float sA[64][17];
    __shared__ float sW[64][17];
    const int tid=threadIdx.x;
    const int m0=blockIdx.y*64, n0=blockIdx.x*64;
    const int tr=(tid/16)*4, tc=(tid%16)*4;
    float acc[4][4];
#pragma unroll
    for (int i=0;i<4;i++)
#pragma unroll
        for (int j=0;j<4;j++) acc[i][j]=0.f;
    for (int k0=0;k0<K;k0+=16){
        for (int i=tid;i<1024;i+=256){
            int k=i&15, r=i>>4;
            int gm=m0+r, gk=k0+k;
            sA[r][k]=(gm<M && gk<K)? A[gm*K+gk] : 0.f;
            int gn=n0+r;
            sW[r][k]=(gn<N && gk<K)? W[gn*K+gk] : 0.f;
        }
        __syncthreads();
#pragma unroll
        for (int k=0;k<16;k++){
            float a[4], w[4];
#pragma unroll
            for (int i=0;i<4;i++) a[i]=sA[tr+i][k];
#pragma unroll
            for (int j=0;j<4;j++) w[j]=sW[tc+j][k];
#pragma unroll
            for (int i=0;i<4;i++)
#pragma unroll
                for (int j=0;j<4;j++) acc[i][j]=fmaf(a[i],w[j],acc[i][j]);
        }
        __syncthreads();
    }
#pragma unroll
    for (int i=0;i<4;i++){
        int gm=m0+tr+i;
        if (gm>=M) continue;
#pragma unroll
        for (int j=0;j<4;j++){
            int gn=n0+tc+j;
            if (gn>=N) continue;
            float v=acc[i][j]+bias[gn];
            if (relu) v=fmaxf(v,0.f);
            C[gm*N+gn]=v;
        }
    }
}

__global__ void ei_kernel(const int* __restrict__ eidx, float* __restrict__ out)
{
    int e=blockIdx.x*blockDim.x+threadIdx.x;
    if (e>=ET) return;
    int s,d;
    if (e<NE){ s=eidx[e]; d=eidx[NE+e]; }
    else { s=e-NE; d=e-NE; }
    out[EI_OFF+e]    =(float)s;
    out[EI_OFF+ET+e] =(float)d;
}

extern "C" void kernel_launch(void* const* d_in, const int* in_sizes, int n_in,
                              void* d_out, int out_size)
{
    const float* x      =(const float*)d_in[0];
    const float* gat_Wl =(const float*)d_in[1];
    const float* gat_bl =(const float*)d_in[2];
    const float* gat_Wr =(const float*)d_in[3];
    const float* gat_br =(const float*)d_in[4];
    const float* gat_att=(const float*)d_in[5];
    const float* gat_bias=(const float*)d_in[6];
    const float* tcn0_w =(const float*)d_in[7];
    const float* ln0_w  =(const float*)d_in[9];
    const float* ln0_b  =(const float*)d_in[10];
    const float* tcn1_w =(const float*)d_in[11];
    const float* ln1_w  =(const float*)d_in[13];
    const float* ln1_b  =(const float*)d_in[14];
    const float* ds1_w  =(const float*)d_in[15];
    const float* ds1_b  =(const float*)d_in[16];
    const float* tcn2_w =(const float*)d_in[17];
    const float* ln2_w  =(const float*)d_in[19];
    const float* ln2_b  =(const float*)d_in[20];
    const float* ds2_w  =(const float*)d_in[21];
    const float* ds2_b  =(const float*)d_in[22];
    const float* fc1_w  =(const float*)d_in[23];
    const float* fc1_b  =(const float*)d_in[24];
    const float* fc2_w  =(const float*)d_in[25];
    const float* fc2_b  =(const float*)d_in[26];
    const float* fc3_w  =(const float*)d_in[27];
    const float* fc3_b  =(const float*)d_in[28];
    const int*   edge   =(const int*)d_in[29];
    float* out=(float*)d_out;

    cudaFuncSetAttribute(attn_kernel, cudaFuncAttributeMaxDynamicSharedMemorySize, ATTN_SMEM_BYTES);
    cudaFuncSetAttribute(conv_mma<0>, cudaFuncAttributeMaxDynamicSharedMemorySize, CONV_SMEM);
    cudaFuncSetAttribute(conv_mma<1>, cudaFuncAttributeMaxDynamicSharedMemorySize, CONV_SMEM);
    cudaFuncSetAttribute(conv_mma<2>, cudaFuncAttributeMaxDynamicSharedMemorySize, CONV_SMEM);

    prep_kernel<<<1024,256>>>(gat_Wl, gat_Wr, tcn0_w, tcn1_w, tcn2_w, ds1_w, ds2_w);
    xform_kernel<<<NL/32,256>>>(x, gat_bl, gat_br);

    int write_alpha = (out_size >= ALPHA_OFF + ALPHA_LEN) ? 1 : 0;
    attn_kernel<<<NB,256,ATTN_SMEM_BYTES>>>(edge, gat_att, gat_bias, out, write_alpha);

    void *ph=nullptr,*py0=nullptr,*py1=nullptr,*pz=nullptr,*pz1=nullptr,*pz2=nullptr;
    void *a0h,*a0l,*a1h,*a1l,*a2h,*a2l,*d1h,*d1l,*d2h,*d2l;
    cudaGetSymbolAddress(&ph,  g_h);  cudaGetSymbolAddress(&py0, g_y0);
    cudaGetSymbolAddress(&py1, g_y1); cudaGetSymbolAddress(&pz,  g_z);
    cudaGetSymbolAddress(&pz1, g_z1); cudaGetSymbolAddress(&pz2, g_z2);
    cudaGetSymbolAddress(&a0h, g_A0H); cudaGetSymbolAddress(&a0l, g_A0L);
    cudaGetSymbolAddress(&a1h, g_A1H); cudaGetSymbolAddress(&a1l, g_A1L);
    cudaGetSymbolAddress(&a2h, g_A2H); cudaGetSymbolAddress(&a2l, g_A2L);
    cudaGetSymbolAddress(&d1h, g_D1H); cudaGetSymbolAddress(&d1l, g_D1L);
    cudaGetSymbolAddress(&d2h, g_D2H); cudaGetSymbolAddress(&d2l, g_D2L);

    conv_mma<0><<<NB/2,512,CONV_SMEM>>>((const float*)ph,
        (const uint4*)a0h,(const uint4*)a0l,(const uint4*)a0h,(const uint4*)a0l,
        nullptr, ln0_w, ln0_b, (float*)py0);
    conv_mma<1><<<NB/2,512,CONV_SMEM>>>((const float*)py0,
        (const uint4*)a1h,(const uint4*)a1l,(const uint4*)d1h,(const uint4*)d1l,
        ds1_b, ln1_w, ln1_b, (float*)py1);
    conv_mma<2><<<NB/2,512,CONV_SMEM>>>((const float*)py1,
        (const uint4*)a2h,(const uint4*)a2l,(const uint4*)d2h,(const uint4*)d2l,
        ds2_b, ln2_w, ln2_b, (float*)pz);

    fc1_kernel<<<dim3(8,8,SK),256>>>((const float*)pz, fc1_w);
    fc1red_kernel<<<(1024*512)/256,256>>>(fc1_b);

    gemm_kernel<<<dim3(256/64, NB/64),256>>>((const float*)pz1, fc2_w, fc2_b, (float*)pz2, NB, 256, 512, 1);
    gemm_kernel<<<dim3((144+63)/64, NB/64),256>>>((const float*)pz2, fc3_w, fc3_b, out, NB, 144, 256, 0);

    if (out_size >= EI_OFF + EI_LEN)
        ei_kernel<<<(ET+255)/256,256>>>(edge, out);
}

// round 9
// speedup vs baseline: 1.0567x; 1.0338x over previous
#include <cuda_runtime.h>
#include <cuda_bf16.h>
#include <cstdint>

#define NN   30
#define HH   4
#define CC   64
#define HC   256
#define FIN  64
#define NB   1024
#define EPG  240
#define NE   (NB*EPG)
#define NL   (NB*NN)
#define ET   (NE+NL)
#define EG   (EPG+NN)
#define OUT_LEN   (NB*144)
#define ALPHA_OFF OUT_LEN
#define ALPHA_LEN (ET*HH)
#define EI_OFF    (ALPHA_OFF+ALPHA_LEN)
#define EI_LEN    (2*ET)
#define LN_EPS 1e-5f
#define NSLOPE 0.2f
#define RS 40

typedef unsigned long long u64;

__device__ __forceinline__ u64 pk2(float a, float b){
    u64 r; asm("mov.b64 %0,{%1,%2};":"=l"(r):"f"(a),"f"(b)); return r;
}
__device__ __forceinline__ u64 f2fma(u64 a, u64 b, u64 c){
    u64 d; asm("fma.rn.f32x2 %0,%1,%2,%3;":"=l"(d):"l"(a),"l"(b),"l"(c)); return d;
}
__device__ __forceinline__ void upk(u64 v, float& lo, float& hi){
    asm("mov.b64 {%0,%1},%2;":"=f"(lo),"=f"(hi):"l"(v));
}

__device__ __forceinline__ void mma16816(float c[4], uint4 a, uint32_t b0, uint32_t b1){
    asm volatile("mma.sync.aligned.m16n8k16.row.col.f32.bf16.bf16.f32 "
        "{%0,%1,%2,%3},{%4,%5,%6,%7},{%8,%9},{%0,%1,%2,%3};"
        : "+f"(c[0]),"+f"(c[1]),"+f"(c[2]),"+f"(c[3])
        : "r"(a.x),"r"(a.y),"r"(a.z),"r"(a.w),"r"(b0),"r"(b1));
}

// ---------------- device scratch ----------------
__device__ float g_WlT[FIN*HC];
__device__ float g_WrT[FIN*HC];
__device__ float g_xl[NL*HC];
__device__ float g_xr[NL*HC];
__device__ float g_h [(size_t)NB*HC*RS];
__device__ float g_y0[(size_t)NB*256*RS];
__device__ float g_y1[(size_t)NB*512*RS];
__device__ float g_z [NB*HC*NN];
__device__ float g_z1[NB*512];
__device__ float g_z2[NB*256];
#define SK 4
__device__ float g_p1[SK*1024*512];

// A-fragment-packed weights (uint4 per lane per fragment)
__device__ uint4 g_A0H[24576], g_A0L[24576];
__device__ uint4 g_A1H[49152], g_A1L[49152];
__device__ uint4 g_D1H[16384], g_D1L[16384];
__device__ uint4 g_A2H[49152], g_A2L[49152];
__device__ uint4 g_D2H[16384], g_D2L[16384];

__device__ __forceinline__ uint32_t packbf(float v0, float v1, int lo){
    __nv_bfloat16 h0=__float2bfloat16(v0), h1=__float2bfloat16(v1);
    if (lo){ h0=__float2bfloat16(v0-__bfloat162float(h0)); h1=__float2bfloat16(v1-__bfloat162float(h1)); }
    return (uint32_t)__bfloat16_as_ushort(h0) | ((uint32_t)__bfloat16_as_ushort(h1)<<16);
}

__device__ void fill_convA(uint32_t* H, uint32_t* L, const float* w, int Cin, int MT, int nslots,
                           int t0, int stride)
{
    for (int i=t0;i<nslots;i+=stride){
        int q=i&3, lane=(i>>2)&31, mtg=(i>>7)%MT, kstep=i/(MT*128);
        int g=lane>>2, tc=lane&3;
        int m=mtg*16 + g + (q&1)*8;
        int kk=kstep*16 + (q>>1)*8 + tc*2;
        int t=kk/Cin, cin=kk-t*Cin;
        float v0=w[(m*Cin+cin)*3+t], v1=w[(m*Cin+cin+1)*3+t];
        H[i]=packbf(v0,v1,0); L[i]=packbf(v0,v1,1);
    }
}
__device__ void fill_dsA(uint32_t* H, uint32_t* L, const float* w, int Cin, int MT, int nslots,
                         int t0, int stride)
{
    for (int i=t0;i<nslots;i+=stride){
        int q=i&3, lane=(i>>2)&31, mtg=(i>>7)%MT, kstep=i/(MT*128);
        int g=lane>>2, tc=lane&3;
        int m=mtg*16 + g + (q&1)*8;
        int cin=kstep*16 + (q>>1)*8 + tc*2;
        float v0=w[m*Cin+cin], v1=w[m*Cin+cin+1];
        H[i]=packbf(v0,v1,0); L[i]=packbf(v0,v1,1);
    }
}

__global__ void prep_kernel(const float* __restrict__ Wl, const float* __restrict__ Wr,
                            const float* __restrict__ w0, const float* __restrict__ w1,
                            const float* __restrict__ w2, const float* __restrict__ d1,
                            const float* __restrict__ d2)
{
    int t0 = blockIdx.x*blockDim.x + threadIdx.x;
    int stride = gridDim.x*blockDim.x;
    for (int i=t0;i<FIN*HC;i+=stride){ int j=i%HC,k=i/HC; g_WlT[i]=Wl[j*FIN+k]; g_WrT[i]=Wr[j*FIN+k]; }
    fill_convA((uint32_t*)g_A0H,(uint32_t*)g_A0L, w0, 256, 16,  98304, t0, stride);
    fill_convA((uint32_t*)g_A1H,(uint32_t*)g_A1L, w1, 256, 32, 196608, t0, stride);
    fill_convA((uint32_t*)g_A2H,(uint32_t*)g_A2L, w2, 512, 16, 196608, t0, stride);
    fill_dsA  ((uint32_t*)g_D1H,(uint32_t*)g_D1L, d1, 256, 32,  65536, t0, stride);
    fill_dsA  ((uint32_t*)g_D2H,(uint32_t*)g_D2L, d2, 512, 16,  65536, t0, stride);
}

__global__ void __launch_bounds__(256) xform_kernel(const float* __restrict__ x,
                                                    const float* __restrict__ bl,
                                                    const float* __restrict__ br)
{
    __shared__ float xs[32*FIN];
    const int base = blockIdx.x*32;
    const int tid = threadIdx.x;
    for (int i=tid;i<32*FIN;i+=256) xs[i]=x[base*FIN+i];
    __syncthreads();
    float accl[32], accr[32];
#pragma unroll
    for (int n=0;n<32;n++){ accl[n]=0.f; accr[n]=0.f; }
    const int j = tid;
    for (int k=0;k<FIN;k++){
        float wl=g_WlT[k*HC+j], wr=g_WrT[k*HC+j];
#pragma unroll
        for (int n=0;n<32;n++){ float xv=xs[n*FIN+k]; accl[n]=fmaf(wl,xv,accl[n]); accr[n]=fmaf(wr,xv,accr[n]); }
    }
    float blv=bl[j], brv=br[j];
#pragma unroll
    for (int n=0;n<32;n++){
        g_xl[(base+n)*HC+j]=accl[n]+blv;
        g_xr[(base+n)*HC+j]=accr[n]+brv;
    }
}

#define ATTN_SMEM_BYTES (18272*4 + 901*4 + 16)
__global__ void __launch_bounds__(256) attn_kernel(const int* __restrict__ eidx,
                                                   const float* __restrict__ att,
                                                   const float* __restrict__ gbias,
                                                   float* __restrict__ out,
                                                   int write_alpha)
{
    extern __shared__ char smemraw[];
    float* xl_s   = (float*)smemraw;
    float* xr_s   = xl_s + 7680;
    float* att_s  = xr_s + 7680;
    float* bias_s = att_s + 256;
    float* esc    = bias_s + 256;
    float* alp    = esc + 1080;
    float* mmax   = alp + 1080;
    float* ssum   = mmax + 120;
    int*   srcl   = (int*)(ssum + 120);
    int*   dstl   = srcl + 270;
    int*   deg    = dstl + 270;
    int*   off    = deg + 30;
    int*   pos    = off + 31;
    int*   order  = pos + 30;
    const int b = blockIdx.x, tid = threadIdx.x;

    for (int i=tid;i<7680;i+=256){ xl_s[i]=g_xl[b*7680+i]; xr_s[i]=g_xr[b*7680+i]; }
    for (int i=tid;i<256;i+=256){ att_s[i]=att[i]; bias_s[i]=gbias[i]; }
    if (tid<30) deg[tid]=0;
    __syncthreads();
    for (int e=tid;e<EG;e+=256){
        int s,d;
        if (e<EPG){ s=eidx[b*EPG+e]-b*NN; d=eidx[NE+b*EPG+e]-b*NN; }
        else      { s=e-EPG; d=e-EPG; }
        srcl[e]=s; dstl[e]=d;
        atomicAdd(&deg[d],1);
    }
    __syncthreads();
    if (tid==0){ off[0]=0; for (int n=0;n<NN;n++) off[n+1]=off[n]+deg[n]; }
    __syncthreads();
    if (tid<30) pos[tid]=off[tid];
    __syncthreads();
    for (int e=tid;e<EG;e+=256){ int slot=atomicAdd(&pos[dstl[e]],1); order[slot]=e; }
    __syncthreads();
    for (int idx=tid; idx<EG*HH; idx+=256){
        int e=idx>>2, h=idx&3;
        const float* ps=&xl_s[srcl[e]*HC + h*CC];
        const float* pd=&xr_s[dstl[e]*HC + h*CC];
        const float* pa=&att_s[h*CC];
        float acc=0.f;
#pragma unroll 8
        for (int c=0;c<CC;c++){
            float v=ps[c]+pd[c];
            v = v>0.f ? v : NSLOPE*v;
            acc = fmaf(v, pa[c], acc);
        }
        esc[e*HH+h]=acc;
    }
    __syncthreads();
    for (int idx=tid; idx<NN*HH; idx+=256){
        int n=idx>>2, h=idx&3;
        float m=-1e30f;
        for (int i=off[n];i<off[n+1];i++) m=fmaxf(m, esc[order[i]*HH+h]);
        float s=0.f;
        for (int i=off[n];i<off[n+1];i++) s+=__expf(esc[order[i]*HH+h]-m);
        mmax[idx]=m; ssum[idx]=s;
    }
    __syncthreads();
    for (int idx=tid; idx<EG*HH; idx+=256){
        int e=idx>>2, h=idx&3;
        int d=dstl[e];
        float a=__expf(esc[e*HH+h]-mmax[d*HH+h])/ssum[d*HH+h];
        alp[e*HH+h]=a;
        if (write_alpha){
            int gid = (e<EPG) ? (b*EPG+e) : (NE + b*NN + (e-EPG));
            out[ALPHA_OFF + gid*HH + h]=a;
        }
    }
    __syncthreads();
    {
        const int j = tid;
        const int h = j>>6;
        for (int n=0;n<NN;n++){
            float acc=0.f;
            for (int i=off[n];i<off[n+1];i++){
                int e=order[i];
                acc = fmaf(alp[e*HH+h], xl_s[srcl[e]*HC+j], acc);
            }
            float v=acc+bias_s[j];
            xr_s[j*NN+n]=fmaxf(v,0.f);
        }
    }
    __syncthreads();
    for (int i=tid;i<256*RS;i+=256){
        int c=i/RS, col=i-c*RS;
        float v = (col>=4 && col<34) ? xr_s[c*NN + col-4] : 0.f;
        g_h[(size_t)b*256*RS + i]=v;
    }
}

// ================= mma.sync TCN conv layer (512 threads, wave-scheduled) =================
#define CS 270
#define CONV_SMEM (2*2*40*CS*2)   // 86400B

template<int MODE>
__global__ void __launch_bounds__(512,1) conv_mma(
    const float* __restrict__ in,
    const uint4* __restrict__ AH, const uint4* __restrict__ AL,
    const uint4* __restrict__ DH, const uint4* __restrict__ DL,
    const float* __restrict__ db,
    const float* __restrict__ lnw, const float* __restrict__ lnb,
    float* __restrict__ outp)
{
    constexpr int Cin   = (MODE==2)?512:256;
    constexpr int COUT  = (MODE==1)?512:256;
    constexpr int MT    = (MODE==1)?32:16;
    constexpr int MP    = (MODE==1)?2:1;
    constexpr int PH    = (MODE==2)?2:1;
    constexpr int DIL   = (MODE==0)?1:((MODE==1)?2:4);
    constexpr bool HASDS= (MODE>=1);
    constexpr int KS_T  = Cin/16;
    constexpr bool SPLITC = (MODE==0);

    extern __shared__ __nv_bfloat16 sm_bf[];
    __nv_bfloat16* sH = sm_bf;
    __nv_bfloat16* sL = sm_bf + 2*40*CS;
    __shared__ float s_lnw[32], s_lnb[32];

    const int tid=threadIdx.x, lane=tid&31, wid=tid>>5;
    const int g=lane>>2, tc=lane&3;
    const int b0=blockIdx.x*2;
    const int nhalf = wid&1;
    const int mtp   = wid>>1;

    if (tid<30){ s_lnw[tid]=lnw[tid]; s_lnb[tid]=lnb[tid]; }

    for (int mp=0; mp<MP; mp++){
        float acc[2][4][4];
        float acl[SPLITC?2:1][SPLITC?4:1][SPLITC?4:1];
        float dsacc[HASDS?2:1][HASDS?4:1][HASDS?4:1];
#pragma unroll
        for (int a=0;a<2;a++)
#pragma unroll
            for (int f=0;f<4;f++)
#pragma unroll
                for (int q=0;q<4;q++) acc[a][f][q]=0.f;
        if constexpr(SPLITC){
#pragma unroll
            for (int a=0;a<2;a++)
#pragma unroll
                for (int f=0;f<4;f++)
#pragma unroll
                    for (int q=0;q<4;q++) acl[a][f][q]=0.f;
        }
        if constexpr(HASDS){
#pragma unroll
            for (int a=0;a<2;a++)
#pragma unroll
                for (int f=0;f<4;f++)
#pragma unroll
                    for (int q=0;q<4;q++) dsacc[a][f][q]=0.f;
        }

        for (int ph=0; ph<PH; ph++){
            if (mp==0){
                if (ph>0) __syncthreads();
                for (int idx=tid; idx<2*256*RS; idx+=512){
                    int gr = idx/(256*RS);
                    int r  = idx - gr*256*RS;
                    int c  = r/RS;
                    int l  = r - c*RS;
                    float v = in[(((size_t)(b0+gr))*Cin + ph*256 + c)*RS + l];
                    __nv_bfloat16 h=__float2bfloat16(v);
                    int sidx=(gr*40+l)*CS+c;
                    sH[sidx]=h;
                    sL[sidx]=__float2bfloat16(v-__bfloat162float(h));
                }
            }
            __syncthreads();

            const int mtile0 = mp*16 + mtp*2;
            const int sb0 = (nhalf*40 + 4 + g)*CS + tc*2;

#pragma unroll
            for (int t=0;t<3;t++){
                int abase = ((t*KS_T + ph*16)*MT + mtile0)*32 + lane;
                const int srow = sb0 + DIL*(t-1)*CS;
                uint4 ah0=AH[abase], ah1=AH[abase+32], al0=AL[abase], al1=AL[abase+32];
                for (int ch=0; ch<16; ch++){
                    uint32_t Bh0[4],Bh1[4],Bl0[4],Bl1[4];
#pragma unroll
                    for (int f=0;f<4;f++){
                        const __nv_bfloat16* p = sH + (srow + f*(8*CS) + ch*16);
                        const __nv_bfloat16* q = sL + (srow + f*(8*CS) + ch*16);
                        Bh0[f]=*(const uint32_t*)p; Bh1[f]=*(const uint32_t*)(p+8);
                        Bl0[f]=*(const uint32_t*)q; Bl1[f]=*(const uint32_t*)(q+8);
                    }
                    int nbase = abase + ((ch<15)? MT*32 : 0);
                    uint4 nh0=AH[nbase], nh1=AH[nbase+32], nl0=AL[nbase], nl1=AL[nbase+32];
                    // wave 1: hi*hi
#pragma unroll
                    for (int f=0;f<4;f++){
                        mma16816(acc[0][f], ah0, Bh0[f],Bh1[f]);
                        mma16816(acc[1][f], ah1, Bh0[f],Bh1[f]);
                    }
                    // wave 2: lo*hi
#pragma unroll
                    for (int f=0;f<4;f++){
                        if constexpr(SPLITC){
                            mma16816(acl[0][f], al0, Bh0[f],Bh1[f]);
                            mma16816(acl[1][f], al1, Bh0[f],Bh1[f]);
                        } else {
                            mma16816(acc[0][f], al0, Bh0[f],Bh1[f]);
                            mma16816(acc[1][f], al1, Bh0[f],Bh1[f]);
                        }
                    }
                    // wave 3: hi*lo
#pragma unroll
                    for (int f=0;f<4;f++){
                        if constexpr(SPLITC){
                            mma16816(acl[0][f], ah0, Bl0[f],Bl1[f]);
                            mma16816(acl[1][f], ah1, Bl0[f],Bl1[f]);
                        } else {
                            mma16816(acc[0][f], ah0, Bl0[f],Bl1[f]);
                            mma16816(acc[1][f], ah1, Bl0[f],Bl1[f]);
                        }
                    }
                    abase=nbase; ah0=nh0; ah1=nh1; al0=nl0; al1=nl1;
                }
            }

            if constexpr(HASDS){
                int dbase = ((ph*16)*MT + mtile0)*32 + lane;
                const int srow = sb0;
                uint4 dh0=DH[dbase], dh1=DH[dbase+32], dl0=DL[dbase], dl1=DL[dbase+32];
                for (int ch=0; ch<16; ch++){
                    uint32_t Bh0[4],Bh1[4],Bl0[4],Bl1[4];
#pragma unroll
                    for (int f=0;f<4;f++){
                        const __nv_bfloat16* p = sH + (srow + f*(8*CS) + ch*16);
                        const __nv_bfloat16* q = sL + (srow + f*(8*CS) + ch*16);
                        Bh0[f]=*(const uint32_t*)p; Bh1[f]=*(const uint32_t*)(p+8);
                        Bl0[f]=*(const uint32_t*)q; Bl1[f]=*(const uint32_t*)(q+8);
                    }
                    int nbase = dbase + ((ch<15)? MT*32 : 0);
                    uint4 nh0=DH[nbase], nh1=DH[nbase+32], nl0=DL[nbase], nl1=DL[nbase+32];
#pragma unroll
                    for (int f=0;f<4;f++){
                        mma16816(dsacc[0][f], dh0, Bh0[f],Bh1[f]);
                        mma16816(dsacc[1][f], dh1, Bh0[f],Bh1[f]);
                    }
#pragma unroll
                    for (int f=0;f<4;f++){
                        mma16816(dsacc[0][f], dl0, Bh0[f],Bh1[f]);
                        mma16816(dsacc[1][f], dl1, Bh0[f],Bh1[f]);
                    }
#pragma unroll
                    for (int f=0;f<4;f++){
                        mma16816(dsacc[0][f], dh0, Bl0[f],Bl1[f]);
                        mma16816(dsacc[1][f], dh1, Bl0[f],Bl1[f]);
                    }
                    dbase=nbase; dh0=nh0; dh1=nh1; dl0=nl0; dl1=nl1;
                }
            }
        }

        // ---- epilogue ----
        if constexpr(SPLITC){
#pragma unroll
            for (int a=0;a<2;a++)
#pragma unroll
                for (int f=0;f<4;f++)
#pragma unroll
                    for (int q=0;q<4;q++) acc[a][f][q]+=acl[a][f][q];
        }
        const int gr = nhalf;
#pragma unroll
        for (int mt=0; mt<2; mt++){
            const int mrow0 = mp*256 + (mtp*2+mt)*16 + g;
#pragma unroll
            for (int half=0; half<2; half++){
                const int mrow = mrow0 + half*8;
                float dbv = 0.f;
                if constexpr(HASDS) dbv = __ldg(&db[mrow]);
                float s=0.f;
#pragma unroll
                for (int f=0; f<4; f++)
#pragma unroll
                    for (int i=0;i<2;i++){
                        int l=f*8+tc*2+i;
                        if (l<30) s+=acc[mt][f][half*2+i];
                    }
                s += __shfl_xor_sync(0xffffffffu,s,1);
                s += __shfl_xor_sync(0xffffffffu,s,2);
                float mean = s*(1.f/30.f);
                float qv=0.f;
#pragma unroll
                for (int f=0; f<4; f++)
#pragma unroll
                    for (int i=0;i<2;i++){
                        int l=f*8+tc*2+i;
                        if (l<30){ float d=acc[mt][f][half*2+i]-mean; qv=fmaf(d,d,qv); }
                    }
                qv += __shfl_xor_sync(0xffffffffu,qv,1);
                qv += __shfl_xor_sync(0xffffffffu,qv,2);
                float rsn = rsqrtf(qv*(1.f/30.f)+LN_EPS);

                size_t rb;
                if constexpr(MODE==2) rb = (((size_t)(b0+gr))*256 + mrow)*(size_t)NN;
                else                  rb = (((size_t)(b0+gr))*COUT + mrow)*(size_t)RS;
#pragma unroll
                for (int f=0; f<4; f++){
                    int l0=f*8+tc*2;
                    if (l0>=30) continue;
                    float o0,o1;
                    {
                        float v=(acc[mt][f][half*2+0]-mean)*rsn*s_lnw[l0]+s_lnb[l0];
                        o0=fmaxf(v,0.f);
                        v=(acc[mt][f][half*2+1]-mean)*rsn*s_lnw[l0+1]+s_lnb[l0+1];
                        o1=fmaxf(v,0.f);
                    }
                    if constexpr(MODE==0){
                        float2 res=*(const float2*)&in[(((size_t)(b0+gr))*256 + mrow)*RS + 4 + l0];
                        o0+=res.x; o1+=res.y;
                    } else {
                        o0 += dsacc[mt][f][half*2+0] + dbv;
                        o1 += dsacc[mt][f][half*2+1] + dbv;
                    }
                    if constexpr(MODE==2) *(float2*)&outp[rb+l0]   = make_float2(o0,o1);
                    else                  *(float2*)&outp[rb+4+l0] = make_float2(o0,o1);
                }
                if constexpr(MODE!=2){
                    if (tc==0) *(float4*)&outp[rb] = make_float4(0.f,0.f,0.f,0.f);
                    if (tc==3){
                        *(float2*)&outp[rb+34]=make_float2(0.f,0.f);
                        *(float4*)&outp[rb+36]=make_float4(0.f,0.f,0.f,0.f);
                    }
                }
            }
        }
    }
}

// ================= fc1: split-K f32x2 GEMM =================
__global__ void __launch_bounds__(256,2) fc1_kernel(const float* __restrict__ A,
                                                    const float* __restrict__ W)
{
    __shared__ float2 sA[128][17];
    __shared__ float2 sW[64][17];
    const int tid=threadIdx.x;
    const int n0=blockIdx.x*64, m0=blockIdx.y*128, kz=blockIdx.z;
    const int ty=tid>>4, tx=tid&15;
    u64 acc[8][4];
    u64 z=pk2(0.f,0.f);
#pragma unroll
    for (int i=0;i<8;i++)
#pragma unroll
        for (int j=0;j<4;j++) acc[i][j]=z;
    const int kbase = kz*(7680/SK);
    for (int k0=0;k0<7680/SK;k0+=32){
#pragma unroll
        for (int q=0;q<4;q++){
            int idx=tid+q*256; int m=idx>>3, kq=idx&7;
            float4 v=*(const float4*)&A[(m0+m)*7680 + kbase+k0+4*kq];
            sA[m][2*kq]  =make_float2(v.x,v.y);
            sA[m][2*kq+1]=make_float2(v.z,v.w);
        }
#pragma unroll
        for (int q=0;q<2;q++){
            int idx=tid+q*256; int m=idx>>3, kq=idx&7;
            float4 v=*(const float4*)&W[(n0+m)*7680 + kbase+k0+4*kq];
            sW[m][2*kq]  =make_float2(v.x,v.y);
            sW[m][2*kq+1]=make_float2(v.z,v.w);
        }
        __syncthreads();
#pragma unroll
        for (int p=0;p<16;p++){
            u64 av[8], wv[4];
#pragma unroll
            for (int i=0;i<8;i++) av[i]=*(const u64*)&sA[ty+16*i][p];
#pragma unroll
            for (int j=0;j<4;j++) wv[j]=*(const u64*)&sW[tx+16*j][p];
#pragma unroll
            for (int i=0;i<8;i++)
#pragma unroll
                for (int j=0;j<4;j++) acc[i][j]=f2fma(av[i],wv[j],acc[i][j]);
        }
        __syncthreads();
    }
#pragma unroll
    for (int i=0;i<8;i++){
        int gm=m0+ty+16*i;
#pragma unroll
        for (int j=0;j<4;j++){
            int gn=n0+tx+16*j;
            float lo,hi; upk(acc[i][j],lo,hi);
            g_p1[(kz*1024+gm)*512+gn]=lo+hi;
        }
    }
}

__global__ void fc1red_kernel(const float* __restrict__ bias)
{
    int i=blockIdx.x*blockDim.x+threadIdx.x;
    float s=g_p1[i]+g_p1[524288+i]+g_p1[2*524288+i]+g_p1[3*524288+i];
    s+=bias[i&511];
    g_z1[i]=fmaxf(s,0.f);
}

__global__ void __launch_bounds__(256) gemm_kernel(const float* __restrict__ A,
                                                   const float* __restrict__ W,
                                                   const float* __restrict__ bias,
                                                   float* __restrict__ C,
                                                   int M, int N, int K, int relu)
{
    __shared__ float sA[64][17];
    __shared__ float sW[64][17];
    const int tid=threadIdx.x;
    const int m0=blockIdx.y*64, n0=blockIdx.x*64;
    const int tr=(tid/16)*4, tc=(tid%16)*4;
    float acc[4][4];
#pragma unroll
    for (int i=0;i<4;i++)
#pragma unroll
        for (int j=0;j<4;j++) acc[i][j]=0.f;
    for (int k0=0;k0<K;k0+=16){
        for (int i=tid;i<1024;i+=256){
            int k=i&15, r=i>>4;
            int gm=m0+r, gk=k0+k;
            sA[r][k]=(gm<M && gk<K)? A[gm*K+gk] : 0.f;
            int gn=n0+r;
            sW[r][k]=(gn<N && gk<K)? W[gn*K+gk] : 0.f;
        }
        __syncthreads();
#pragma unroll
        for (int k=0;k<16;k++){
            float a[4], w[4];
#pragma unroll
            for (int i=0;i<4;i++) a[i]=sA[tr+i][k];
#pragma unroll
            for (int j=0;j<4;j++) w[j]=sW[tc+j][k];
#pragma unroll
            for (int i=0;i<4;i++)
#pragma unroll
                for (int j=0;j<4;j++) acc[i][j]=fmaf(a[i],w[j],acc[i][j]);
        }
        __syncthreads();
    }
#pragma unroll
    for (int i=0;i<4;i++){
        int gm=m0+tr+i;
        if (gm>=M) continue;
#pragma unroll
        for (int j=0;j<4;j++){
            int gn=n0+tc+j;
            if (gn>=N) continue;
            float v=acc[i][j]+bias[gn];
            if (relu) v=fmaxf(v,0.f);
            C[gm*N+gn]=v;
        }
    }
}

__global__ void ei_kernel(const int* __restrict__ eidx, float* __restrict__ out)
{
    int e=blockIdx.x*blockDim.x+threadIdx.x;
    if (e>=ET) return;
    int s,d;
    if (e<NE){ s=eidx[e]; d=eidx[NE+e]; }
    else { s=e-NE; d=e-NE; }
    out[EI_OFF+e]    =(float)s;
    out[EI_OFF+ET+e] =(float)d;
}

extern "C" void kernel_launch(void* const* d_in, const int* in_sizes, int n_in,
                              void* d_out, int out_size)
{
    const float* x      =(const float*)d_in[0];
    const float* gat_Wl =(const float*)d_in[1];
    const float* gat_bl =(const float*)d_in[2];
    const float* gat_Wr =(const float*)d_in[3];
    const float* gat_br =(const float*)d_in[4];
    const float* gat_att=(const float*)d_in[5];
    const float* gat_bias=(const float*)d_in[6];
    const float* tcn0_w =(const float*)d_in[7];
    const float* ln0_w  =(const float*)d_in[9];
    const float* ln0_b  =(const float*)d_in[10];
    const float* tcn1_w =(const float*)d_in[11];
    const float* ln1_w  =(const float*)d_in[13];
    const float* ln1_b  =(const float*)d_in[14];
    const float* ds1_w  =(const float*)d_in[15];
    const float* ds1_b  =(const float*)d_in[16];
    const float* tcn2_w =(const float*)d_in[17];
    const float* ln2_w  =(const float*)d_in[19];
    const float* ln2_b  =(const float*)d_in[20];
    const float* ds2_w  =(const float*)d_in[21];
    const float* ds2_b  =(const float*)d_in[22];
    const float* fc1_w  =(const float*)d_in[23];
    const float* fc1_b  =(const float*)d_in[24];
    const float* fc2_w  =(const float*)d_in[25];
    const float* fc2_b  =(const float*)d_in[26];
    const float* fc3_w  =(const float*)d_in[27];
    const float* fc3_b  =(const float*)d_in[28];
    const int*   edge   =(const int*)d_in[29];
    float* out=(float*)d_out;

    cudaFuncSetAttribute(attn_kernel, cudaFuncAttributeMaxDynamicSharedMemorySize, ATTN_SMEM_BYTES);
    cudaFuncSetAttribute(conv_mma<0>, cudaFuncAttributeMaxDynamicSharedMemorySize, CONV_SMEM);
    cudaFuncSetAttribute(conv_mma<1>, cudaFuncAttributeMaxDynamicSharedMemorySize, CONV_SMEM);
    cudaFuncSetAttribute(conv_mma<2>, cudaFuncAttributeMaxDynamicSharedMemorySize, CONV_SMEM);

    prep_kernel<<<1024,256>>>(gat_Wl, gat_Wr, tcn0_w, tcn1_w, tcn2_w, ds1_w, ds2_w);
    xform_kernel<<<NL/32,256>>>(x, gat_bl, gat_br);

    int write_alpha = (out_size >= ALPHA_OFF + ALPHA_LEN) ? 1 : 0;
    attn_kernel<<<NB,256,ATTN_SMEM_BYTES>>>(edge, gat_att, gat_bias, out, write_alpha);

    void *ph=nullptr,*py0=nullptr,*py1=nullptr,*pz=nullptr,*pz1=nullptr,*pz2=nullptr;
    void *a0h,*a0l,*a1h,*a1l,*a2h,*a2l,*d1h,*d1l,*d2h,*d2l;
    cudaGetSymbolAddress(&ph,  g_h);  cudaGetSymbolAddress(&py0, g_y0);
    cudaGetSymbolAddress(&py1, g_y1); cudaGetSymbolAddress(&pz,  g_z);
    cudaGetSymbolAddress(&pz1, g_z1); cudaGetSymbolAddress(&pz2, g_z2);
    cudaGetSymbolAddress(&a0h, g_A0H); cudaGetSymbolAddress(&a0l, g_A0L);
    cudaGetSymbolAddress(&a1h, g_A1H); cudaGetSymbolAddress(&a1l, g_A1L);
    cudaGetSymbolAddress(&a2h, g_A2H); cudaGetSymbolAddress(&a2l, g_A2L);
    cudaGetSymbolAddress(&d1h, g_D1H); cudaGetSymbolAddress(&d1l, g_D1L);
    cudaGetSymbolAddress(&d2h, g_D2H); cudaGetSymbolAddress(&d2l, g_D2L);

    conv_mma<0><<<NB/2,512,CONV_SMEM>>>((const float*)ph,
        (const uint4*)a0h,(const uint4*)a0l,(const uint4*)a0h,(const uint4*)a0l,
        nullptr, ln0_w, ln0_b, (float*)py0);
    conv_mma<1><<<NB/2,512,CONV_SMEM>>>((const float*)py0,
        (const uint4*)a1h,(const uint4*)a1l,(const uint4*)d1h,(const uint4*)d1l,
        ds1_b, ln1_w, ln1_b, (float*)py1);
    conv_mma<2><<<NB/2,512,CONV_SMEM>>>((const float*)py1,
        (const uint4*)a2h,(const uint4*)a2l,(const uint4*)d2h,(const uint4*)d2l,
        ds2_b, ln2_w, ln2_b, (float*)pz);

    fc1_kernel<<<dim3(8,8,SK),256>>>((const float*)pz, fc1_w);
    fc1red_kernel<<<(1024*512)/256,256>>>(fc1_b);

    gemm_kernel<<<dim3(256/64, NB/64),256>>>((const float*)pz1, fc2_w, fc2_b, (float*)pz2, NB, 256, 512, 1);
    gemm_kernel<<<dim3((144+63)/64, NB/64),256>>>((const float*)pz2, fc3_w, fc3_b, out, NB, 144, 256, 0);

    if (out_size >= EI_OFF + EI_LEN)
        ei_kernel<<<(ET+255)/256,256>>>(edge, out);
}

// round 10
// speedup vs baseline: 1.0695x; 1.0121x over previous
#include <cuda_runtime.h>
#include <cuda_bf16.h>
#include <cstdint>

#define NN   30
#define HH   4
#define CC   64
#define HC   256
#define FIN  64
#define NB   1024
#define EPG  240
#define NE   (NB*EPG)
#define NL   (NB*NN)
#define ET   (NE+NL)
#define EG   (EPG+NN)
#define OUT_LEN   (NB*144)
#define ALPHA_OFF OUT_LEN
#define ALPHA_LEN (ET*HH)
#define EI_OFF    (ALPHA_OFF+ALPHA_LEN)
#define EI_LEN    (2*ET)
#define LN_EPS 1e-5f
#define NSLOPE 0.2f
#define RS 40

typedef unsigned long long u64;

__device__ __forceinline__ u64 pk2(float a, float b){
    u64 r; asm("mov.b64 %0,{%1,%2};":"=l"(r):"f"(a),"f"(b)); return r;
}
__device__ __forceinline__ u64 f2fma(u64 a, u64 b, u64 c){
    u64 d; asm("fma.rn.f32x2 %0,%1,%2,%3;":"=l"(d):"l"(a),"l"(b),"l"(c)); return d;
}
__device__ __forceinline__ void upk(u64 v, float& lo, float& hi){
    asm("mov.b64 {%0,%1},%2;":"=f"(lo),"=f"(hi):"l"(v));
}

__device__ __forceinline__ void mma16816(float c[4], uint4 a, uint32_t b0, uint32_t b1){
    asm volatile("mma.sync.aligned.m16n8k16.row.col.f32.bf16.bf16.f32 "
        "{%0,%1,%2,%3},{%4,%5,%6,%7},{%8,%9},{%0,%1,%2,%3};"
        : "+f"(c[0]),"+f"(c[1]),"+f"(c[2]),"+f"(c[3])
        : "r"(a.x),"r"(a.y),"r"(a.z),"r"(a.w),"r"(b0),"r"(b1));
}

// ---------------- device scratch ----------------
__device__ float g_WlT[FIN*HC];
__device__ float g_WrT[FIN*HC];
__device__ float g_xl[NL*HC];
__device__ float g_xr[NL*HC];
__device__ float g_h [(size_t)NB*HC*RS];
__device__ float g_y0[(size_t)NB*256*RS];
__device__ float g_y1[(size_t)NB*512*RS];
__device__ float g_z [NB*HC*NN];
__device__ float g_z1[NB*512];
__device__ float g_z2[NB*256];
#define SK 4
__device__ float g_p1[SK*1024*512];

// A-fragment-packed weights (uint4 per lane per fragment), k-permuted for LDS.64 B loads
__device__ uint4 g_A0H[24576], g_A0L[24576];
__device__ uint4 g_A1H[49152], g_A1L[49152];
__device__ uint4 g_D1H[16384], g_D1L[16384];
__device__ uint4 g_A2H[49152], g_A2L[49152];
__device__ uint4 g_D2H[16384], g_D2L[16384];

__device__ __forceinline__ uint32_t packbf(float v0, float v1, int lo){
    __nv_bfloat16 h0=__float2bfloat16(v0), h1=__float2bfloat16(v1);
    if (lo){ h0=__float2bfloat16(v0-__bfloat162float(h0)); h1=__float2bfloat16(v1-__bfloat162float(h1)); }
    return (uint32_t)__bfloat16_as_ushort(h0) | ((uint32_t)__bfloat16_as_ushort(h1)<<16);
}

// k-permutation: mma slot pair for quad q at lane tc reads cin offset tc*4 + (q>>1)*2
__device__ void fill_convA(uint32_t* H, uint32_t* L, const float* w, int Cin, int MT, int nslots,
                           int t0, int stride)
{
    for (int i=t0;i<nslots;i+=stride){
        int q=i&3, lane=(i>>2)&31, mtg=(i>>7)%MT, kstep=i/(MT*128);
        int g=lane>>2, tc=lane&3;
        int m=mtg*16 + g + (q&1)*8;
        int kk=kstep*16 + tc*4 + (q>>1)*2;
        int t=kk/Cin, cin=kk-t*Cin;
        float v0=w[(m*Cin+cin)*3+t], v1=w[(m*Cin+cin+1)*3+t];
        H[i]=packbf(v0,v1,0); L[i]=packbf(v0,v1,1);
    }
}
__device__ void fill_dsA(uint32_t* H, uint32_t* L, const float* w, int Cin, int MT, int nslots,
                         int t0, int stride)
{
    for (int i=t0;i<nslots;i+=stride){
        int q=i&3, lane=(i>>2)&31, mtg=(i>>7)%MT, kstep=i/(MT*128);
        int g=lane>>2, tc=lane&3;
        int m=mtg*16 + g + (q&1)*8;
        int cin=kstep*16 + tc*4 + (q>>1)*2;
        float v0=w[m*Cin+cin], v1=w[m*Cin+cin+1];
        H[i]=packbf(v0,v1,0); L[i]=packbf(v0,v1,1);
    }
}

__global__ void prep_kernel(const float* __restrict__ Wl, const float* __restrict__ Wr,
                            const float* __restrict__ w0, const float* __restrict__ w1,
                            const float* __restrict__ w2, const float* __restrict__ d1,
                            const float* __restrict__ d2)
{
    int t0 = blockIdx.x*blockDim.x + threadIdx.x;
    int stride = gridDim.x*blockDim.x;
    for (int i=t0;i<FIN*HC;i+=stride){ int j=i%HC,k=i/HC; g_WlT[i]=Wl[j*FIN+k]; g_WrT[i]=Wr[j*FIN+k]; }
    fill_convA((uint32_t*)g_A0H,(uint32_t*)g_A0L, w0, 256, 16,  98304, t0, stride);
    fill_convA((uint32_t*)g_A1H,(uint32_t*)g_A1L, w1, 256, 32, 196608, t0, stride);
    fill_convA((uint32_t*)g_A2H,(uint32_t*)g_A2L, w2, 512, 16, 196608, t0, stride);
    fill_dsA  ((uint32_t*)g_D1H,(uint32_t*)g_D1L, d1, 256, 32,  65536, t0, stride);
    fill_dsA  ((uint32_t*)g_D2H,(uint32_t*)g_D2L, d2, 512, 16,  65536, t0, stride);
}

__global__ void __launch_bounds__(256) xform_kernel(const float* __restrict__ x,
                                                    const float* __restrict__ bl,
                                                    const float* __restrict__ br)
{
    __shared__ float xs[32*FIN];
    const int base = blockIdx.x*32;
    const int tid = threadIdx.x;
    for (int i=tid;i<32*FIN;i+=256) xs[i]=x[base*FIN+i];
    __syncthreads();
    float accl[32], accr[32];
#pragma unroll
    for (int n=0;n<32;n++){ accl[n]=0.f; accr[n]=0.f; }
    const int j = tid;
    for (int k=0;k<FIN;k++){
        float wl=g_WlT[k*HC+j], wr=g_WrT[k*HC+j];
#pragma unroll
        for (int n=0;n<32;n++){ float xv=xs[n*FIN+k]; accl[n]=fmaf(wl,xv,accl[n]); accr[n]=fmaf(wr,xv,accr[n]); }
    }
    float blv=bl[j], brv=br[j];
#pragma unroll
    for (int n=0;n<32;n++){
        g_xl[(base+n)*HC+j]=accl[n]+blv;
        g_xr[(base+n)*HC+j]=accr[n]+brv;
    }
}

#define ATTN_SMEM_BYTES (18272*4 + 901*4 + 16)
__global__ void __launch_bounds__(256) attn_kernel(const int* __restrict__ eidx,
                                                   const float* __restrict__ att,
                                                   const float* __restrict__ gbias,
                                                   float* __restrict__ out,
                                                   int write_alpha)
{
    extern __shared__ char smemraw[];
    float* xl_s   = (float*)smemraw;
    float* xr_s   = xl_s + 7680;
    float* att_s  = xr_s + 7680;
    float* bias_s = att_s + 256;
    float* esc    = bias_s + 256;
    float* alp    = esc + 1080;
    float* mmax   = alp + 1080;
    float* ssum   = mmax + 120;
    int*   srcl   = (int*)(ssum + 120);
    int*   dstl   = srcl + 270;
    int*   deg    = dstl + 270;
    int*   off    = deg + 30;
    int*   pos    = off + 31;
    int*   order  = pos + 30;
    const int b = blockIdx.x, tid = threadIdx.x;

    for (int i=tid;i<7680;i+=256){ xl_s[i]=g_xl[b*7680+i]; xr_s[i]=g_xr[b*7680+i]; }
    for (int i=tid;i<256;i+=256){ att_s[i]=att[i]; bias_s[i]=gbias[i]; }
    if (tid<30) deg[tid]=0;
    __syncthreads();
    for (int e=tid;e<EG;e+=256){
        int s,d;
        if (e<EPG){ s=eidx[b*EPG+e]-b*NN; d=eidx[NE+b*EPG+e]-b*NN; }
        else      { s=e-EPG; d=e-EPG; }
        srcl[e]=s; dstl[e]=d;
        atomicAdd(&deg[d],1);
    }
    __syncthreads();
    if (tid==0){ off[0]=0; for (int n=0;n<NN;n++) off[n+1]=off[n]+deg[n]; }
    __syncthreads();
    if (tid<30) pos[tid]=off[tid];
    __syncthreads();
    for (int e=tid;e<EG;e+=256){ int slot=atomicAdd(&pos[dstl[e]],1); order[slot]=e; }
    __syncthreads();
    for (int idx=tid; idx<EG*HH; idx+=256){
        int e=idx>>2, h=idx&3;
        const float* ps=&xl_s[srcl[e]*HC + h*CC];
        const float* pd=&xr_s[dstl[e]*HC + h*CC];
        const float* pa=&att_s[h*CC];
        float acc=0.f;
#pragma unroll 8
        for (int c=0;c<CC;c++){
            float v=ps[c]+pd[c];
            v = v>0.f ? v : NSLOPE*v;
            acc = fmaf(v, pa[c], acc);
        }
        esc[e*HH+h]=acc;
    }
    __syncthreads();
    for (int idx=tid; idx<NN*HH; idx+=256){
        int n=idx>>2, h=idx&3;
        float m=-1e30f;
        for (int i=off[n];i<off[n+1];i++) m=fmaxf(m, esc[order[i]*HH+h]);
        float s=0.f;
        for (int i=off[n];i<off[n+1];i++) s+=__expf(esc[order[i]*HH+h]-m);
        mmax[idx]=m; ssum[idx]=s;
    }
    __syncthreads();
    for (int idx=tid; idx<EG*HH; idx+=256){
        int e=idx>>2, h=idx&3;
        int d=dstl[e];
        float a=__expf(esc[e*HH+h]-mmax[d*HH+h])/ssum[d*HH+h];
        alp[e*HH+h]=a;
        if (write_alpha){
            int gid = (e<EPG) ? (b*EPG+e) : (NE + b*NN + (e-EPG));
            out[ALPHA_OFF + gid*HH + h]=a;
        }
    }
    __syncthreads();
    {
        const int j = tid;
        const int h = j>>6;
        for (int n=0;n<NN;n++){
            float acc=0.f;
            for (int i=off[n];i<off[n+1];i++){
                int e=order[i];
                acc = fmaf(alp[e*HH+h], xl_s[srcl[e]*HC+j], acc);
            }
            float v=acc+bias_s[j];
            xr_s[j*NN+n]=fmaxf(v,0.f);
        }
    }
    __syncthreads();
    for (int i=tid;i<256*RS;i+=256){
        int c=i/RS, col=i-c*RS;
        float v = (col>=4 && col<34) ? xr_s[c*NN + col-4] : 0.f;
        g_h[(size_t)b*256*RS + i]=v;
    }
}

// ================= mma.sync TCN conv layer (512 thr, LDS.64 B, ds folded into tap 1) =================
#define CS 272
#define CONV_SMEM (2*2*40*CS*2)   // 87040B

template<int MODE>
__global__ void __launch_bounds__(512,1) conv_mma(
    const float* __restrict__ in,
    const uint4* __restrict__ AH, const uint4* __restrict__ AL,
    const uint4* __restrict__ DH, const uint4* __restrict__ DL,
    const float* __restrict__ db,
    const float* __restrict__ lnw, const float* __restrict__ lnb,
    float* __restrict__ outp)
{
    constexpr int Cin   = (MODE==2)?512:256;
    constexpr int COUT  = (MODE==1)?512:256;
    constexpr int MT    = (MODE==1)?32:16;
    constexpr int MP    = (MODE==1)?2:1;
    constexpr int PH    = (MODE==2)?2:1;
    constexpr int DIL   = (MODE==0)?1:((MODE==1)?2:4);
    constexpr bool HASDS= (MODE>=1);
    constexpr int KS_T  = Cin/16;
    constexpr bool SPLITC = (MODE==0);

    extern __shared__ __nv_bfloat16 sm_bf[];
    __nv_bfloat16* sH = sm_bf;
    __nv_bfloat16* sL = sm_bf + 2*40*CS;
    __shared__ float s_lnw[32], s_lnb[32];

    const int tid=threadIdx.x, lane=tid&31, wid=tid>>5;
    const int g=lane>>2, tc=lane&3;
    const int b0=blockIdx.x*2;
    const int nhalf = wid&1;
    const int mtp   = wid>>1;

    if (tid<30){ s_lnw[tid]=lnw[tid]; s_lnb[tid]=lnb[tid]; }

    for (int mp=0; mp<MP; mp++){
        float acc[2][4][4];
        float acl[SPLITC?2:1][SPLITC?4:1][SPLITC?4:1];
        float dsacc[HASDS?2:1][HASDS?4:1][HASDS?4:1];
#pragma unroll
        for (int a=0;a<2;a++)
#pragma unroll
            for (int f=0;f<4;f++)
#pragma unroll
                for (int q=0;q<4;q++) acc[a][f][q]=0.f;
        if constexpr(SPLITC){
#pragma unroll
            for (int a=0;a<2;a++)
#pragma unroll
                for (int f=0;f<4;f++)
#pragma unroll
                    for (int q=0;q<4;q++) acl[a][f][q]=0.f;
        }
        if constexpr(HASDS){
#pragma unroll
            for (int a=0;a<2;a++)
#pragma unroll
                for (int f=0;f<4;f++)
#pragma unroll
                    for (int q=0;q<4;q++) dsacc[a][f][q]=0.f;
        }

        for (int ph=0; ph<PH; ph++){
            if (mp==0){
                if (ph>0) __syncthreads();
                for (int idx=tid; idx<2*256*RS; idx+=512){
                    int gr = idx/(256*RS);
                    int r  = idx - gr*256*RS;
                    int c  = r/RS;
                    int l  = r - c*RS;
                    float v = in[(((size_t)(b0+gr))*Cin + ph*256 + c)*RS + l];
                    __nv_bfloat16 h=__float2bfloat16(v);
                    int sidx=(gr*40+l)*CS+c;
                    sH[sidx]=h;
                    sL[sidx]=__float2bfloat16(v-__bfloat162float(h));
                }
            }
            __syncthreads();

            const int mtile0 = mp*16 + mtp*2;
            const int sb0 = (nhalf*40 + 4 + g)*CS + tc*4;

#pragma unroll
            for (int t=0;t<3;t++){
                int abase = ((t*KS_T + ph*16)*MT + mtile0)*32 + lane;
                const int srow = sb0 + DIL*(t-1)*CS;
                if (HASDS && t==1){
                    // ---- tap 1 with folded downsample GEMM (shares B fragments) ----
                    int dbase = ((ph*16)*MT + mtile0)*32 + lane;
                    for (int ch=0; ch<16; ch++){
                        uint4 ah0=AH[abase], ah1=AH[abase+32], al0=AL[abase], al1=AL[abase+32];
                        uint4 dh0=DH[dbase], dh1=DH[dbase+32], dl0=DL[dbase], dl1=DL[dbase+32];
                        uint2 BH[4], BL[4];
#pragma unroll
                        for (int f=0;f<4;f++){
                            BH[f]=*(const uint2*)(sH + srow + f*(8*CS) + ch*16);
                            BL[f]=*(const uint2*)(sL + srow + f*(8*CS) + ch*16);
                        }
#pragma unroll
                        for (int f=0;f<4;f++){
                            mma16816(acc[0][f], ah0, BH[f].x,BH[f].y);
                            mma16816(acc[1][f], ah1, BH[f].x,BH[f].y);
                        }
#pragma unroll
                        for (int f=0;f<4;f++){
                            mma16816(acc[0][f], al0, BH[f].x,BH[f].y);
                            mma16816(acc[1][f], al1, BH[f].x,BH[f].y);
                        }
#pragma unroll
                        for (int f=0;f<4;f++){
                            mma16816(acc[0][f], ah0, BL[f].x,BL[f].y);
                            mma16816(acc[1][f], ah1, BL[f].x,BL[f].y);
                        }
#pragma unroll
                        for (int f=0;f<4;f++){
                            mma16816(dsacc[0][f], dh0, BH[f].x,BH[f].y);
                            mma16816(dsacc[1][f], dh1, BH[f].x,BH[f].y);
                        }
#pragma unroll
                        for (int f=0;f<4;f++){
                            mma16816(dsacc[0][f], dl0, BH[f].x,BH[f].y);
                            mma16816(dsacc[1][f], dl1, BH[f].x,BH[f].y);
                        }
#pragma unroll
                        for (int f=0;f<4;f++){
                            mma16816(dsacc[0][f], dh0, BL[f].x,BL[f].y);
                            mma16816(dsacc[1][f], dh1, BL[f].x,BL[f].y);
                        }
                        abase += MT*32; dbase += MT*32;
                    }
                } else {
                    uint4 ah0=AH[abase], ah1=AH[abase+32], al0=AL[abase], al1=AL[abase+32];
                    for (int ch=0; ch<16; ch++){
                        uint2 BH[4], BL[4];
#pragma unroll
                        for (int f=0;f<4;f++){
                            BH[f]=*(const uint2*)(sH + srow + f*(8*CS) + ch*16);
                            BL[f]=*(const uint2*)(sL + srow + f*(8*CS) + ch*16);
                        }
                        int nbase = abase + ((ch<15)? MT*32 : 0);
                        uint4 nh0=AH[nbase], nh1=AH[nbase+32], nl0=AL[nbase], nl1=AL[nbase+32];
#pragma unroll
                        for (int f=0;f<4;f++){
                            mma16816(acc[0][f], ah0, BH[f].x,BH[f].y);
                            mma16816(acc[1][f], ah1, BH[f].x,BH[f].y);
                        }
#pragma unroll
                        for (int f=0;f<4;f++){
                            if constexpr(SPLITC){
                                mma16816(acl[0][f], al0, BH[f].x,BH[f].y);
                                mma16816(acl[1][f], al1, BH[f].x,BH[f].y);
                            } else {
                                mma16816(acc[0][f], al0, BH[f].x,BH[f].y);
                                mma16816(acc[1][f], al1, BH[f].x,BH[f].y);
                            }
                        }
#pragma unroll
                        for (int f=0;f<4;f++){
                            if constexpr(SPLITC){
                                mma16816(acl[0][f], ah0, BL[f].x,BL[f].y);
                                mma16816(acl[1][f], ah1, BL[f].x,BL[f].y);
                            } else {
                                mma16816(acc[0][f], ah0, BL[f].x,BL[f].y);
                                mma16816(acc[1][f], ah1, BL[f].x,BL[f].y);
                            }
                        }
                        abase=nbase; ah0=nh0; ah1=nh1; al0=nl0; al1=nl1;
                    }
                }
            }
        }

        // ---- epilogue ----
        if constexpr(SPLITC){
#pragma unroll
            for (int a=0;a<2;a++)
#pragma unroll
                for (int f=0;f<4;f++)
#pragma unroll
                    for (int q=0;q<4;q++) acc[a][f][q]+=acl[a][f][q];
        }
        const int gr = nhalf;
#pragma unroll
        for (int mt=0; mt<2; mt++){
            const int mrow0 = mp*256 + (mtp*2+mt)*16 + g;
#pragma unroll
            for (int half=0; half<2; half++){
                const int mrow = mrow0 + half*8;
                float dbv = 0.f;
                if constexpr(HASDS) dbv = __ldg(&db[mrow]);
                float s=0.f;
#pragma unroll
                for (int f=0; f<4; f++)
#pragma unroll
                    for (int i=0;i<2;i++){
                        int l=f*8+tc*2+i;
                        if (l<30) s+=acc[mt][f][half*2+i];
                    }
                s += __shfl_xor_sync(0xffffffffu,s,1);
                s += __shfl_xor_sync(0xffffffffu,s,2);
                float mean = s*(1.f/30.f);
                float qv=0.f;
#pragma unroll
                for (int f=0; f<4; f++)
#pragma unroll
                    for (int i=0;i<2;i++){
                        int l=f*8+tc*2+i;
                        if (l<30){ float d=acc[mt][f][half*2+i]-mean; qv=fmaf(d,d,qv); }
                    }
                qv += __shfl_xor_sync(0xffffffffu,qv,1);
                qv += __shfl_xor_sync(0xffffffffu,qv,2);
                float rsn = rsqrtf(qv*(1.f/30.f)+LN_EPS);

                size_t rb;
                if constexpr(MODE==2) rb = (((size_t)(b0+gr))*256 + mrow)*(size_t)NN;
                else                  rb = (((size_t)(b0+gr))*COUT + mrow)*(size_t)RS;
#pragma unroll
                for (int f=0; f<4; f++){
                    int l0=f*8+tc*2;
                    if (l0>=30) continue;
                    float o0,o1;
                    {
                        float v=(acc[mt][f][half*2+0]-mean)*rsn*s_lnw[l0]+s_lnb[l0];
                        o0=fmaxf(v,0.f);
                        v=(acc[mt][f][half*2+1]-mean)*rsn*s_lnw[l0+1]+s_lnb[l0+1];
                        o1=fmaxf(v,0.f);
                    }
                    if constexpr(MODE==0){
                        float2 res=*(const float2*)&in[(((size_t)(b0+gr))*256 + mrow)*RS + 4 + l0];
                        o0+=res.x; o1+=res.y;
                    } else {
                        o0 += dsacc[mt][f][half*2+0] + dbv;
                        o1 += dsacc[mt][f][half*2+1] + dbv;
                    }
                    if constexpr(MODE==2) *(float2*)&outp[rb+l0]   = make_float2(o0,o1);
                    else                  *(float2*)&outp[rb+4+l0] = make_float2(o0,o1);
                }
                if constexpr(MODE!=2){
                    if (tc==0) *(float4*)&outp[rb] = make_float4(0.f,0.f,0.f,0.f);
                    if (tc==3){
                        *(float2*)&outp[rb+34]=make_float2(0.f,0.f);
                        *(float4*)&outp[rb+36]=make_float4(0.f,0.f,0.f,0.f);
                    }
                }
            }
        }
    }
}

// ================= fc1: split-K f32x2 GEMM =================
__global__ void __launch_bounds__(256,2) fc1_kernel(const float* __restrict__ A,
                                                    const float* __restrict__ W)
{
    __shared__ float2 sA[128][17];
    __shared__ float2 sW[64][17];
    const int tid=threadIdx.x;
    const int n0=blockIdx.x*64, m0=blockIdx.y*128, kz=blockIdx.z;
    const int ty=tid>>4, tx=tid&15;
    u64 acc[8][4];
    u64 z=pk2(0.f,0.f);
#pragma unroll
    for (int i=0;i<8;i++)
#pragma unroll
        for (int j=0;j<4;j++) acc[i][j]=z;
    const int kbase = kz*(7680/SK);
    for (int k0=0;k0<7680/SK;k0+=32){
#pragma unroll
        for (int q=0;q<4;q++){
            int idx=tid+q*256; int m=idx>>3, kq=idx&7;
            float4 v=*(const float4*)&A[(m0+m)*7680 + kbase+k0+4*kq];
            sA[m][2*kq]  =make_float2(v.x,v.y);
            sA[m][2*kq+1]=make_float2(v.z,v.w);
        }
#pragma unroll
        for (int q=0;q<2;q++){
            int idx=tid+q*256; int m=idx>>3, kq=idx&7;
            float4 v=*(const float4*)&W[(n0+m)*7680 + kbase+k0+4*kq];
            sW[m][2*kq]  =make_float2(v.x,v.y);
            sW[m][2*kq+1]=make_float2(v.z,v.w);
        }
        __syncthreads();
#pragma unroll
        for (int p=0;p<16;p++){
            u64 av[8], wv[4];
#pragma unroll
            for (int i=0;i<8;i++) av[i]=*(const u64*)&sA[ty+16*i][p];
#pragma unroll
            for (int j=0;j<4;j++) wv[j]=*(const u64*)&sW[tx+16*j][p];
#pragma unroll
            for (int i=0;i<8;i++)
#pragma unroll
                for (int j=0;j<4;j++) acc[i][j]=f2fma(av[i],wv[j],acc[i][j]);
        }
        __syncthreads();
    }
#pragma unroll
    for (int i=0;i<8;i++){
        int gm=m0+ty+16*i;
#pragma unroll
        for (int j=0;j<4;j++){
            int gn=n0+tx+16*j;
            float lo,hi; upk(acc[i][j],lo,hi);
            g_p1[(kz*1024+gm)*512+gn]=lo+hi;
        }
    }
}

__global__ void fc1red_kernel(const float* __restrict__ bias)
{
    int i=blockIdx.x*blockDim.x+threadIdx.x;
    float s=g_p1[i]+g_p1[524288+i]+g_p1[2*524288+i]+g_p1[3*524288+i];
    s+=bias[i&511];
    g_z1[i]=fmaxf(s,0.f);
}

__global__ void __launch_bounds__(256) gemm_kernel(const float* __restrict__ A,
                                                   const float* __restrict__ W,
                                                   const float* __restrict__ bias,
                                                   float* __restrict__ C,
                                                   int M, int N, int K, int relu)
{
    __shared__ float sA[64][17];
    __shared__ float sW[64][17];
    const int tid=threadIdx.x;
    const int m0=blockIdx.y*64, n0=blockIdx.x*64;
    const int tr=(tid/16)*4, tc=(tid%16)*4;
    float acc[4][4];
#pragma unroll
    for (int i=0;i<4;i++)
#pragma unroll
        for (int j=0;j<4;j++) acc[i][j]=0.f;
    for (int k0=0;k0<K;k0+=16){
        for (int i=tid;i<1024;i+=256){
            int k=i&15, r=i>>4;
            int gm=m0+r, gk=k0+k;
            sA[r][k]=(gm<M && gk<K)? A[gm*K+gk] : 0.f;
            int gn=n0+r;
            sW[r][k]=(gn<N && gk<K)? W[gn*K+gk] : 0.f;
        }
        __syncthreads();
#pragma unroll
        for (int k=0;k<16;k++){
            float a[4], w[4];
#pragma unroll
            for (int i=0;i<4;i++) a[i]=sA[tr+i][k];
#pragma unroll
            for (int j=0;j<4;j++) w[j]=sW[tc+j][k];
#pragma unroll
            for (int i=0;i<4;i++)
#pragma unroll
                for (int j=0;j<4;j++) acc[i][j]=fmaf(a[i],w[j],acc[i][j]);
        }
        __syncthreads();
    }
#pragma unroll
    for (int i=0;i<4;i++){
        int gm=m0+tr+i;
        if (gm>=M) continue;
#pragma unroll
        for (int j=0;j<4;j++){
            int gn=n0+tc+j;
            if (gn>=N) continue;
            float v=acc[i][j]+bias[gn];
            if (relu) v=fmaxf(v,0.f);
            C[gm*N+gn]=v;
        }
    }
}

__global__ void ei_kernel(const int* __restrict__ eidx, float* __restrict__ out)
{
    int e=blockIdx.x*blockDim.x+threadIdx.x;
    if (e>=ET) return;
    int s,d;
    if (e<NE){ s=eidx[e]; d=eidx[NE+e]; }
    else { s=e-NE; d=e-NE; }
    out[EI_OFF+e]    =(float)s;
    out[EI_OFF+ET+e] =(float)d;
}

extern "C" void kernel_launch(void* const* d_in, const int* in_sizes, int n_in,
                              void* d_out, int out_size)
{
    const float* x      =(const float*)d_in[0];
    const float* gat_Wl =(const float*)d_in[1];
    const float* gat_bl =(const float*)d_in[2];
    const float* gat_Wr =(const float*)d_in[3];
    const float* gat_br =(const float*)d_in[4];
    const float* gat_att=(const float*)d_in[5];
    const float* gat_bias=(const float*)d_in[6];
    const float* tcn0_w =(const float*)d_in[7];
    const float* ln0_w  =(const float*)d_in[9];
    const float* ln0_b  =(const float*)d_in[10];
    const float* tcn1_w =(const float*)d_in[11];
    const float* ln1_w  =(const float*)d_in[13];
    const float* ln1_b  =(const float*)d_in[14];
    const float* ds1_w  =(const float*)d_in[15];
    const float* ds1_b  =(const float*)d_in[16];
    const float* tcn2_w =(const float*)d_in[17];
    const float* ln2_w  =(const float*)d_in[19];
    const float* ln2_b  =(const float*)d_in[20];
    const float* ds2_w  =(const float*)d_in[21];
    const float* ds2_b  =(const float*)d_in[22];
    const float* fc1_w  =(const float*)d_in[23];
    const float* fc1_b  =(const float*)d_in[24];
    const float* fc2_w  =(const float*)d_in[25];
    const float* fc2_b  =(const float*)d_in[26];
    const float* fc3_w  =(const float*)d_in[27];
    const float* fc3_b  =(const float*)d_in[28];
    const int*   edge   =(const int*)d_in[29];
    float* out=(float*)d_out;

    cudaFuncSetAttribute(attn_kernel, cudaFuncAttributeMaxDynamicSharedMemorySize, ATTN_SMEM_BYTES);
    cudaFuncSetAttribute(conv_mma<0>, cudaFuncAttributeMaxDynamicSharedMemorySize, CONV_SMEM);
    cudaFuncSetAttribute(conv_mma<1>, cudaFuncAttributeMaxDynamicSharedMemorySize, CONV_SMEM);
    cudaFuncSetAttribute(conv_mma<2>, cudaFuncAttributeMaxDynamicSharedMemorySize, CONV_SMEM);

    prep_kernel<<<1024,256>>>(gat_Wl, gat_Wr, tcn0_w, tcn1_w, tcn2_w, ds1_w, ds2_w);
    xform_kernel<<<NL/32,256>>>(x, gat_bl, gat_br);

    int write_alpha = (out_size >= ALPHA_OFF + ALPHA_LEN) ? 1 : 0;
    attn_kernel<<<NB,256,ATTN_SMEM_BYTES>>>(edge, gat_att, gat_bias, out, write_alpha);

    void *ph=nullptr,*py0=nullptr,*py1=nullptr,*pz=nullptr,*pz1=nullptr,*pz2=nullptr;
    void *a0h,*a0l,*a1h,*a1l,*a2h,*a2l,*d1h,*d1l,*d2h,*d2l;
    cudaGetSymbolAddress(&ph,  g_h);  cudaGetSymbolAddress(&py0, g_y0);
    cudaGetSymbolAddress(&py1, g_y1); cudaGetSymbolAddress(&pz,  g_z);
    cudaGetSymbolAddress(&pz1, g_z1); cudaGetSymbolAddress(&pz2, g_z2);
    cudaGetSymbolAddress(&a0h, g_A0H); cudaGetSymbolAddress(&a0l, g_A0L);
    cudaGetSymbolAddress(&a1h, g_A1H); cudaGetSymbolAddress(&a1l, g_A1L);
    cudaGetSymbolAddress(&a2h, g_A2H); cudaGetSymbolAddress(&a2l, g_A2L);
    cudaGetSymbolAddress(&d1h, g_D1H); cudaGetSymbolAddress(&d1l, g_D1L);
    cudaGetSymbolAddress(&d2h, g_D2H); cudaGetSymbolAddress(&d2l, g_D2L);

    conv_mma<0><<<NB/2,512,CONV_SMEM>>>((const float*)ph,
        (const uint4*)a0h,(const uint4*)a0l,(const uint4*)a0h,(const uint4*)a0l,
        nullptr, ln0_w, ln0_b, (float*)py0);
    conv_mma<1><<<NB/2,512,CONV_SMEM>>>((const float*)py0,
        (const uint4*)a1h,(const uint4*)a1l,(const uint4*)d1h,(const uint4*)d1l,
        ds1_b, ln1_w, ln1_b, (float*)py1);
    conv_mma<2><<<NB/2,512,CONV_SMEM>>>((const float*)py1,
        (const uint4*)a2h,(const uint4*)a2l,(const uint4*)d2h,(const uint4*)d2l,
        ds2_b, ln2_w, ln2_b, (float*)pz);

    fc1_kernel<<<dim3(8,8,SK),256>>>((const float*)pz, fc1_w);
    fc1red_kernel<<<(1024*512)/256,256>>>(fc1_b);

    gemm_kernel<<<dim3(256/64, NB/64),256>>>((const float*)pz1, fc2_w, fc2_b, (float*)pz2, NB, 256, 512, 1);
    gemm_kernel<<<dim3((144+63)/64, NB/64),256>>>((const float*)pz2, fc3_w, fc3_b, out, NB, 144, 256, 0);

    if (out_size >= EI_OFF + EI_LEN)
        ei_kernel<<<(ET+255)/256,256>>>(edge, out);
}

// round 11
// speedup vs baseline: 1.1460x; 1.0715x over previous
#include <cuda_runtime.h>
#include <cuda_bf16.h>
#include <cstdint>

#define NN   30
#define HH   4
#define CC   64
#define HC   256
#define FIN  64
#define NB   1024
#define EPG  240
#define NE   (NB*EPG)
#define NL   (NB*NN)
#define ET   (NE+NL)
#define EG   (EPG+NN)
#define OUT_LEN   (NB*144)
#define ALPHA_OFF OUT_LEN
#define ALPHA_LEN (ET*HH)
#define EI_OFF    (ALPHA_OFF+ALPHA_LEN)
#define EI_LEN    (2*ET)
#define LN_EPS 1e-5f
#define NSLOPE 0.2f
#define RS 40

typedef unsigned long long u64;

__device__ __forceinline__ u64 pk2(float a, float b){
    u64 r; asm("mov.b64 %0,{%1,%2};":"=l"(r):"f"(a),"f"(b)); return r;
}
__device__ __forceinline__ u64 f2fma(u64 a, u64 b, u64 c){
    u64 d; asm("fma.rn.f32x2 %0,%1,%2,%3;":"=l"(d):"l"(a),"l"(b),"l"(c)); return d;
}
__device__ __forceinline__ void upk(u64 v, float& lo, float& hi){
    asm("mov.b64 {%0,%1},%2;":"=f"(lo),"=f"(hi):"l"(v));
}

__device__ __forceinline__ void mma16816(float c[4], uint4 a, uint32_t b0, uint32_t b1){
    asm volatile("mma.sync.aligned.m16n8k16.row.col.f32.bf16.bf16.f32 "
        "{%0,%1,%2,%3},{%4,%5,%6,%7},{%8,%9},{%0,%1,%2,%3};"
        : "+f"(c[0]),"+f"(c[1]),"+f"(c[2]),"+f"(c[3])
        : "r"(a.x),"r"(a.y),"r"(a.z),"r"(a.w),"r"(b0),"r"(b1));
}

// ---------------- device scratch ----------------
__device__ float g_WlT[FIN*HC];
__device__ float g_WrT[FIN*HC];
__device__ float g_xl[NL*HC];
__device__ float g_xr[NL*HC];
__device__ float g_h [(size_t)NB*HC*RS];
__device__ float g_y0[(size_t)NB*256*RS];
__device__ float g_y1[(size_t)NB*512*RS];
__device__ float g_z [NB*HC*NN];
__device__ float g_z1[NB*512];
__device__ float g_z2[NB*256];
#define SK 4
__device__ float g_p1[SK*1024*512];

// A-fragment-packed weights (uint4 per lane per fragment), k-permuted for LDS.64 B loads
__device__ uint4 g_A0H[24576], g_A0L[24576];
__device__ uint4 g_A1H[49152], g_A1L[49152];
__device__ uint4 g_D1H[16384], g_D1L[16384];
__device__ uint4 g_A2H[49152], g_A2L[49152];
__device__ uint4 g_D2H[16384], g_D2L[16384];

__device__ __forceinline__ uint32_t packbf(float v0, float v1, int lo){
    __nv_bfloat16 h0=__float2bfloat16(v0), h1=__float2bfloat16(v1);
    if (lo){ h0=__float2bfloat16(v0-__bfloat162float(h0)); h1=__float2bfloat16(v1-__bfloat162float(h1)); }
    return (uint32_t)__bfloat16_as_ushort(h0) | ((uint32_t)__bfloat16_as_ushort(h1)<<16);
}

// k-permutation: mma slot pair for quad q at lane tc reads cin offset tc*4 + (q>>1)*2
__device__ void fill_convA(uint32_t* H, uint32_t* L, const float* w, int Cin, int MT, int nslots,
                           int t0, int stride)
{
    for (int i=t0;i<nslots;i+=stride){
        int q=i&3, lane=(i>>2)&31, mtg=(i>>7)%MT, kstep=i/(MT*128);
        int g=lane>>2, tc=lane&3;
        int m=mtg*16 + g + (q&1)*8;
        int kk=kstep*16 + tc*4 + (q>>1)*2;
        int t=kk/Cin, cin=kk-t*Cin;
        float v0=w[(m*Cin+cin)*3+t], v1=w[(m*Cin+cin+1)*3+t];
        H[i]=packbf(v0,v1,0); L[i]=packbf(v0,v1,1);
    }
}
__device__ void fill_dsA(uint32_t* H, uint32_t* L, const float* w, int Cin, int MT, int nslots,
                         int t0, int stride)
{
    for (int i=t0;i<nslots;i+=stride){
        int q=i&3, lane=(i>>2)&31, mtg=(i>>7)%MT, kstep=i/(MT*128);
        int g=lane>>2, tc=lane&3;
        int m=mtg*16 + g + (q&1)*8;
        int cin=kstep*16 + tc*4 + (q>>1)*2;
        float v0=w[m*Cin+cin], v1=w[m*Cin+cin+1];
        H[i]=packbf(v0,v1,0); L[i]=packbf(v0,v1,1);
    }
}

__global__ void prep_kernel(const float* __restrict__ Wl, const float* __restrict__ Wr,
                            const float* __restrict__ w0, const float* __restrict__ w1,
                            const float* __restrict__ w2, const float* __restrict__ d1,
                            const float* __restrict__ d2)
{
    int t0 = blockIdx.x*blockDim.x + threadIdx.x;
    int stride = gridDim.x*blockDim.x;
    for (int i=t0;i<FIN*HC;i+=stride){ int j=i%HC,k=i/HC; g_WlT[i]=Wl[j*FIN+k]; g_WrT[i]=Wr[j*FIN+k]; }
    fill_convA((uint32_t*)g_A0H,(uint32_t*)g_A0L, w0, 256, 16,  98304, t0, stride);
    fill_convA((uint32_t*)g_A1H,(uint32_t*)g_A1L, w1, 256, 32, 196608, t0, stride);
    fill_convA((uint32_t*)g_A2H,(uint32_t*)g_A2L, w2, 512, 16, 196608, t0, stride);
    fill_dsA  ((uint32_t*)g_D1H,(uint32_t*)g_D1L, d1, 256, 32,  65536, t0, stride);
    fill_dsA  ((uint32_t*)g_D2H,(uint32_t*)g_D2L, d2, 512, 16,  65536, t0, stride);
}

__global__ void __launch_bounds__(256) xform_kernel(const float* __restrict__ x,
                                                    const float* __restrict__ bl,
                                                    const float* __restrict__ br)
{
    __shared__ float xs[32*FIN];
    const int base = blockIdx.x*32;
    const int tid = threadIdx.x;
    for (int i=tid;i<32*FIN;i+=256) xs[i]=x[base*FIN+i];
    __syncthreads();
    float accl[32], accr[32];
#pragma unroll
    for (int n=0;n<32;n++){ accl[n]=0.f; accr[n]=0.f; }
    const int j = tid;
    for (int k=0;k<FIN;k++){
        float wl=g_WlT[k*HC+j], wr=g_WrT[k*HC+j];
#pragma unroll
        for (int n=0;n<32;n++){ float xv=xs[n*FIN+k]; accl[n]=fmaf(wl,xv,accl[n]); accr[n]=fmaf(wr,xv,accr[n]); }
    }
    float blv=bl[j], brv=br[j];
#pragma unroll
    for (int n=0;n<32;n++){
        g_xl[(base+n)*HC+j]=accl[n]+blv;
        g_xr[(base+n)*HC+j]=accr[n]+brv;
    }
}

#define ATTN_SMEM_BYTES (18272*4 + 901*4 + 16)
__global__ void __launch_bounds__(256) attn_kernel(const int* __restrict__ eidx,
                                                   const float* __restrict__ att,
                                                   const float* __restrict__ gbias,
                                                   float* __restrict__ out,
                                                   int write_alpha)
{
    extern __shared__ char smemraw[];
    float* xl_s   = (float*)smemraw;
    float* xr_s   = xl_s + 7680;
    float* att_s  = xr_s + 7680;
    float* bias_s = att_s + 256;
    float* esc    = bias_s + 256;
    float* alp    = esc + 1080;
    float* mmax   = alp + 1080;
    float* ssum   = mmax + 120;
    int*   srcl   = (int*)(ssum + 120);
    int*   dstl   = srcl + 270;
    int*   deg    = dstl + 270;
    int*   off    = deg + 30;
    int*   pos    = off + 31;
    int*   order  = pos + 30;
    const int b = blockIdx.x, tid = threadIdx.x;
    const int lane = tid&31, wrp = tid>>5;

    for (int i=tid;i<7680;i+=256){ xl_s[i]=g_xl[b*7680+i]; xr_s[i]=g_xr[b*7680+i]; }
    for (int i=tid;i<256;i+=256){ att_s[i]=att[i]; bias_s[i]=gbias[i]; }
    if (tid<30) deg[tid]=0;
    __syncthreads();
    for (int e=tid;e<EG;e+=256){
        int s,d;
        if (e<EPG){ s=eidx[b*EPG+e]-b*NN; d=eidx[NE+b*EPG+e]-b*NN; }
        else      { s=e-EPG; d=e-EPG; }
        srcl[e]=s; dstl[e]=d;
        atomicAdd(&deg[d],1);
    }
    __syncthreads();
    if (tid==0){ off[0]=0; for (int n=0;n<NN;n++) off[n+1]=off[n]+deg[n]; }
    __syncthreads();
    if (tid<30) pos[tid]=off[tid];
    __syncthreads();
    for (int e=tid;e<EG;e+=256){ int slot=atomicAdd(&pos[dstl[e]],1); order[slot]=e; }
    __syncthreads();

    // scores: one warp per (edge,head); lanes sweep channels (conflict-free LDS)
    for (int p=wrp; p<EG*HH; p+=8){
        int e=p>>2, h=p&3;
        const float* ps=&xl_s[srcl[e]*HC + h*CC];
        const float* pd=&xr_s[dstl[e]*HC + h*CC];
        const float* pa=&att_s[h*CC];
        float acc=0.f;
#pragma unroll
        for (int cc=0; cc<2; cc++){
            int c = lane + cc*32;
            float v = ps[c]+pd[c];
            v = v>0.f ? v : NSLOPE*v;
            acc = fmaf(v, pa[c], acc);
        }
        acc += __shfl_xor_sync(0xffffffffu, acc, 16);
        acc += __shfl_xor_sync(0xffffffffu, acc, 8);
        acc += __shfl_xor_sync(0xffffffffu, acc, 4);
        acc += __shfl_xor_sync(0xffffffffu, acc, 2);
        acc += __shfl_xor_sync(0xffffffffu, acc, 1);
        if (lane==0) esc[p]=acc;
    }
    __syncthreads();

    for (int idx=tid; idx<NN*HH; idx+=256){
        int n=idx>>2, h=idx&3;
        float m=-1e30f;
        for (int i=off[n];i<off[n+1];i++) m=fmaxf(m, esc[order[i]*HH+h]);
        float s=0.f;
        for (int i=off[n];i<off[n+1];i++) s+=__expf(esc[order[i]*HH+h]-m);
        mmax[idx]=m; ssum[idx]=s;
    }
    __syncthreads();
    for (int idx=tid; idx<EG*HH; idx+=256){
        int e=idx>>2, h=idx&3;
        int d=dstl[e];
        float a=__expf(esc[idx]-mmax[d*HH+h])/ssum[d*HH+h];
        alp[idx]=a;
        if (write_alpha){
            int gid = (e<EPG) ? (b*EPG+e) : (NE + b*NN + (e-EPG));
            out[ALPHA_OFF + gid*HH + h]=a;
        }
    }
    __syncthreads();
    {
        const int j = tid;
        const int h = j>>6;
        for (int n=0;n<NN;n++){
            float acc=0.f;
            for (int i=off[n];i<off[n+1];i++){
                int e=order[i];
                acc = fmaf(alp[e*HH+h], xl_s[srcl[e]*HC+j], acc);
            }
            float v=acc+bias_s[j];
            xr_s[j*NN+n]=fmaxf(v,0.f);
        }
    }
    __syncthreads();
    for (int i=tid;i<256*RS;i+=256){
        int c=i/RS, col=i-c*RS;
        float v = (col>=4 && col<34) ? xr_s[c*NN + col-4] : 0.f;
        g_h[(size_t)b*256*RS + i]=v;
    }
}

// ================= mma.sync TCN conv layer (512 thr, LDS.64 B, ds folded into tap 1) =================
#define CS 272
#define CONV_SMEM (2*2*40*CS*2)   // 87040B

template<int MODE>
__global__ void __launch_bounds__(512,1) conv_mma(
    const float* __restrict__ in,
    const uint4* __restrict__ AH, const uint4* __restrict__ AL,
    const uint4* __restrict__ DH, const uint4* __restrict__ DL,
    const float* __restrict__ db,
    const float* __restrict__ lnw, const float* __restrict__ lnb,
    float* __restrict__ outp)
{
    constexpr int Cin   = (MODE==2)?512:256;
    constexpr int COUT  = (MODE==1)?512:256;
    constexpr int MT    = (MODE==1)?32:16;
    constexpr int MP    = (MODE==1)?2:1;
    constexpr int PH    = (MODE==2)?2:1;
    constexpr int DIL   = (MODE==0)?1:((MODE==1)?2:4);
    constexpr bool HASDS= (MODE>=1);
    constexpr int KS_T  = Cin/16;

    extern __shared__ __nv_bfloat16 sm_bf[];
    __nv_bfloat16* sH = sm_bf;
    __nv_bfloat16* sL = sm_bf + 2*40*CS;
    __shared__ float s_lnw[32], s_lnb[32];

    const int tid=threadIdx.x, lane=tid&31, wid=tid>>5;
    const int g=lane>>2, tc=lane&3;
    const int b0=blockIdx.x*2;
    const int nhalf = wid&1;
    const int mtp   = wid>>1;

    if (tid<30){ s_lnw[tid]=lnw[tid]; s_lnb[tid]=lnb[tid]; }

    for (int mp=0; mp<MP; mp++){
        float acc[2][4][4];
        float dsacc[HASDS?2:1][HASDS?4:1][HASDS?4:1];
#pragma unroll
        for (int a=0;a<2;a++)
#pragma unroll
            for (int f=0;f<4;f++)
#pragma unroll
                for (int q=0;q<4;q++) acc[a][f][q]=0.f;
        if constexpr(HASDS){
#pragma unroll
            for (int a=0;a<2;a++)
#pragma unroll
                for (int f=0;f<4;f++)
#pragma unroll
                    for (int q=0;q<4;q++) dsacc[a][f][q]=0.f;
        }

        for (int ph=0; ph<PH; ph++){
            if (mp==0){
                if (ph>0) __syncthreads();
                for (int idx=tid; idx<2*256*RS; idx+=512){
                    int gr = idx/(256*RS);
                    int r  = idx - gr*256*RS;
                    int c  = r/RS;
                    int l  = r - c*RS;
                    float v = in[(((size_t)(b0+gr))*Cin + ph*256 + c)*RS + l];
                    __nv_bfloat16 h=__float2bfloat16(v);
                    int sidx=(gr*40+l)*CS+c;
                    sH[sidx]=h;
                    sL[sidx]=__float2bfloat16(v-__bfloat162float(h));
                }
            }
            __syncthreads();

            const int mtile0 = mp*16 + mtp*2;
            const int sb0 = (nhalf*40 + 4 + g)*CS + tc*4;

            if constexpr(MODE==0){
                // linear kstep: abase advances MT*32 per iteration; depth-2 A prefetch
                int anext = mtile0*32 + lane;
                uint4 bH0[2], bH1[2], bL0[2], bL1[2];
                bH0[0]=AH[anext]; bH1[0]=AH[anext+32]; bL0[0]=AL[anext]; bL1[0]=AL[anext+32];
                anext += MT*32;
                bH0[1]=AH[anext]; bH1[1]=AH[anext+32]; bL0[1]=AL[anext]; bL1[1]=AL[anext+32];
                anext += MT*32;
#pragma unroll
                for (int t=0;t<3;t++){
                    const int srow = sb0 + DIL*(t-1)*CS;
#pragma unroll 4
                    for (int ch=0; ch<16; ch++){
                        const int it = t*16+ch;
                        const int sel = it&1;
                        uint4 ah0=bH0[sel], ah1=bH1[sel], al0=bL0[sel], al1=bL1[sel];
                        if (it+2<48){
                            bH0[sel]=AH[anext]; bH1[sel]=AH[anext+32];
                            bL0[sel]=AL[anext]; bL1[sel]=AL[anext+32];
                            anext += MT*32;
                        }
                        uint2 BH[4], BL[4];
#pragma unroll
                        for (int f=0;f<4;f++){
                            BH[f]=*(const uint2*)(sH + srow + f*(8*CS) + ch*16);
                            BL[f]=*(const uint2*)(sL + srow + f*(8*CS) + ch*16);
                        }
#pragma unroll
                        for (int f=0;f<4;f++){
                            mma16816(acc[0][f], ah0, BH[f].x,BH[f].y);
                            mma16816(acc[1][f], ah1, BH[f].x,BH[f].y);
                        }
#pragma unroll
                        for (int f=0;f<4;f++){
                            mma16816(acc[0][f], al0, BH[f].x,BH[f].y);
                            mma16816(acc[1][f], al1, BH[f].x,BH[f].y);
                        }
#pragma unroll
                        for (int f=0;f<4;f++){
                            mma16816(acc[0][f], ah0, BL[f].x,BL[f].y);
                            mma16816(acc[1][f], ah1, BL[f].x,BL[f].y);
                        }
                    }
                }
            } else {
#pragma unroll
            for (int t=0;t<3;t++){
                int abase = ((t*KS_T + ph*16)*MT + mtile0)*32 + lane;
                const int srow = sb0 + DIL*(t-1)*CS;
                if (HASDS && t==1){
                    int dbase = ((ph*16)*MT + mtile0)*32 + lane;
                    for (int ch=0; ch<16; ch++){
                        uint4 ah0=AH[abase], ah1=AH[abase+32], al0=AL[abase], al1=AL[abase+32];
                        uint4 dh0=DH[dbase], dh1=DH[dbase+32], dl0=DL[dbase], dl1=DL[dbase+32];
                        uint2 BH[4], BL[4];
#pragma unroll
                        for (int f=0;f<4;f++){
                            BH[f]=*(const uint2*)(sH + srow + f*(8*CS) + ch*16);
                            BL[f]=*(const uint2*)(sL + srow + f*(8*CS) + ch*16);
                        }
#pragma unroll
                        for (int f=0;f<4;f++){
                            mma16816(acc[0][f], ah0, BH[f].x,BH[f].y);
                            mma16816(acc[1][f], ah1, BH[f].x,BH[f].y);
                        }
#pragma unroll
                        for (int f=0;f<4;f++){
                            mma16816(acc[0][f], al0, BH[f].x,BH[f].y);
                            mma16816(acc[1][f], al1, BH[f].x,BH[f].y);
                        }
#pragma unroll
                        for (int f=0;f<4;f++){
                            mma16816(acc[0][f], ah0, BL[f].x,BL[f].y);
                            mma16816(acc[1][f], ah1, BL[f].x,BL[f].y);
                        }
#pragma unroll
                        for (int f=0;f<4;f++){
                            mma16816(dsacc[0][f], dh0, BH[f].x,BH[f].y);
                            mma16816(dsacc[1][f], dh1, BH[f].x,BH[f].y);
                        }
#pragma unroll
                        for (int f=0;f<4;f++){
                            mma16816(dsacc[0][f], dl0, BH[f].x,BH[f].y);
                            mma16816(dsacc[1][f], dl1, BH[f].x,BH[f].y);
                        }
#pragma unroll
                        for (int f=0;f<4;f++){
                            mma16816(dsacc[0][f], dh0, BL[f].x,BL[f].y);
                            mma16816(dsacc[1][f], dh1, BL[f].x,BL[f].y);
                        }
                        abase += MT*32; dbase += MT*32;
                    }
                } else {
                    uint4 ah0=AH[abase], ah1=AH[abase+32], al0=AL[abase], al1=AL[abase+32];
                    for (int ch=0; ch<16; ch++){
                        uint2 BH[4], BL[4];
#pragma unroll
                        for (int f=0;f<4;f++){
                            BH[f]=*(const uint2*)(sH + srow + f*(8*CS) + ch*16);
                            BL[f]=*(const uint2*)(sL + srow + f*(8*CS) + ch*16);
                        }
                        int nbase = abase + ((ch<15)? MT*32 : 0);
                        uint4 nh0=AH[nbase], nh1=AH[nbase+32], nl0=AL[nbase], nl1=AL[nbase+32];
#pragma unroll
                        for (int f=0;f<4;f++){
                            mma16816(acc[0][f], ah0, BH[f].x,BH[f].y);
                            mma16816(acc[1][f], ah1, BH[f].x,BH[f].y);
                        }
#pragma unroll
                        for (int f=0;f<4;f++){
                            mma16816(acc[0][f], al0, BH[f].x,BH[f].y);
                            mma16816(acc[1][f], al1, BH[f].x,BH[f].y);
                        }
#pragma unroll
                        for (int f=0;f<4;f++){
                            mma16816(acc[0][f], ah0, BL[f].x,BL[f].y);
                            mma16816(acc[1][f], ah1, BL[f].x,BL[f].y);
                        }
                        abase=nbase; ah0=nh0; ah1=nh1; al0=nl0; al1=nl1;
                    }
                }
            }
            }
        }

        // ---- epilogue ----
        const int gr = nhalf;
#pragma unroll
        for (int mt=0; mt<2; mt++){
            const int mrow0 = mp*256 + (mtp*2+mt)*16 + g;
#pragma unroll
            for (int half=0; half<2; half++){
                const int mrow = mrow0 + half*8;
                float dbv = 0.f;
                if constexpr(HASDS) dbv = __ldg(&db[mrow]);
                float s=0.f;
#pragma unroll
                for (int f=0; f<4; f++)
#pragma unroll
                    for (int i=0;i<2;i++){
                        int l=f*8+tc*2+i;
                        if (l<30) s+=acc[mt][f][half*2+i];
                    }
                s += __shfl_xor_sync(0xffffffffu,s,1);
                s += __shfl_xor_sync(0xffffffffu,s,2);
                float mean = s*(1.f/30.f);
                float qv=0.f;
#pragma unroll
                for (int f=0; f<4; f++)
#pragma unroll
                    for (int i=0;i<2;i++){
                        int l=f*8+tc*2+i;
                        if (l<30){ float d=acc[mt][f][half*2+i]-mean; qv=fmaf(d,d,qv); }
                    }
                qv += __shfl_xor_sync(0xffffffffu,qv,1);
                qv += __shfl_xor_sync(0xffffffffu,qv,2);
                float rsn = rsqrtf(qv*(1.f/30.f)+LN_EPS);

                size_t rb;
                if constexpr(MODE==2) rb = (((size_t)(b0+gr))*256 + mrow)*(size_t)NN;
                else                  rb = (((size_t)(b0+gr))*COUT + mrow)*(size_t)RS;
#pragma unroll
                for (int f=0; f<4; f++){
                    int l0=f*8+tc*2;
                    if (l0>=30) continue;
                    float o0,o1;
                    {
                        float v=(acc[mt][f][half*2+0]-mean)*rsn*s_lnw[l0]+s_lnb[l0];
                        o0=fmaxf(v,0.f);
                        v=(acc[mt][f][half*2+1]-mean)*rsn*s_lnw[l0+1]+s_lnb[l0+1];
                        o1=fmaxf(v,0.f);
                    }
                    if constexpr(MODE==0){
                        float2 res=*(const float2*)&in[(((size_t)(b0+gr))*256 + mrow)*RS + 4 + l0];
                        o0+=res.x; o1+=res.y;
                    } else {
                        o0 += dsacc[mt][f][half*2+0] + dbv;
                        o1 += dsacc[mt][f][half*2+1] + dbv;
                    }
                    if constexpr(MODE==2) *(float2*)&outp[rb+l0]   = make_float2(o0,o1);
                    else                  *(float2*)&outp[rb+4+l0] = make_float2(o0,o1);
                }
                if constexpr(MODE!=2){
                    if (tc==0) *(float4*)&outp[rb] = make_float4(0.f,0.f,0.f,0.f);
                    if (tc==3){
                        *(float2*)&outp[rb+34]=make_float2(0.f,0.f);
                        *(float4*)&outp[rb+36]=make_float4(0.f,0.f,0.f,0.f);
                    }
                }
            }
        }
    }
}

// ================= fc1: split-K f32x2 GEMM =================
__global__ void __launch_bounds__(256,2) fc1_kernel(const float* __restrict__ A,
                                                    const float* __restrict__ W)
{
    __shared__ float2 sA[128][17];
    __shared__ float2 sW[64][17];
    const int tid=threadIdx.x;
    const int n0=blockIdx.x*64, m0=blockIdx.y*128, kz=blockIdx.z;
    const int ty=tid>>4, tx=tid&15;
    u64 acc[8][4];
    u64 z=pk2(0.f,0.f);
#pragma unroll
    for (int i=0;i<8;i++)
#pragma unroll
        for (int j=0;j<4;j++) acc[i][j]=z;
    const int kbase = kz*(7680/SK);
    for (int k0=0;k0<7680/SK;k0+=32){
#pragma unroll
        for (int q=0;q<4;q++){
            int idx=tid+q*256; int m=idx>>3, kq=idx&7;
            float4 v=*(const float4*)&A[(m0+m)*7680 + kbase+k0+4*kq];
            sA[m][2*kq]  =make_float2(v.x,v.y);
            sA[m][2*kq+1]=make_float2(v.z,v.w);
        }
#pragma unroll
        for (int q=0;q<2;q++){
            int idx=tid+q*256; int m=idx>>3, kq=idx&7;
            float4 v=*(const float4*)&W[(n0+m)*7680 + kbase+k0+4*kq];
            sW[m][2*kq]  =make_float2(v.x,v.y);
            sW[m][2*kq+1]=make_float2(v.z,v.w);
        }
        __syncthreads();
#pragma unroll
        for (int p=0;p<16;p++){
            u64 av[8], wv[4];
#pragma unroll
            for (int i=0;i<8;i++) av[i]=*(const u64*)&sA[ty+16*i][p];
#pragma unroll
            for (int j=0;j<4;j++) wv[j]=*(const u64*)&sW[tx+16*j][p];
#pragma unroll
            for (int i=0;i<8;i++)
#pragma unroll
                for (int j=0;j<4;j++) acc[i][j]=f2fma(av[i],wv[j],acc[i][j]);
        }
        __syncthreads();
    }
#pragma unroll
    for (int i=0;i<8;i++){
        int gm=m0+ty+16*i;
#pragma unroll
        for (int j=0;j<4;j++){
            int gn=n0+tx+16*j;
            float lo,hi; upk(acc[i][j],lo,hi);
            g_p1[(kz*1024+gm)*512+gn]=lo+hi;
        }
    }
}

__global__ void fc1red_kernel(const float* __restrict__ bias)
{
    int i=blockIdx.x*blockDim.x+threadIdx.x;
    float s=g_p1[i]+g_p1[524288+i]+g_p1[2*524288+i]+g_p1[3*524288+i];
    s+=bias[i&511];
    g_z1[i]=fmaxf(s,0.f);
}

__global__ void __launch_bounds__(256) gemm_kernel(const float* __restrict__ A,
                                                   const float* __restrict__ W,
                                                   const float* __restrict__ bias,
                                                   float* __restrict__ C,
                                                   int M, int N, int K, int relu)
{
    __shared__ float sA[64][17];
    __shared__ float sW[64][17];
    const int tid=threadIdx.x;
    const int m0=blockIdx.y*64, n0=blockIdx.x*64;
    const int tr=(tid/16)*4, tc=(tid%16)*4;
    float acc[4][4];
#pragma unroll
    for (int i=0;i<4;i++)
#pragma unroll
        for (int j=0;j<4;j++) acc[i][j]=0.f;
    for (int k0=0;k0<K;k0+=16){
        for (int i=tid;i<1024;i+=256){
            int k=i&15, r=i>>4;
            int gm=m0+r, gk=k0+k;
            sA[r][k]=(gm<M && gk<K)? A[gm*K+gk] : 0.f;
            int gn=n0+r;
            sW[r][k]=(gn<N && gk<K)? W[gn*K+gk] : 0.f;
        }
        __syncthreads();
#pragma unroll
        for (int k=0;k<16;k++){
            float a[4], w[4];
#pragma unroll
            for (int i=0;i<4;i++) a[i]=sA[tr+i][k];
#pragma unroll
            for (int j=0;j<4;j++) w[j]=sW[tc+j][k];
#pragma unroll
            for (int i=0;i<4;i++)
#pragma unroll
                for (int j=0;j<4;j++) acc[i][j]=fmaf(a[i],w[j],acc[i][j]);
        }
        __syncthreads();
    }
#pragma unroll
    for (int i=0;i<4;i++){
        int gm=m0+tr+i;
        if (gm>=M) continue;
#pragma unroll
        for (int j=0;j<4;j++){
            int gn=n0+tc+j;
            if (gn>=N) continue;
            float v=acc[i][j]+bias[gn];
            if (relu) v=fmaxf(v,0.f);
            C[gm*N+gn]=v;
        }
    }
}

__global__ void ei_kernel(const int* __restrict__ eidx, float* __restrict__ out)
{
    int e=blockIdx.x*blockDim.x+threadIdx.x;
    if (e>=ET) return;
    int s,d;
    if (e<NE){ s=eidx[e]; d=eidx[NE+e]; }
    else { s=e-NE; d=e-NE; }
    out[EI_OFF+e]    =(float)s;
    out[EI_OFF+ET+e] =(float)d;
}

extern "C" void kernel_launch(void* const* d_in, const int* in_sizes, int n_in,
                              void* d_out, int out_size)
{
    const float* x      =(const float*)d_in[0];
    const float* gat_Wl =(const float*)d_in[1];
    const float* gat_bl =(const float*)d_in[2];
    const float* gat_Wr =(const float*)d_in[3];
    const float* gat_br =(const float*)d_in[4];
    const float* gat_att=(const float*)d_in[5];
    const float* gat_bias=(const float*)d_in[6];
    const float* tcn0_w =(const float*)d_in[7];
    const float* ln0_w  =(const float*)d_in[9];
    const float* ln0_b  =(const float*)d_in[10];
    const float* tcn1_w =(const float*)d_in[11];
    const float* ln1_w  =(const float*)d_in[13];
    const float* ln1_b  =(const float*)d_in[14];
    const float* ds1_w  =(const float*)d_in[15];
    const float* ds1_b  =(const float*)d_in[16];
    const float* tcn2_w =(const float*)d_in[17];
    const float* ln2_w  =(const float*)d_in[19];
    const float* ln2_b  =(const float*)d_in[20];
    const float* ds2_w  =(const float*)d_in[21];
    const float* ds2_b  =(const float*)d_in[22];
    const float* fc1_w  =(const float*)d_in[23];
    const float* fc1_b  =(const float*)d_in[24];
    const float* fc2_w  =(const float*)d_in[25];
    const float* fc2_b  =(const float*)d_in[26];
    const float* fc3_w  =(const float*)d_in[27];
    const float* fc3_b  =(const float*)d_in[28];
    const int*   edge   =(const int*)d_in[29];
    float* out=(float*)d_out;

    cudaFuncSetAttribute(attn_kernel, cudaFuncAttributeMaxDynamicSharedMemorySize, ATTN_SMEM_BYTES);
    cudaFuncSetAttribute(conv_mma<0>, cudaFuncAttributeMaxDynamicSharedMemorySize, CONV_SMEM);
    cudaFuncSetAttribute(conv_mma<1>, cudaFuncAttributeMaxDynamicSharedMemorySize, CONV_SMEM);
    cudaFuncSetAttribute(conv_mma<2>, cudaFuncAttributeMaxDynamicSharedMemorySize, CONV_SMEM);

    prep_kernel<<<1024,256>>>(gat_Wl, gat_Wr, tcn0_w, tcn1_w, tcn2_w, ds1_w, ds2_w);
    xform_kernel<<<NL/32,256>>>(x, gat_bl, gat_br);

    int write_alpha = (out_size >= ALPHA_OFF + ALPHA_LEN) ? 1 : 0;
    attn_kernel<<<NB,256,ATTN_SMEM_BYTES>>>(edge, gat_att, gat_bias, out, write_alpha);

    void *ph=nullptr,*py0=nullptr,*py1=nullptr,*pz=nullptr,*pz1=nullptr,*pz2=nullptr;
    void *a0h,*a0l,*a1h,*a1l,*a2h,*a2l,*d1h,*d1l,*d2h,*d2l;
    cudaGetSymbolAddress(&ph,  g_h);  cudaGetSymbolAddress(&py0, g_y0);
    cudaGetSymbolAddress(&py1, g_y1); cudaGetSymbolAddress(&pz,  g_z);
    cudaGetSymbolAddress(&pz1, g_z1); cudaGetSymbolAddress(&pz2, g_z2);
    cudaGetSymbolAddress(&a0h, g_A0H); cudaGetSymbolAddress(&a0l, g_A0L);
    cudaGetSymbolAddress(&a1h, g_A1H); cudaGetSymbolAddress(&a1l, g_A1L);
    cudaGetSymbolAddress(&a2h, g_A2H); cudaGetSymbolAddress(&a2l, g_A2L);
    cudaGetSymbolAddress(&d1h, g_D1H); cudaGetSymbolAddress(&d1l, g_D1L);
    cudaGetSymbolAddress(&d2h, g_D2H); cudaGetSymbolAddress(&d2l, g_D2L);

    conv_mma<0><<<NB/2,512,CONV_SMEM>>>((const float*)ph,
        (const uint4*)a0h,(const uint4*)a0l,(const uint4*)a0h,(const uint4*)a0l,
        nullptr, ln0_w, ln0_b, (float*)py0);
    conv_mma<1><<<NB/2,512,CONV_SMEM>>>((const float*)py0,
        (const uint4*)a1h,(const uint4*)a1l,(const uint4*)d1h,(const uint4*)d1l,
        ds1_b, ln1_w, ln1_b, (float*)py1);
    conv_mma<2><<<NB/2,512,CONV_SMEM>>>((const float*)py1,
        (const uint4*)a2h,(const uint4*)a2l,(const uint4*)d2h,(const uint4*)d2l,
        ds2_b, ln2_w, ln2_b, (float*)pz);

    fc1_kernel<<<dim3(8,8,SK),256>>>((const float*)pz, fc1_w);
    fc1red_kernel<<<(1024*512)/256,256>>>(fc1_b);

    gemm_kernel<<<dim3(256/64, NB/64),256>>>((const float*)pz1, fc2_w, fc2_b, (float*)pz2, NB, 256, 512, 1);
    gemm_kernel<<<dim3((144+63)/64, NB/64),256>>>((const float*)pz2, fc3_w, fc3_b, out, NB, 144, 256, 0);

    if (out_size >= EI_OFF + EI_LEN)
        ei_kernel<<<(ET+255)/256,256>>>(edge, out);
}

// round 12
// speedup vs baseline: 1.2939x; 1.1291x over previous
#include <cuda_runtime.h>
#include <cuda_bf16.h>
#include <cstdint>

#define NN   30
#define HH   4
#define CC   64
#define HC   256
#define FIN  64
#define NB   1024
#define EPG  240
#define NE   (NB*EPG)
#define NL   (NB*NN)
#define ET   (NE+NL)
#define EG   (EPG+NN)
#define OUT_LEN   (NB*144)
#define ALPHA_OFF OUT_LEN
#define ALPHA_LEN (ET*HH)
#define EI_OFF    (ALPHA_OFF+ALPHA_LEN)
#define EI_LEN    (2*ET)
#define LN_EPS 1e-5f
#define NSLOPE 0.2f
#define RS 40

typedef unsigned long long u64;

__device__ __forceinline__ void mma16816(float c[4], uint4 a, uint32_t b0, uint32_t b1){
    asm volatile("mma.sync.aligned.m16n8k16.row.col.f32.bf16.bf16.f32 "
        "{%0,%1,%2,%3},{%4,%5,%6,%7},{%8,%9},{%0,%1,%2,%3};"
        : "+f"(c[0]),"+f"(c[1]),"+f"(c[2]),"+f"(c[3])
        : "r"(a.x),"r"(a.y),"r"(a.z),"r"(a.w),"r"(b0),"r"(b1));
}

// ---------------- device scratch ----------------
__device__ float g_WlT[FIN*HC];
__device__ float g_WrT[FIN*HC];
__device__ float g_xl[NL*HC];
__device__ float g_xr[NL*HC];
__device__ float g_h [(size_t)NB*HC*RS];
__device__ float g_y0[(size_t)NB*256*RS];
__device__ float g_y1[(size_t)NB*512*RS];
__device__ float g_z [NB*HC*NN];
__device__ float g_z1[NB*512];
__device__ float g_z2[NB*256];
#define SKF 8
__device__ float g_p1[SKF*1024*512];

// A-fragment-packed weights (uint4 per lane per fragment), k-permuted for LDS.64 B loads
__device__ uint4 g_A0H[24576], g_A0L[24576];
__device__ uint4 g_A1H[49152], g_A1L[49152];
__device__ uint4 g_D1H[16384], g_D1L[16384];
__device__ uint4 g_A2H[49152], g_A2L[49152];
__device__ uint4 g_D2H[16384], g_D2L[16384];
__device__ uint4 g_FH[491520], g_FL[491520];   // fc1: 480 ksteps * 32 mtiles * 32 lanes

__device__ __forceinline__ uint32_t packbf(float v0, float v1, int lo){
    __nv_bfloat16 h0=__float2bfloat16(v0), h1=__float2bfloat16(v1);
    if (lo){ h0=__float2bfloat16(v0-__bfloat162float(h0)); h1=__float2bfloat16(v1-__bfloat162float(h1)); }
    return (uint32_t)__bfloat16_as_ushort(h0) | ((uint32_t)__bfloat16_as_ushort(h1)<<16);
}

// k-permutation: mma slot pair for quad q at lane tc reads k offset tc*4 + (q>>1)*2
__device__ void fill_convA(uint32_t* H, uint32_t* L, const float* w, int Cin, int MT, int nslots,
                           int t0, int stride)
{
    for (int i=t0;i<nslots;i+=stride){
        int q=i&3, lane=(i>>2)&31, mtg=(i>>7)%MT, kstep=i/(MT*128);
        int g=lane>>2, tc=lane&3;
        int m=mtg*16 + g + (q&1)*8;
        int kk=kstep*16 + tc*4 + (q>>1)*2;
        int t=kk/Cin, cin=kk-t*Cin;
        float v0=w[(m*Cin+cin)*3+t], v1=w[(m*Cin+cin+1)*3+t];
        H[i]=packbf(v0,v1,0); L[i]=packbf(v0,v1,1);
    }
}
__device__ void fill_dsA(uint32_t* H, uint32_t* L, const float* w, int Cin, int MT, int nslots,
                         int t0, int stride)
{
    for (int i=t0;i<nslots;i+=stride){
        int q=i&3, lane=(i>>2)&31, mtg=(i>>7)%MT, kstep=i/(MT*128);
        int g=lane>>2, tc=lane&3;
        int m=mtg*16 + g + (q&1)*8;
        int cin=kstep*16 + tc*4 + (q>>1)*2;
        float v0=w[m*Cin+cin], v1=w[m*Cin+cin+1];
        H[i]=packbf(v0,v1,0); L[i]=packbf(v0,v1,1);
    }
}

__global__ void prep_kernel(const float* __restrict__ Wl, const float* __restrict__ Wr,
                            const float* __restrict__ w0, const float* __restrict__ w1,
                            const float* __restrict__ w2, const float* __restrict__ d1,
                            const float* __restrict__ d2, const float* __restrict__ f1)
{
    int t0 = blockIdx.x*blockDim.x + threadIdx.x;
    int stride = gridDim.x*blockDim.x;
    for (int i=t0;i<FIN*HC;i+=stride){ int j=i%HC,k=i/HC; g_WlT[i]=Wl[j*FIN+k]; g_WrT[i]=Wr[j*FIN+k]; }
    fill_convA((uint32_t*)g_A0H,(uint32_t*)g_A0L, w0, 256, 16,  98304, t0, stride);
    fill_convA((uint32_t*)g_A1H,(uint32_t*)g_A1L, w1, 256, 32, 196608, t0, stride);
    fill_convA((uint32_t*)g_A2H,(uint32_t*)g_A2L, w2, 512, 16, 196608, t0, stride);
    fill_dsA  ((uint32_t*)g_D1H,(uint32_t*)g_D1L, d1, 256, 32,  65536, t0, stride);
    fill_dsA  ((uint32_t*)g_D2H,(uint32_t*)g_D2L, d2, 512, 16,  65536, t0, stride);
    fill_dsA  ((uint32_t*)g_FH, (uint32_t*)g_FL,  f1, 7680, 32, 1966080, t0, stride);
}

__global__ void __launch_bounds__(256) xform_kernel(const float* __restrict__ x,
                                                    const float* __restrict__ bl,
                                                    const float* __restrict__ br)
{
    __shared__ float xs[32*FIN];
    const int base = blockIdx.x*32;
    const int tid = threadIdx.x;
    for (int i=tid;i<32*FIN;i+=256) xs[i]=x[base*FIN+i];
    __syncthreads();
    float accl[32], accr[32];
#pragma unroll
    for (int n=0;n<32;n++){ accl[n]=0.f; accr[n]=0.f; }
    const int j = tid;
    for (int k=0;k<FIN;k++){
        float wl=g_WlT[k*HC+j], wr=g_WrT[k*HC+j];
#pragma unroll
        for (int n=0;n<32;n++){ float xv=xs[n*FIN+k]; accl[n]=fmaf(wl,xv,accl[n]); accr[n]=fmaf(wr,xv,accr[n]); }
    }
    float blv=bl[j], brv=br[j];
#pragma unroll
    for (int n=0;n<32;n++){
        g_xl[(base+n)*HC+j]=accl[n]+blv;
        g_xr[(base+n)*HC+j]=accr[n]+brv;
    }
}

#define ATTN_SMEM_BYTES (18272*4 + 901*4 + 16)
__global__ void __launch_bounds__(256) attn_kernel(const int* __restrict__ eidx,
                                                   const float* __restrict__ att,
                                                   const float* __restrict__ gbias,
                                                   float* __restrict__ out,
                                                   int write_alpha)
{
    extern __shared__ char smemraw[];
    float* xl_s   = (float*)smemraw;
    float* xr_s   = xl_s + 7680;
    float* att_s  = xr_s + 7680;
    float* bias_s = att_s + 256;
    float* esc    = bias_s + 256;
    float* alp    = esc + 1080;
    float* mmax   = alp + 1080;
    float* ssum   = mmax + 120;
    int*   srcl   = (int*)(ssum + 120);
    int*   dstl   = srcl + 270;
    int*   deg    = dstl + 270;
    int*   off    = deg + 30;
    int*   pos    = off + 31;
    int*   order  = pos + 30;
    const int b = blockIdx.x, tid = threadIdx.x;
    const int lane = tid&31, wrp = tid>>5;

    for (int i=tid;i<7680;i+=256){ xl_s[i]=g_xl[b*7680+i]; xr_s[i]=g_xr[b*7680+i]; }
    for (int i=tid;i<256;i+=256){ att_s[i]=att[i]; bias_s[i]=gbias[i]; }
    if (tid<30) deg[tid]=0;
    __syncthreads();
    for (int e=tid;e<EG;e+=256){
        int s,d;
        if (e<EPG){ s=eidx[b*EPG+e]-b*NN; d=eidx[NE+b*EPG+e]-b*NN; }
        else      { s=e-EPG; d=e-EPG; }
        srcl[e]=s; dstl[e]=d;
        atomicAdd(&deg[d],1);
    }
    __syncthreads();
    if (tid==0){ off[0]=0; for (int n=0;n<NN;n++) off[n+1]=off[n]+deg[n]; }
    __syncthreads();
    if (tid<30) pos[tid]=off[tid];
    __syncthreads();
    for (int e=tid;e<EG;e+=256){ int slot=atomicAdd(&pos[dstl[e]],1); order[slot]=e; }
    __syncthreads();

    for (int p=wrp; p<EG*HH; p+=8){
        int e=p>>2, h=p&3;
        const float* ps=&xl_s[srcl[e]*HC + h*CC];
        const float* pd=&xr_s[dstl[e]*HC + h*CC];
        const float* pa=&att_s[h*CC];
        float acc=0.f;
#pragma unroll
        for (int cc=0; cc<2; cc++){
            int c = lane + cc*32;
            float v = ps[c]+pd[c];
            v = v>0.f ? v : NSLOPE*v;
            acc = fmaf(v, pa[c], acc);
        }
        acc += __shfl_xor_sync(0xffffffffu, acc, 16);
        acc += __shfl_xor_sync(0xffffffffu, acc, 8);
        acc += __shfl_xor_sync(0xffffffffu, acc, 4);
        acc += __shfl_xor_sync(0xffffffffu, acc, 2);
        acc += __shfl_xor_sync(0xffffffffu, acc, 1);
        if (lane==0) esc[p]=acc;
    }
    __syncthreads();

    for (int idx=tid; idx<NN*HH; idx+=256){
        int n=idx>>2, h=idx&3;
        float m=-1e30f;
        for (int i=off[n];i<off[n+1];i++) m=fmaxf(m, esc[order[i]*HH+h]);
        float s=0.f;
        for (int i=off[n];i<off[n+1];i++) s+=__expf(esc[order[i]*HH+h]-m);
        mmax[idx]=m; ssum[idx]=s;
    }
    __syncthreads();
    for (int idx=tid; idx<EG*HH; idx+=256){
        int e=idx>>2, h=idx&3;
        int d=dstl[e];
        float a=__expf(esc[idx]-mmax[d*HH+h])/ssum[d*HH+h];
        alp[idx]=a;
        if (write_alpha){
            int gid = (e<EPG) ? (b*EPG+e) : (NE + b*NN + (e-EPG));
            out[ALPHA_OFF + gid*HH + h]=a;
        }
    }
    __syncthreads();
    {
        const int j = tid;
        const int h = j>>6;
        for (int n=0;n<NN;n++){
            float acc=0.f;
            for (int i=off[n];i<off[n+1];i++){
                int e=order[i];
                acc = fmaf(alp[e*HH+h], xl_s[srcl[e]*HC+j], acc);
            }
            float v=acc+bias_s[j];
            xr_s[j*NN+n]=fmaxf(v,0.f);
        }
    }
    __syncthreads();
    for (int i=tid;i<256*RS;i+=256){
        int c=i/RS, col=i-c*RS;
        float v = (col>=4 && col<34) ? xr_s[c*NN + col-4] : 0.f;
        g_h[(size_t)b*256*RS + i]=v;
    }
}

// ================= mma.sync TCN conv layer =================
#define CS 272
#define CONV_SMEM (2*2*40*CS*2)   // 87040B

template<int MODE>
__global__ void __launch_bounds__(512,1) conv_mma(
    const float* __restrict__ in,
    const uint4* __restrict__ AH, const uint4* __restrict__ AL,
    const uint4* __restrict__ DH, const uint4* __restrict__ DL,
    const float* __restrict__ db,
    const float* __restrict__ lnw, const float* __restrict__ lnb,
    float* __restrict__ outp)
{
    constexpr int Cin   = (MODE==2)?512:256;
    constexpr int COUT  = (MODE==1)?512:256;
    constexpr int MT    = (MODE==1)?32:16;
    constexpr int MP    = (MODE==1)?2:1;
    constexpr int PH    = (MODE==2)?2:1;
    constexpr int DIL   = (MODE==0)?1:((MODE==1)?2:4);
    constexpr bool HASDS= (MODE>=1);
    constexpr int KS_T  = Cin/16;

    extern __shared__ __nv_bfloat16 sm_bf[];
    __nv_bfloat16* sH = sm_bf;
    __nv_bfloat16* sL = sm_bf + 2*40*CS;
    __shared__ float s_lnw[32], s_lnb[32];

    const int tid=threadIdx.x, lane=tid&31, wid=tid>>5;
    const int g=lane>>2, tc=lane&3;
    const int b0=blockIdx.x*2;
    const int nhalf = wid&1;
    const int mtp   = wid>>1;

    if (tid<30){ s_lnw[tid]=lnw[tid]; s_lnb[tid]=lnb[tid]; }

    for (int mp=0; mp<MP; mp++){
        float acc[2][4][4];
        float dsacc[HASDS?2:1][HASDS?4:1][HASDS?4:1];
#pragma unroll
        for (int a=0;a<2;a++)
#pragma unroll
            for (int f=0;f<4;f++)
#pragma unroll
                for (int q=0;q<4;q++) acc[a][f][q]=0.f;
        if constexpr(HASDS){
#pragma unroll
            for (int a=0;a<2;a++)
#pragma unroll
                for (int f=0;f<4;f++)
#pragma unroll
                    for (int q=0;q<4;q++) dsacc[a][f][q]=0.f;
        }

        for (int ph=0; ph<PH; ph++){
            if (mp==0){
                if (ph>0) __syncthreads();
                for (int idx=tid; idx<2*256*RS; idx+=512){
                    int gr = idx/(256*RS);
                    int r  = idx - gr*256*RS;
                    int c  = r/RS;
                    int l  = r - c*RS;
                    float v = in[(((size_t)(b0+gr))*Cin + ph*256 + c)*RS + l];
                    __nv_bfloat16 h=__float2bfloat16(v);
                    int sidx=(gr*40+l)*CS+c;
                    sH[sidx]=h;
                    sL[sidx]=__float2bfloat16(v-__bfloat162float(h));
                }
            }
            __syncthreads();

            const int mtile0 = mp*16 + mtp*2;
            const int sb0 = (nhalf*40 + 4 + g)*CS + tc*4;

            if constexpr(MODE==0){
                int anext = mtile0*32 + lane;
                uint4 bH0[2], bH1[2], bL0[2], bL1[2];
                bH0[0]=AH[anext]; bH1[0]=AH[anext+32]; bL0[0]=AL[anext]; bL1[0]=AL[anext+32];
                anext += MT*32;
                bH0[1]=AH[anext]; bH1[1]=AH[anext+32]; bL0[1]=AL[anext]; bL1[1]=AL[anext+32];
                anext += MT*32;
#pragma unroll
                for (int t=0;t<3;t++){
                    const int srow = sb0 + DIL*(t-1)*CS;
#pragma unroll 4
                    for (int ch=0; ch<16; ch++){
                        const int it = t*16+ch;
                        const int sel = it&1;
                        uint4 ah0=bH0[sel], ah1=bH1[sel], al0=bL0[sel], al1=bL1[sel];
                        if (it+2<48){
                            bH0[sel]=AH[anext]; bH1[sel]=AH[anext+32];
                            bL0[sel]=AL[anext]; bL1[sel]=AL[anext+32];
                            anext += MT*32;
                        }
                        uint2 BH[4], BL[4];
#pragma unroll
                        for (int f=0;f<4;f++){
                            BH[f]=*(const uint2*)(sH + srow + f*(8*CS) + ch*16);
                            BL[f]=*(const uint2*)(sL + srow + f*(8*CS) + ch*16);
                        }
#pragma unroll
                        for (int f=0;f<4;f++){
                            mma16816(acc[0][f], ah0, BH[f].x,BH[f].y);
                            mma16816(acc[1][f], ah1, BH[f].x,BH[f].y);
                        }
#pragma unroll
                        for (int f=0;f<4;f++){
                            mma16816(acc[0][f], al0, BH[f].x,BH[f].y);
                            mma16816(acc[1][f], al1, BH[f].x,BH[f].y);
                        }
#pragma unroll
                        for (int f=0;f<4;f++){
                            mma16816(acc[0][f], ah0, BL[f].x,BL[f].y);
                            mma16816(acc[1][f], ah1, BL[f].x,BL[f].y);
                        }
                    }
                }
            } else {
#pragma unroll
            for (int t=0;t<3;t++){
                int abase = ((t*KS_T + ph*16)*MT + mtile0)*32 + lane;
                const int srow = sb0 + DIL*(t-1)*CS;
                if (HASDS && t==1){
                    int dbase = ((ph*16)*MT + mtile0)*32 + lane;
                    for (int ch=0; ch<16; ch++){
                        uint4 ah0=AH[abase], ah1=AH[abase+32], al0=AL[abase], al1=AL[abase+32];
                        uint4 dh0=DH[dbase], dh1=DH[dbase+32], dl0=DL[dbase], dl1=DL[dbase+32];
                        uint2 BH[4], BL[4];
#pragma unroll
                        for (int f=0;f<4;f++){
                            BH[f]=*(const uint2*)(sH + srow + f*(8*CS) + ch*16);
                            BL[f]=*(const uint2*)(sL + srow + f*(8*CS) + ch*16);
                        }
#pragma unroll
                        for (int f=0;f<4;f++){
                            mma16816(acc[0][f], ah0, BH[f].x,BH[f].y);
                            mma16816(acc[1][f], ah1, BH[f].x,BH[f].y);
                        }
#pragma unroll
                        for (int f=0;f<4;f++){
                            mma16816(acc[0][f], al0, BH[f].x,BH[f].y);
                            mma16816(acc[1][f], al1, BH[f].x,BH[f].y);
                        }
#pragma unroll
                        for (int f=0;f<4;f++){
                            mma16816(acc[0][f], ah0, BL[f].x,BL[f].y);
                            mma16816(acc[1][f], ah1, BL[f].x,BL[f].y);
                        }
#pragma unroll
                        for (int f=0;f<4;f++){
                            mma16816(dsacc[0][f], dh0, BH[f].x,BH[f].y);
                            mma16816(dsacc[1][f], dh1, BH[f].x,BH[f].y);
                        }
#pragma unroll
                        for (int f=0;f<4;f++){
                            mma16816(dsacc[0][f], dl0, BH[f].x,BH[f].y);
                            mma16816(dsacc[1][f], dl1, BH[f].x,BH[f].y);
                        }
#pragma unroll
                        for (int f=0;f<4;f++){
                            mma16816(dsacc[0][f], dh0, BL[f].x,BL[f].y);
                            mma16816(dsacc[1][f], dh1, BL[f].x,BL[f].y);
                        }
                        abase += MT*32; dbase += MT*32;
                    }
                } else {
                    uint4 ah0=AH[abase], ah1=AH[abase+32], al0=AL[abase], al1=AL[abase+32];
                    for (int ch=0; ch<16; ch++){
                        uint2 BH[4], BL[4];
#pragma unroll
                        for (int f=0;f<4;f++){
                            BH[f]=*(const uint2*)(sH + srow + f*(8*CS) + ch*16);
                            BL[f]=*(const uint2*)(sL + srow + f*(8*CS) + ch*16);
                        }
                        int nbase = abase + ((ch<15)? MT*32 : 0);
                        uint4 nh0=AH[nbase], nh1=AH[nbase+32], nl0=AL[nbase], nl1=AL[nbase+32];
#pragma unroll
                        for (int f=0;f<4;f++){
                            mma16816(acc[0][f], ah0, BH[f].x,BH[f].y);
                            mma16816(acc[1][f], ah1, BH[f].x,BH[f].y);
                        }
#pragma unroll
                        for (int f=0;f<4;f++){
                            mma16816(acc[0][f], al0, BH[f].x,BH[f].y);
                            mma16816(acc[1][f], al1, BH[f].x,BH[f].y);
                        }
#pragma unroll
                        for (int f=0;f<4;f++){
                            mma16816(acc[0][f], ah0, BL[f].x,BL[f].y);
                            mma16816(acc[1][f], ah1, BL[f].x,BL[f].y);
                        }
                        abase=nbase; ah0=nh0; ah1=nh1; al0=nl0; al1=nl1;
                    }
                }
            }
            }
        }

        // ---- epilogue ----
        const int gr = nhalf;
#pragma unroll
        for (int mt=0; mt<2; mt++){
            const int mrow0 = mp*256 + (mtp*2+mt)*16 + g;
#pragma unroll
            for (int half=0; half<2; half++){
                const int mrow = mrow0 + half*8;
                float dbv = 0.f;
                if constexpr(HASDS) dbv = __ldg(&db[mrow]);
                float s=0.f;
#pragma unroll
                for (int f=0; f<4; f++)
#pragma unroll
                    for (int i=0;i<2;i++){
                        int l=f*8+tc*2+i;
                        if (l<30) s+=acc[mt][f][half*2+i];
                    }
                s += __shfl_xor_sync(0xffffffffu,s,1);
                s += __shfl_xor_sync(0xffffffffu,s,2);
                float mean = s*(1.f/30.f);
                float qv=0.f;
#pragma unroll
                for (int f=0; f<4; f++)
#pragma unroll
                    for (int i=0;i<2;i++){
                        int l=f*8+tc*2+i;
                        if (l<30){ float d=acc[mt][f][half*2+i]-mean; qv=fmaf(d,d,qv); }
                    }
                qv += __shfl_xor_sync(0xffffffffu,qv,1);
                qv += __shfl_xor_sync(0xffffffffu,qv,2);
                float rsn = rsqrtf(qv*(1.f/30.f)+LN_EPS);

                size_t rb;
                if constexpr(MODE==2) rb = (((size_t)(b0+gr))*256 + mrow)*(size_t)NN;
                else                  rb = (((size_t)(b0+gr))*COUT + mrow)*(size_t)RS;
#pragma unroll
                for (int f=0; f<4; f++){
                    int l0=f*8+tc*2;
                    if (l0>=30) continue;
                    float o0,o1;
                    {
                        float v=(acc[mt][f][half*2+0]-mean)*rsn*s_lnw[l0]+s_lnb[l0];
                        o0=fmaxf(v,0.f);
                        v=(acc[mt][f][half*2+1]-mean)*rsn*s_lnw[l0+1]+s_lnb[l0+1];
                        o1=fmaxf(v,0.f);
                    }
                    if constexpr(MODE==0){
                        float2 res=*(const float2*)&in[(((size_t)(b0+gr))*256 + mrow)*RS + 4 + l0];
                        o0+=res.x; o1+=res.y;
                    } else {
                        o0 += dsacc[mt][f][half*2+0] + dbv;
                        o1 += dsacc[mt][f][half*2+1] + dbv;
                    }
                    if constexpr(MODE==2) *(float2*)&outp[rb+l0]   = make_float2(o0,o1);
                    else                  *(float2*)&outp[rb+4+l0] = make_float2(o0,o1);
                }
                if constexpr(MODE!=2){
                    if (tc==0) *(float4*)&outp[rb] = make_float4(0.f,0.f,0.f,0.f);
                    if (tc==3){
                        *(float2*)&outp[rb+34]=make_float2(0.f,0.f);
                        *(float4*)&outp[rb+36]=make_float4(0.f,0.f,0.f,0.f);
                    }
                }
            }
        }
    }
}

// ================= fc1: bf16 hi/lo mma GEMM, split-K=8 =================
// CTA: 64 batch x 256 couts; K chunk 960, staged 240 at a time.
#define FC1_SMEM (2*64*240*2)   // 61440B
__global__ void __launch_bounds__(512,1) fc1_mma(
    const float* __restrict__ Z,
    const uint4* __restrict__ FH, const uint4* __restrict__ FL)
{
    extern __shared__ __nv_bfloat16 sm[];
    __nv_bfloat16* sH = sm;
    __nv_bfloat16* sL = sm + 64*240;
    const int tid=threadIdx.x, lane=tid&31, wid=tid>>5;
    const int g=lane>>2, tc=lane&3;
    const int nb0 = blockIdx.x*64;
    const int cb0 = blockIdx.y*256;
    const int kz  = blockIdx.z;
    const int nhalf = wid&1, mtp = wid>>1;
    const int mtile0 = (cb0>>4) + mtp*2;

    float acc[2][4][4];
#pragma unroll
    for (int a=0;a<2;a++)
#pragma unroll
        for (int f=0;f<4;f++)
#pragma unroll
            for (int q=0;q<4;q++) acc[a][f][q]=0.f;

    for (int chunk=0; chunk<4; chunk++){
        if (chunk>0) __syncthreads();
        for (int idx=tid; idx<3840; idx+=512){
            int row = idx/60, c4 = idx-row*60;
            float4 v = *(const float4*)&Z[(size_t)(nb0+row)*7680 + kz*960 + chunk*240 + c4*4];
            __nv_bfloat16 h0=__float2bfloat16(v.x), h1=__float2bfloat16(v.y);
            __nv_bfloat16 h2=__float2bfloat16(v.z), h3=__float2bfloat16(v.w);
            __nv_bfloat16* ph = sH + row*240 + c4*4;
            __nv_bfloat16* pl = sL + row*240 + c4*4;
            ph[0]=h0; ph[1]=h1; ph[2]=h2; ph[3]=h3;
            pl[0]=__float2bfloat16(v.x-__bfloat162float(h0));
            pl[1]=__float2bfloat16(v.y-__bfloat162float(h1));
            pl[2]=__float2bfloat16(v.z-__bfloat162float(h2));
            pl[3]=__float2bfloat16(v.w-__bfloat162float(h3));
        }
        __syncthreads();

        int abase = ((kz*60 + chunk*15)*32 + mtile0)*32 + lane;
        uint4 ah0=FH[abase], ah1=FH[abase+32], al0=FL[abase], al1=FL[abase+32];
        const int sb0 = (nhalf*32 + g)*240 + tc*4;
        for (int ch=0; ch<15; ch++){
            uint2 BH[4], BL[4];
#pragma unroll
            for (int f=0;f<4;f++){
                BH[f]=*(const uint2*)(sH + sb0 + f*(8*240) + ch*16);
                BL[f]=*(const uint2*)(sL + sb0 + f*(8*240) + ch*16);
            }
            int nbase = abase + ((ch<14)? 1024 : 0);
            uint4 nh0=FH[nbase], nh1=FH[nbase+32], nl0=FL[nbase], nl1=FL[nbase+32];
#pragma unroll
            for (int f=0;f<4;f++){
                mma16816(acc[0][f], ah0, BH[f].x,BH[f].y);
                mma16816(acc[1][f], ah1, BH[f].x,BH[f].y);
            }
#pragma unroll
            for (int f=0;f<4;f++){
                mma16816(acc[0][f], al0, BH[f].x,BH[f].y);
                mma16816(acc[1][f], al1, BH[f].x,BH[f].y);
            }
#pragma unroll
            for (int f=0;f<4;f++){
                mma16816(acc[0][f], ah0, BL[f].x,BL[f].y);
                mma16816(acc[1][f], ah1, BL[f].x,BL[f].y);
            }
            abase=nbase; ah0=nh0; ah1=nh1; al0=nl0; al1=nl1;
        }
    }

    // epilogue: scatter partials to g_p1[kz][batch][cout]
    float* dst = &g_p1[(size_t)kz*1024*512];
#pragma unroll
    for (int mt=0; mt<2; mt++){
        const int co = cb0 + (mtp*2+mt)*16 + g;
#pragma unroll
        for (int f=0; f<4; f++){
            const int bc = nb0 + nhalf*32 + f*8 + tc*2;
            dst[(size_t)bc*512 + co]       = acc[mt][f][0];
            dst[(size_t)(bc+1)*512 + co]   = acc[mt][f][1];
            dst[(size_t)bc*512 + co + 8]   = acc[mt][f][2];
            dst[(size_t)(bc+1)*512 + co+8] = acc[mt][f][3];
        }
    }
}

__global__ void fc1red_kernel(const float* __restrict__ bias)
{
    int i=blockIdx.x*blockDim.x+threadIdx.x;
    float s=0.f;
#pragma unroll
    for (int k=0;k<SKF;k++) s+=g_p1[(size_t)k*524288 + i];
    s+=bias[i&511];
    g_z1[i]=fmaxf(s,0.f);
}

__global__ void __launch_bounds__(256) gemm_kernel(const float* __restrict__ A,
                                                   const float* __restrict__ W,
                                                   const float* __restrict__ bias,
                                                   float* __restrict__ C,
                                                   int M, int N, int K, int relu)
{
    __shared__ float sA[64][17];
    __shared__ float sW[64][17];
    const int tid=threadIdx.x;
    const int m0=blockIdx.y*64, n0=blockIdx.x*64;
    const int tr=(tid/16)*4, tc=(tid%16)*4;
    float acc[4][4];
#pragma unroll
    for (int i=0;i<4;i++)
#pragma unroll
        for (int j=0;j<4;j++) acc[i][j]=0.f;
    for (int k0=0;k0<K;k0+=16){
        for (int i=tid;i<1024;i+=256){
            int k=i&15, r=i>>4;
            int gm=m0+r, gk=k0+k;
            sA[r][k]=(gm<M && gk<K)? A[gm*K+gk] : 0.f;
            int gn=n0+r;
            sW[r][k]=(gn<N && gk<K)? W[gn*K+gk] : 0.f;
        }
        __syncthreads();
#pragma unroll
        for (int k=0;k<16;k++){
            float a[4], w[4];
#pragma unroll
            for (int i=0;i<4;i++) a[i]=sA[tr+i][k];
#pragma unroll
            for (int j=0;j<4;j++) w[j]=sW[tc+j][k];
#pragma unroll
            for (int i=0;i<4;i++)
#pragma unroll
                for (int j=0;j<4;j++) acc[i][j]=fmaf(a[i],w[j],acc[i][j]);
        }
        __syncthreads();
    }
#pragma unroll
    for (int i=0;i<4;i++){
        int gm=m0+tr+i;
        if (gm>=M) continue;
#pragma unroll
        for (int j=0;j<4;j++){
            int gn=n0+tc+j;
            if (gn>=N) continue;
            float v=acc[i][j]+bias[gn];
            if (relu) v=fmaxf(v,0.f);
            C[gm*N+gn]=v;
        }
    }
}

__global__ void ei_kernel(const int* __restrict__ eidx, float* __restrict__ out)
{
    int e=blockIdx.x*blockDim.x+threadIdx.x;
    if (e>=ET) return;
    int s,d;
    if (e<NE){ s=eidx[e]; d=eidx[NE+e]; }
    else { s=e-NE; d=e-NE; }
    out[EI_OFF+e]    =(float)s;
    out[EI_OFF+ET+e] =(float)d;
}

extern "C" void kernel_launch(void* const* d_in, const int* in_sizes, int n_in,
                              void* d_out, int out_size)
{
    const float* x      =(const float*)d_in[0];
    const float* gat_Wl =(const float*)d_in[1];
    const float* gat_bl =(const float*)d_in[2];
    const float* gat_Wr =(const float*)d_in[3];
    const float* gat_br =(const float*)d_in[4];
    const float* gat_att=(const float*)d_in[5];
    const float* gat_bias=(const float*)d_in[6];
    const float* tcn0_w =(const float*)d_in[7];
    const float* ln0_w  =(const float*)d_in[9];
    const float* ln0_b  =(const float*)d_in[10];
    const float* tcn1_w =(const float*)d_in[11];
    const float* ln1_w  =(const float*)d_in[13];
    const float* ln1_b  =(const float*)d_in[14];
    const float* ds1_w  =(const float*)d_in[15];
    const float* ds1_b  =(const float*)d_in[16];
    const float* tcn2_w =(const float*)d_in[17];
    const float* ln2_w  =(const float*)d_in[19];
    const float* ln2_b  =(const float*)d_in[20];
    const float* ds2_w  =(const float*)d_in[21];
    const float* ds2_b  =(const float*)d_in[22];
    const float* fc1_w  =(const float*)d_in[23];
    const float* fc1_b  =(const float*)d_in[24];
    const float* fc2_w  =(const float*)d_in[25];
    const float* fc2_b  =(const float*)d_in[26];
    const float* fc3_w  =(const float*)d_in[27];
    const float* fc3_b  =(const float*)d_in[28];
    const int*   edge   =(const int*)d_in[29];
    float* out=(float*)d_out;

    cudaFuncSetAttribute(attn_kernel, cudaFuncAttributeMaxDynamicSharedMemorySize, ATTN_SMEM_BYTES);
    cudaFuncSetAttribute(conv_mma<0>, cudaFuncAttributeMaxDynamicSharedMemorySize, CONV_SMEM);
    cudaFuncSetAttribute(conv_mma<1>, cudaFuncAttributeMaxDynamicSharedMemorySize, CONV_SMEM);
    cudaFuncSetAttribute(conv_mma<2>, cudaFuncAttributeMaxDynamicSharedMemorySize, CONV_SMEM);
    cudaFuncSetAttribute(fc1_mma,     cudaFuncAttributeMaxDynamicSharedMemorySize, FC1_SMEM);

    prep_kernel<<<1024,256>>>(gat_Wl, gat_Wr, tcn0_w, tcn1_w, tcn2_w, ds1_w, ds2_w, fc1_w);
    xform_kernel<<<NL/32,256>>>(x, gat_bl, gat_br);

    int write_alpha = (out_size >= ALPHA_OFF + ALPHA_LEN) ? 1 : 0;
    attn_kernel<<<NB,256,ATTN_SMEM_BYTES>>>(edge, gat_att, gat_bias, out, write_alpha);

    void *ph=nullptr,*py0=nullptr,*py1=nullptr,*pz=nullptr,*pz1=nullptr,*pz2=nullptr;
    void *a0h,*a0l,*a1h,*a1l,*a2h,*a2l,*d1h,*d1l,*d2h,*d2l,*fh,*fl;
    cudaGetSymbolAddress(&ph,  g_h);  cudaGetSymbolAddress(&py0, g_y0);
    cudaGetSymbolAddress(&py1, g_y1); cudaGetSymbolAddress(&pz,  g_z);
    cudaGetSymbolAddress(&pz1, g_z1); cudaGetSymbolAddress(&pz2, g_z2);
    cudaGetSymbolAddress(&a0h, g_A0H); cudaGetSymbolAddress(&a0l, g_A0L);
    cudaGetSymbolAddress(&a1h, g_A1H); cudaGetSymbolAddress(&a1l, g_A1L);
    cudaGetSymbolAddress(&a2h, g_A2H); cudaGetSymbolAddress(&a2l, g_A2L);
    cudaGetSymbolAddress(&d1h, g_D1H); cudaGetSymbolAddress(&d1l, g_D1L);
    cudaGetSymbolAddress(&d2h, g_D2H); cudaGetSymbolAddress(&d2l, g_D2L);
    cudaGetSymbolAddress(&fh,  g_FH); cudaGetSymbolAddress(&fl,  g_FL);

    conv_mma<0><<<NB/2,512,CONV_SMEM>>>((const float*)ph,
        (const uint4*)a0h,(const uint4*)a0l,(const uint4*)a0h,(const uint4*)a0l,
        nullptr, ln0_w, ln0_b, (float*)py0);
    conv_mma<1><<<NB/2,512,CONV_SMEM>>>((const float*)py0,
        (const uint4*)a1h,(const uint4*)a1l,(const uint4*)d1h,(const uint4*)d1l,
        ds1_b, ln1_w, ln1_b, (float*)py1);
    conv_mma<2><<<NB/2,512,CONV_SMEM>>>((const float*)py1,
        (const uint4*)a2h,(const uint4*)a2l,(const uint4*)d2h,(const uint4*)d2l,
        ds2_b, ln2_w, ln2_b, (float*)pz);

    fc1_mma<<<dim3(16,2,SKF),512,FC1_SMEM>>>((const float*)pz, (const uint4*)fh, (const uint4*)fl);
    fc1red_kernel<<<(1024*512)/256,256>>>(fc1_b);

    gemm_kernel<<<dim3(256/64, NB/64),256>>>((const float*)pz1, fc2_w, fc2_b, (float*)pz2, NB, 256, 512, 1);
    gemm_kernel<<<dim3((144+63)/64, NB/64),256>>>((const float*)pz2, fc3_w, fc3_b, out, NB, 144, 256, 0);

    if (out_size >= EI_OFF + EI_LEN)
        ei_kernel<<<(ET+255)/256,256>>>(edge, out);
}

// round 13
// speedup vs baseline: 1.3184x; 1.0189x over previous
#include <cuda_runtime.h>
#include <cuda_bf16.h>
#include <cstdint>

#define NN   30
#define HH   4
#define CC   64
#define HC   256
#define FIN  64
#define NB   1024
#define EPG  240
#define NE   (NB*EPG)
#define NL   (NB*NN)
#define ET   (NE+NL)
#define EG   (EPG+NN)
#define OUT_LEN   (NB*144)
#define ALPHA_OFF OUT_LEN
#define ALPHA_LEN (ET*HH)
#define EI_OFF    (ALPHA_OFF+ALPHA_LEN)
#define EI_LEN    (2*ET)
#define LN_EPS 1e-5f
#define NSLOPE 0.2f
#define RS 40

typedef unsigned long long u64;

__device__ __forceinline__ void mma16816(float c[4], uint4 a, uint32_t b0, uint32_t b1){
    asm volatile("mma.sync.aligned.m16n8k16.row.col.f32.bf16.bf16.f32 "
        "{%0,%1,%2,%3},{%4,%5,%6,%7},{%8,%9},{%0,%1,%2,%3};"
        : "+f"(c[0]),"+f"(c[1]),"+f"(c[2]),"+f"(c[3])
        : "r"(a.x),"r"(a.y),"r"(a.z),"r"(a.w),"r"(b0),"r"(b1));
}

// ---------------- device scratch ----------------
__device__ float g_WlT[FIN*HC];
__device__ float g_WrT[FIN*HC];
__device__ float g_xl[NL*HC];
__device__ float g_xr[NL*HC];
__device__ float g_h [(size_t)NB*HC*RS];
__device__ float g_y0[(size_t)NB*256*RS];
__device__ float g_y1[(size_t)NB*512*RS];
__device__ float g_z [NB*HC*NN];
__device__ float g_z1[NB*512];
__device__ float g_z2[NB*256];
#define SKF 8
__device__ float g_p1[SKF*1024*512];

// A-fragment-packed weights (uint4 per lane per fragment), k-permuted for LDS.64 B loads
__device__ uint4 g_A0H[24576], g_A0L[24576];
__device__ uint4 g_A1H[49152], g_A1L[49152];
__device__ uint4 g_D1H[16384], g_D1L[16384];
__device__ uint4 g_A2H[49152], g_A2L[49152];
__device__ uint4 g_D2H[16384], g_D2L[16384];
__device__ uint4 g_FH[491520], g_FL[491520];   // fc1: 480 ksteps * 32 mtiles * 32 lanes

__device__ __forceinline__ uint32_t packbf(float v0, float v1, int lo){
    __nv_bfloat16 h0=__float2bfloat16(v0), h1=__float2bfloat16(v1);
    if (lo){ h0=__float2bfloat16(v0-__bfloat162float(h0)); h1=__float2bfloat16(v1-__bfloat162float(h1)); }
    return (uint32_t)__bfloat16_as_ushort(h0) | ((uint32_t)__bfloat16_as_ushort(h1)<<16);
}

__device__ void fill_convA(uint32_t* H, uint32_t* L, const float* w, int Cin, int MT, int nslots,
                           int t0, int stride)
{
    for (int i=t0;i<nslots;i+=stride){
        int q=i&3, lane=(i>>2)&31, mtg=(i>>7)%MT, kstep=i/(MT*128);
        int g=lane>>2, tc=lane&3;
        int m=mtg*16 + g + (q&1)*8;
        int kk=kstep*16 + tc*4 + (q>>1)*2;
        int t=kk/Cin, cin=kk-t*Cin;
        float v0=w[(m*Cin+cin)*3+t], v1=w[(m*Cin+cin+1)*3+t];
        H[i]=packbf(v0,v1,0); L[i]=packbf(v0,v1,1);
    }
}
__device__ void fill_dsA(uint32_t* H, uint32_t* L, const float* w, int Cin, int MT, int nslots,
                         int t0, int stride)
{
    for (int i=t0;i<nslots;i+=stride){
        int q=i&3, lane=(i>>2)&31, mtg=(i>>7)%MT, kstep=i/(MT*128);
        int g=lane>>2, tc=lane&3;
        int m=mtg*16 + g + (q&1)*8;
        int cin=kstep*16 + tc*4 + (q>>1)*2;
        float v0=w[m*Cin+cin], v1=w[m*Cin+cin+1];
        H[i]=packbf(v0,v1,0); L[i]=packbf(v0,v1,1);
    }
}

__global__ void prep_kernel(const float* __restrict__ Wl, const float* __restrict__ Wr,
                            const float* __restrict__ w0, const float* __restrict__ w1,
                            const float* __restrict__ w2, const float* __restrict__ d1,
                            const float* __restrict__ d2, const float* __restrict__ f1)
{
    int t0 = blockIdx.x*blockDim.x + threadIdx.x;
    int stride = gridDim.x*blockDim.x;
    for (int i=t0;i<FIN*HC;i+=stride){ int j=i%HC,k=i/HC; g_WlT[i]=Wl[j*FIN+k]; g_WrT[i]=Wr[j*FIN+k]; }
    fill_convA((uint32_t*)g_A0H,(uint32_t*)g_A0L, w0, 256, 16,  98304, t0, stride);
    fill_convA((uint32_t*)g_A1H,(uint32_t*)g_A1L, w1, 256, 32, 196608, t0, stride);
    fill_convA((uint32_t*)g_A2H,(uint32_t*)g_A2L, w2, 512, 16, 196608, t0, stride);
    fill_dsA  ((uint32_t*)g_D1H,(uint32_t*)g_D1L, d1, 256, 32,  65536, t0, stride);
    fill_dsA  ((uint32_t*)g_D2H,(uint32_t*)g_D2L, d2, 512, 16,  65536, t0, stride);
    fill_dsA  ((uint32_t*)g_FH, (uint32_t*)g_FL,  f1, 7680, 32, 1966080, t0, stride);
}

__global__ void __launch_bounds__(256) xform_kernel(const float* __restrict__ x,
                                                    const float* __restrict__ bl,
                                                    const float* __restrict__ br)
{
    __shared__ float xs[32*FIN];
    const int base = blockIdx.x*32;
    const int tid = threadIdx.x;
    for (int i=tid;i<32*FIN;i+=256) xs[i]=x[base*FIN+i];
    __syncthreads();
    float accl[32], accr[32];
#pragma unroll
    for (int n=0;n<32;n++){ accl[n]=0.f; accr[n]=0.f; }
    const int j = tid;
    for (int k=0;k<FIN;k++){
        float wl=g_WlT[k*HC+j], wr=g_WrT[k*HC+j];
#pragma unroll
        for (int n=0;n<32;n++){ float xv=xs[n*FIN+k]; accl[n]=fmaf(wl,xv,accl[n]); accr[n]=fmaf(wr,xv,accr[n]); }
    }
    float blv=bl[j], brv=br[j];
#pragma unroll
    for (int n=0;n<32;n++){
        g_xl[(base+n)*HC+j]=accl[n]+blv;
        g_xr[(base+n)*HC+j]=accr[n]+brv;
    }
}

#define ATTN_SMEM_BYTES (18272*4 + 901*4 + 16)
__global__ void __launch_bounds__(256) attn_kernel(const int* __restrict__ eidx,
                                                   const float* __restrict__ att,
                                                   const float* __restrict__ gbias,
                                                   float* __restrict__ out,
                                                   int write_alpha)
{
    extern __shared__ char smemraw[];
    float* xl_s   = (float*)smemraw;
    float* xr_s   = xl_s + 7680;
    float* att_s  = xr_s + 7680;
    float* bias_s = att_s + 256;
    float* esc    = bias_s + 256;
    float* alp    = esc + 1080;
    float* mmax   = alp + 1080;
    float* ssum   = mmax + 120;
    int*   srcl   = (int*)(ssum + 120);
    int*   dstl   = srcl + 270;
    int*   deg    = dstl + 270;
    int*   off    = deg + 30;
    int*   pos    = off + 31;
    int*   order  = pos + 30;
    const int b = blockIdx.x, tid = threadIdx.x;
    const int lane = tid&31, wrp = tid>>5;

    for (int i=tid;i<7680;i+=256){ xl_s[i]=g_xl[b*7680+i]; xr_s[i]=g_xr[b*7680+i]; }
    for (int i=tid;i<256;i+=256){ att_s[i]=att[i]; bias_s[i]=gbias[i]; }
    if (tid<30) deg[tid]=0;
    __syncthreads();
    for (int e=tid;e<EG;e+=256){
        int s,d;
        if (e<EPG){ s=eidx[b*EPG+e]-b*NN; d=eidx[NE+b*EPG+e]-b*NN; }
        else      { s=e-EPG; d=e-EPG; }
        srcl[e]=s; dstl[e]=d;
        atomicAdd(&deg[d],1);
    }
    __syncthreads();
    if (tid==0){ off[0]=0; for (int n=0;n<NN;n++) off[n+1]=off[n]+deg[n]; }
    __syncthreads();
    if (tid<30) pos[tid]=off[tid];
    __syncthreads();
    for (int e=tid;e<EG;e+=256){ int slot=atomicAdd(&pos[dstl[e]],1); order[slot]=e; }
    __syncthreads();

    for (int p=wrp; p<EG*HH; p+=8){
        int e=p>>2, h=p&3;
        const float* ps=&xl_s[srcl[e]*HC + h*CC];
        const float* pd=&xr_s[dstl[e]*HC + h*CC];
        const float* pa=&att_s[h*CC];
        float acc=0.f;
#pragma unroll
        for (int cc=0; cc<2; cc++){
            int c = lane + cc*32;
            float v = ps[c]+pd[c];
            v = v>0.f ? v : NSLOPE*v;
            acc = fmaf(v, pa[c], acc);
        }
        acc += __shfl_xor_sync(0xffffffffu, acc, 16);
        acc += __shfl_xor_sync(0xffffffffu, acc, 8);
        acc += __shfl_xor_sync(0xffffffffu, acc, 4);
        acc += __shfl_xor_sync(0xffffffffu, acc, 2);
        acc += __shfl_xor_sync(0xffffffffu, acc, 1);
        if (lane==0) esc[p]=acc;
    }
    __syncthreads();

    for (int idx=tid; idx<NN*HH; idx+=256){
        int n=idx>>2, h=idx&3;
        float m=-1e30f;
        for (int i=off[n];i<off[n+1];i++) m=fmaxf(m, esc[order[i]*HH+h]);
        float s=0.f;
        for (int i=off[n];i<off[n+1];i++) s+=__expf(esc[order[i]*HH+h]-m);
        mmax[idx]=m; ssum[idx]=s;
    }
    __syncthreads();
    for (int idx=tid; idx<EG*HH; idx+=256){
        int e=idx>>2, h=idx&3;
        int d=dstl[e];
        float a=__expf(esc[idx]-mmax[d*HH+h])/ssum[d*HH+h];
        alp[idx]=a;
        if (write_alpha){
            int gid = (e<EPG) ? (b*EPG+e) : (NE + b*NN + (e-EPG));
            out[ALPHA_OFF + gid*HH + h]=a;
        }
    }
    __syncthreads();
    {
        const int j = tid;
        const int h = j>>6;
        for (int n=0;n<NN;n++){
            float acc=0.f;
            for (int i=off[n];i<off[n+1];i++){
                int e=order[i];
                acc = fmaf(alp[e*HH+h], xl_s[srcl[e]*HC+j], acc);
            }
            float v=acc+bias_s[j];
            xr_s[j*NN+n]=fmaxf(v,0.f);
        }
    }
    __syncthreads();
    for (int i=tid;i<256*RS;i+=256){
        int c=i/RS, col=i-c*RS;
        float v = (col>=4 && col<34) ? xr_s[c*NN + col-4] : 0.f;
        g_h[(size_t)b*256*RS + i]=v;
    }
}

// ================= mma.sync TCN conv layer =================
#define CS 272
#define CONV_SMEM (2*2*40*CS*2)   // 87040B

template<int MODE>
__global__ void __launch_bounds__(512,1) conv_mma(
    const float* __restrict__ in,
    const uint4* __restrict__ AH, const uint4* __restrict__ AL,
    const uint4* __restrict__ DH, const uint4* __restrict__ DL,
    const float* __restrict__ db,
    const float* __restrict__ lnw, const float* __restrict__ lnb,
    float* __restrict__ outp)
{
    constexpr int Cin   = (MODE==2)?512:256;
    constexpr int COUT  = (MODE==1)?512:256;
    constexpr int MT    = (MODE==1)?32:16;
    constexpr int PH    = (MODE==2)?2:1;
    constexpr int DIL   = (MODE==0)?1:((MODE==1)?2:4);
    constexpr bool HASDS= (MODE>=1);
    constexpr int KS_T  = Cin/16;
    constexpr bool SPLITC = (MODE==0);

    extern __shared__ __nv_bfloat16 sm_bf[];
    __nv_bfloat16* sH = sm_bf;
    __nv_bfloat16* sL = sm_bf + 2*40*CS;
    __shared__ float s_lnw[32], s_lnb[32];

    const int tid=threadIdx.x, lane=tid&31, wid=tid>>5;
    const int g=lane>>2, tc=lane&3;
    const int b0=blockIdx.x*2;
    const int mp=blockIdx.y;          // M-split (MODE1: 0/1; others: 0)
    const int nhalf = wid&1;
    const int mtp   = wid>>1;

    if (tid<30){ s_lnw[tid]=lnw[tid]; s_lnb[tid]=lnb[tid]; }

    float acc[2][4][4];
    float acl[SPLITC?2:1][SPLITC?4:1][SPLITC?4:1];
    float dsacc[HASDS?2:1][HASDS?4:1][HASDS?4:1];
#pragma unroll
    for (int a=0;a<2;a++)
#pragma unroll
        for (int f=0;f<4;f++)
#pragma unroll
            for (int q=0;q<4;q++) acc[a][f][q]=0.f;
    if constexpr(SPLITC){
#pragma unroll
        for (int a=0;a<2;a++)
#pragma unroll
            for (int f=0;f<4;f++)
#pragma unroll
                for (int q=0;q<4;q++) acl[a][f][q]=0.f;
    }
    if constexpr(HASDS){
#pragma unroll
        for (int a=0;a<2;a++)
#pragma unroll
            for (int f=0;f<4;f++)
#pragma unroll
                for (int q=0;q<4;q++) dsacc[a][f][q]=0.f;
    }

    for (int ph=0; ph<PH; ph++){
        if (ph>0) __syncthreads();
        for (int idx=tid; idx<2*256*RS; idx+=512){
            int gr = idx/(256*RS);
            int r  = idx - gr*256*RS;
            int c  = r/RS;
            int l  = r - c*RS;
            float v = in[(((size_t)(b0+gr))*Cin + ph*256 + c)*RS + l];
            __nv_bfloat16 h=__float2bfloat16(v);
            int sidx=(gr*40+l)*CS+c;
            sH[sidx]=h;
            sL[sidx]=__float2bfloat16(v-__bfloat162float(h));
        }
        __syncthreads();

        const int mtile0 = mp*16 + mtp*2;
        const int sb0 = (nhalf*40 + 4 + g)*CS + tc*4;

        if constexpr(MODE==0){
            int abase = mtile0*32 + lane;
            uint4 ah0=AH[abase], ah1=AH[abase+32], al0=AL[abase], al1=AL[abase+32];
#pragma unroll
            for (int t=0;t<3;t++){
                const int srow = sb0 + DIL*(t-1)*CS;
                for (int ch=0; ch<16; ch++){
                    uint2 BH[4], BL[4];
#pragma unroll
                    for (int f=0;f<4;f++){
                        BH[f]=*(const uint2*)(sH + srow + f*(8*CS) + ch*16);
                        BL[f]=*(const uint2*)(sL + srow + f*(8*CS) + ch*16);
                    }
                    int nbase = abase + (((t*16+ch)<47)? MT*32 : 0);
                    uint4 nh0=AH[nbase], nh1=AH[nbase+32], nl0=AL[nbase], nl1=AL[nbase+32];
                    // w1 -> acc, w2 -> acl, w3 -> acc (chain distance >= 16)
#pragma unroll
                    for (int f=0;f<4;f++){
                        mma16816(acc[0][f], ah0, BH[f].x,BH[f].y);
                        mma16816(acc[1][f], ah1, BH[f].x,BH[f].y);
                    }
#pragma unroll
                    for (int f=0;f<4;f++){
                        mma16816(acl[0][f], al0, BH[f].x,BH[f].y);
                        mma16816(acl[1][f], al1, BH[f].x,BH[f].y);
                    }
#pragma unroll
                    for (int f=0;f<4;f++){
                        mma16816(acc[0][f], ah0, BL[f].x,BL[f].y);
                        mma16816(acc[1][f], ah1, BL[f].x,BL[f].y);
                    }
                    abase=nbase; ah0=nh0; ah1=nh1; al0=nl0; al1=nl1;
                }
            }
        } else {
#pragma unroll
        for (int t=0;t<3;t++){
            int abase = ((t*KS_T + ph*16)*MT + mtile0)*32 + lane;
            const int srow = sb0 + DIL*(t-1)*CS;
            if (HASDS && t==1){
                int dbase = ((ph*16)*MT + mtile0)*32 + lane;
                for (int ch=0; ch<16; ch++){
                    uint4 ah0=AH[abase], ah1=AH[abase+32], al0=AL[abase], al1=AL[abase+32];
                    uint4 dh0=DH[dbase], dh1=DH[dbase+32], dl0=DL[dbase], dl1=DL[dbase+32];
                    uint2 BH[4], BL[4];
#pragma unroll
                    for (int f=0;f<4;f++){
                        BH[f]=*(const uint2*)(sH + srow + f*(8*CS) + ch*16);
                        BL[f]=*(const uint2*)(sL + srow + f*(8*CS) + ch*16);
                    }
                    // interleave conv/ds waves: chain distance 16
#pragma unroll
                    for (int f=0;f<4;f++){
                        mma16816(acc[0][f], ah0, BH[f].x,BH[f].y);
                        mma16816(acc[1][f], ah1, BH[f].x,BH[f].y);
                    }
#pragma unroll
                    for (int f=0;f<4;f++){
                        mma16816(dsacc[0][f], dh0, BH[f].x,BH[f].y);
                        mma16816(dsacc[1][f], dh1, BH[f].x,BH[f].y);
                    }
#pragma unroll
                    for (int f=0;f<4;f++){
                        mma16816(acc[0][f], al0, BH[f].x,BH[f].y);
                        mma16816(acc[1][f], al1, BH[f].x,BH[f].y);
                    }
#pragma unroll
                    for (int f=0;f<4;f++){
                        mma16816(dsacc[0][f], dl0, BH[f].x,BH[f].y);
                        mma16816(dsacc[1][f], dl1, BH[f].x,BH[f].y);
                    }
#pragma unroll
                    for (int f=0;f<4;f++){
                        mma16816(acc[0][f], ah0, BL[f].x,BL[f].y);
                        mma16816(acc[1][f], ah1, BL[f].x,BL[f].y);
                    }
#pragma unroll
                    for (int f=0;f<4;f++){
                        mma16816(dsacc[0][f], dh0, BL[f].x,BL[f].y);
                        mma16816(dsacc[1][f], dh1, BL[f].x,BL[f].y);
                    }
                    abase += MT*32; dbase += MT*32;
                }
            } else {
                uint4 ah0=AH[abase], ah1=AH[abase+32], al0=AL[abase], al1=AL[abase+32];
                for (int ch=0; ch<16; ch++){
                    uint2 BH[4], BL[4];
#pragma unroll
                    for (int f=0;f<4;f++){
                        BH[f]=*(const uint2*)(sH + srow + f*(8*CS) + ch*16);
                        BL[f]=*(const uint2*)(sL + srow + f*(8*CS) + ch*16);
                    }
                    int nbase = abase + ((ch<15)? MT*32 : 0);
                    uint4 nh0=AH[nbase], nh1=AH[nbase+32], nl0=AL[nbase], nl1=AL[nbase+32];
#pragma unroll
                    for (int f=0;f<4;f++){
                        mma16816(acc[0][f], ah0, BH[f].x,BH[f].y);
                        mma16816(acc[1][f], ah1, BH[f].x,BH[f].y);
                    }
#pragma unroll
                    for (int f=0;f<4;f++){
                        mma16816(acc[0][f], al0, BH[f].x,BH[f].y);
                        mma16816(acc[1][f], al1, BH[f].x,BH[f].y);
                    }
#pragma unroll
                    for (int f=0;f<4;f++){
                        mma16816(acc[0][f], ah0, BL[f].x,BL[f].y);
                        mma16816(acc[1][f], ah1, BL[f].x,BL[f].y);
                    }
                    abase=nbase; ah0=nh0; ah1=nh1; al0=nl0; al1=nl1;
                }
            }
        }
        }
    }

    // ---- epilogue ----
    if constexpr(SPLITC){
#pragma unroll
        for (int a=0;a<2;a++)
#pragma unroll
            for (int f=0;f<4;f++)
#pragma unroll
                for (int q=0;q<4;q++) acc[a][f][q]+=acl[a][f][q];
    }
    const int gr = nhalf;
#pragma unroll
    for (int mt=0; mt<2; mt++){
        const int mrow0 = mp*256 + (mtp*2+mt)*16 + g;
#pragma unroll
        for (int half=0; half<2; half++){
            const int mrow = mrow0 + half*8;
            float dbv = 0.f;
            if constexpr(HASDS) dbv = __ldg(&db[mrow]);
            float s=0.f;
#pragma unroll
            for (int f=0; f<4; f++)
#pragma unroll
                for (int i=0;i<2;i++){
                    int l=f*8+tc*2+i;
                    if (l<30) s+=acc[mt][f][half*2+i];
                }
            s += __shfl_xor_sync(0xffffffffu,s,1);
            s += __shfl_xor_sync(0xffffffffu,s,2);
            float mean = s*(1.f/30.f);
            float qv=0.f;
#pragma unroll
            for (int f=0; f<4; f++)
#pragma unroll
                for (int i=0;i<2;i++){
                    int l=f*8+tc*2+i;
                    if (l<30){ float d=acc[mt][f][half*2+i]-mean; qv=fmaf(d,d,qv); }
                }
            qv += __shfl_xor_sync(0xffffffffu,qv,1);
            qv += __shfl_xor_sync(0xffffffffu,qv,2);
            float rsn = rsqrtf(qv*(1.f/30.f)+LN_EPS);

            size_t rb;
            if constexpr(MODE==2) rb = (((size_t)(b0+gr))*256 + mrow)*(size_t)NN;
            else                  rb = (((size_t)(b0+gr))*COUT + mrow)*(size_t)RS;
#pragma unroll
            for (int f=0; f<4; f++){
                int l0=f*8+tc*2;
                if (l0>=30) continue;
                float o0,o1;
                {
                    float v=(acc[mt][f][half*2+0]-mean)*rsn*s_lnw[l0]+s_lnb[l0];
                    o0=fmaxf(v,0.f);
                    v=(acc[mt][f][half*2+1]-mean)*rsn*s_lnw[l0+1]+s_lnb[l0+1];
                    o1=fmaxf(v,0.f);
                }
                if constexpr(MODE==0){
                    float2 res=*(const float2*)&in[(((size_t)(b0+gr))*256 + mrow)*RS + 4 + l0];
                    o0+=res.x; o1+=res.y;
                } else {
                    o0 += dsacc[mt][f][half*2+0] + dbv;
                    o1 += dsacc[mt][f][half*2+1] + dbv;
                }
                if constexpr(MODE==2) *(float2*)&outp[rb+l0]   = make_float2(o0,o1);
                else                  *(float2*)&outp[rb+4+l0] = make_float2(o0,o1);
            }
            if constexpr(MODE!=2){
                if (tc==0) *(float4*)&outp[rb] = make_float4(0.f,0.f,0.f,0.f);
                if (tc==3){
                    *(float2*)&outp[rb+34]=make_float2(0.f,0.f);
                    *(float4*)&outp[rb+36]=make_float4(0.f,0.f,0.f,0.f);
                }
            }
        }
    }
}

// ================= fc1: bf16 hi/lo mma GEMM, split-K=8 =================
#define FC1_SMEM (2*64*240*2)   // 61440B
__global__ void __launch_bounds__(512,1) fc1_mma(
    const float* __restrict__ Z,
    const uint4* __restrict__ FH, const uint4* __restrict__ FL)
{
    extern __shared__ __nv_bfloat16 sm[];
    __nv_bfloat16* sH = sm;
    __nv_bfloat16* sL = sm + 64*240;
    const int tid=threadIdx.x, lane=tid&31, wid=tid>>5;
    const int g=lane>>2, tc=lane&3;
    const int nb0 = blockIdx.x*64;
    const int cb0 = blockIdx.y*256;
    const int kz  = blockIdx.z;
    const int nhalf = wid&1, mtp = wid>>1;
    const int mtile0 = (cb0>>4) + mtp*2;

    float acc[2][4][4];
#pragma unroll
    for (int a=0;a<2;a++)
#pragma unroll
        for (int f=0;f<4;f++)
#pragma unroll
            for (int q=0;q<4;q++) acc[a][f][q]=0.f;

    for (int chunk=0; chunk<4; chunk++){
        if (chunk>0) __syncthreads();
        for (int idx=tid; idx<3840; idx+=512){
            int row = idx/60, c4 = idx-row*60;
            float4 v = *(const float4*)&Z[(size_t)(nb0+row)*7680 + kz*960 + chunk*240 + c4*4];
            __nv_bfloat16 h0=__float2bfloat16(v.x), h1=__float2bfloat16(v.y);
            __nv_bfloat16 h2=__float2bfloat16(v.z), h3=__float2bfloat16(v.w);
            __nv_bfloat16* ph = sH + row*240 + c4*4;
            __nv_bfloat16* pl = sL + row*240 + c4*4;
            ph[0]=h0; ph[1]=h1; ph[2]=h2; ph[3]=h3;
            pl[0]=__float2bfloat16(v.x-__bfloat162float(h0));
            pl[1]=__float2bfloat16(v.y-__bfloat162float(h1));
            pl[2]=__float2bfloat16(v.z-__bfloat162float(h2));
            pl[3]=__float2bfloat16(v.w-__bfloat162float(h3));
        }
        __syncthreads();

        int abase = ((kz*60 + chunk*15)*32 + mtile0)*32 + lane;
        uint4 ah0=FH[abase], ah1=FH[abase+32], al0=FL[abase], al1=FL[abase+32];
        const int sb0 = (nhalf*32 + g)*240 + tc*4;
        for (int ch=0; ch<15; ch++){
            uint2 BH[4], BL[4];
#pragma unroll
            for (int f=0;f<4;f++){
                BH[f]=*(const uint2*)(sH + sb0 + f*(8*240) + ch*16);
                BL[f]=*(const uint2*)(sL + sb0 + f*(8*240) + ch*16);
            }
            int nbase = abase + ((ch<14)? 1024 : 0);
            uint4 nh0=FH[nbase], nh1=FH[nbase+32], nl0=FL[nbase], nl1=FL[nbase+32];
#pragma unroll
            for (int f=0;f<4;f++){
                mma16816(acc[0][f], ah0, BH[f].x,BH[f].y);
                mma16816(acc[1][f], ah1, BH[f].x,BH[f].y);
            }
#pragma unroll
            for (int f=0;f<4;f++){
                mma16816(acc[0][f], al0, BH[f].x,BH[f].y);
                mma16816(acc[1][f], al1, BH[f].x,BH[f].y);
            }
#pragma unroll
            for (int f=0;f<4;f++){
                mma16816(acc[0][f], ah0, BL[f].x,BL[f].y);
                mma16816(acc[1][f], ah1, BL[f].x,BL[f].y);
            }
            abase=nbase; ah0=nh0; ah1=nh1; al0=nl0; al1=nl1;
        }
    }

    float* dst = &g_p1[(size_t)kz*1024*512];
#pragma unroll
    for (int mt=0; mt<2; mt++){
        const int co = cb0 + (mtp*2+mt)*16 + g;
#pragma unroll
        for (int f=0; f<4; f++){
            const int bc = nb0 + nhalf*32 + f*8 + tc*2;
            dst[(size_t)bc*512 + co]       = acc[mt][f][0];
            dst[(size_t)(bc+1)*512 + co]   = acc[mt][f][1];
            dst[(size_t)bc*512 + co + 8]   = acc[mt][f][2];
            dst[(size_t)(bc+1)*512 + co+8] = acc[mt][f][3];
        }
    }
}

__global__ void fc1red_kernel(const float* __restrict__ bias)
{
    int i=blockIdx.x*blockDim.x+threadIdx.x;
    float s=0.f;
#pragma unroll
    for (int k=0;k<SKF;k++) s+=g_p1[(size_t)k*524288 + i];
    s+=bias[i&511];
    g_z1[i]=fmaxf(s,0.f);
}

__global__ void __launch_bounds__(256) gemm_kernel(const float* __restrict__ A,
                                                   const float* __restrict__ W,
                                                   const float* __restrict__ bias,
                                                   float* __restrict__ C,
                                                   int M, int N, int K, int relu)
{
    __shared__ float sA[64][17];
    __shared__ float sW[64][17];
    const int tid=threadIdx.x;
    const int m0=blockIdx.y*64, n0=blockIdx.x*64;
    const int tr=(tid/16)*4, tc=(tid%16)*4;
    float acc[4][4];
#pragma unroll
    for (int i=0;i<4;i++)
#pragma unroll
        for (int j=0;j<4;j++) acc[i][j]=0.f;
    for (int k0=0;k0<K;k0+=16){
        for (int i=tid;i<1024;i+=256){
            int k=i&15, r=i>>4;
            int gm=m0+r, gk=k0+k;
            sA[r][k]=(gm<M && gk<K)? A[gm*K+gk] : 0.f;
            int gn=n0+r;
            sW[r][k]=(gn<N && gk<K)? W[gn*K+gk] : 0.f;
        }
        __syncthreads();
#pragma unroll
        for (int k=0;k<16;k++){
            float a[4], w[4];
#pragma unroll
            for (int i=0;i<4;i++) a[i]=sA[tr+i][k];
#pragma unroll
            for (int j=0;j<4;j++) w[j]=sW[tc+j][k];
#pragma unroll
            for (int i=0;i<4;i++)
#pragma unroll
                for (int j=0;j<4;j++) acc[i][j]=fmaf(a[i],w[j],acc[i][j]);
        }
        __syncthreads();
    }
#pragma unroll
    for (int i=0;i<4;i++){
        int gm=m0+tr+i;
        if (gm>=M) continue;
#pragma unroll
        for (int j=0;j<4;j++){
            int gn=n0+tc+j;
            if (gn>=N) continue;
            float v=acc[i][j]+bias[gn];
            if (relu) v=fmaxf(v,0.f);
            C[gm*N+gn]=v;
        }
    }
}

__global__ void ei_kernel(const int* __restrict__ eidx, float* __restrict__ out)
{
    int e=blockIdx.x*blockDim.x+threadIdx.x;
    if (e>=ET) return;
    int s,d;
    if (e<NE){ s=eidx[e]; d=eidx[NE+e]; }
    else { s=e-NE; d=e-NE; }
    out[EI_OFF+e]    =(float)s;
    out[EI_OFF+ET+e] =(float)d;
}

extern "C" void kernel_launch(void* const* d_in, const int* in_sizes, int n_in,
                              void* d_out, int out_size)
{
    const float* x      =(const float*)d_in[0];
    const float* gat_Wl =(const float*)d_in[1];
    const float* gat_bl =(const float*)d_in[2];
    const float* gat_Wr =(const float*)d_in[3];
    const float* gat_br =(const float*)d_in[4];
    const float* gat_att=(const float*)d_in[5];
    const float* gat_bias=(const float*)d_in[6];
    const float* tcn0_w =(const float*)d_in[7];
    const float* ln0_w  =(const float*)d_in[9];
    const float* ln0_b  =(const float*)d_in[10];
    const float* tcn1_w =(const float*)d_in[11];
    const float* ln1_w  =(const float*)d_in[13];
    const float* ln1_b  =(const float*)d_in[14];
    const float* ds1_w  =(const float*)d_in[15];
    const float* ds1_b  =(const float*)d_in[16];
    const float* tcn2_w =(const float*)d_in[17];
    const float* ln2_w  =(const float*)d_in[19];
    const float* ln2_b  =(const float*)d_in[20];
    const float* ds2_w  =(const float*)d_in[21];
    const float* ds2_b  =(const float*)d_in[22];
    const float* fc1_w  =(const float*)d_in[23];
    const float* fc1_b  =(const float*)d_in[24];
    const float* fc2_w  =(const float*)d_in[25];
    const float* fc2_b  =(const float*)d_in[26];
    const float* fc3_w  =(const float*)d_in[27];
    const float* fc3_b  =(const float*)d_in[28];
    const int*   edge   =(const int*)d_in[29];
    float* out=(float*)d_out;

    cudaFuncSetAttribute(attn_kernel, cudaFuncAttributeMaxDynamicSharedMemorySize, ATTN_SMEM_BYTES);
    cudaFuncSetAttribute(conv_mma<0>, cudaFuncAttributeMaxDynamicSharedMemorySize, CONV_SMEM);
    cudaFuncSetAttribute(conv_mma<1>, cudaFuncAttributeMaxDynamicSharedMemorySize, CONV_SMEM);
    cudaFuncSetAttribute(conv_mma<2>, cudaFuncAttributeMaxDynamicSharedMemorySize, CONV_SMEM);
    cudaFuncSetAttribute(fc1_mma,     cudaFuncAttributeMaxDynamicSharedMemorySize, FC1_SMEM);

    prep_kernel<<<1024,256>>>(gat_Wl, gat_Wr, tcn0_w, tcn1_w, tcn2_w, ds1_w, ds2_w, fc1_w);
    xform_kernel<<<NL/32,256>>>(x, gat_bl, gat_br);

    int write_alpha = (out_size >= ALPHA_OFF + ALPHA_LEN) ? 1 : 0;
    attn_kernel<<<NB,256,ATTN_SMEM_BYTES>>>(edge, gat_att, gat_bias, out, write_alpha);

    void *ph=nullptr,*py0=nullptr,*py1=nullptr,*pz=nullptr,*pz1=nullptr,*pz2=nullptr;
    void *a0h,*a0l,*a1h,*a1l,*a2h,*a2l,*d1h,*d1l,*d2h,*d2l,*fh,*fl;
    cudaGetSymbolAddress(&ph,  g_h);  cudaGetSymbolAddress(&py0, g_y0);
    cudaGetSymbolAddress(&py1, g_y1); cudaGetSymbolAddress(&pz,  g_z);
    cudaGetSymbolAddress(&pz1, g_z1); cudaGetSymbolAddress(&pz2, g_z2);
    cudaGetSymbolAddress(&a0h, g_A0H); cudaGetSymbolAddress(&a0l, g_A0L);
    cudaGetSymbolAddress(&a1h, g_A1H); cudaGetSymbolAddress(&a1l, g_A1L);
    cudaGetSymbolAddress(&a2h, g_A2H); cudaGetSymbolAddress(&a2l, g_A2L);
    cudaGetSymbolAddress(&d1h, g_D1H); cudaGetSymbolAddress(&d1l, g_D1L);
    cudaGetSymbolAddress(&d2h, g_D2H); cudaGetSymbolAddress(&d2l, g_D2L);
    cudaGetSymbolAddress(&fh,  g_FH); cudaGetSymbolAddress(&fl,  g_FL);

    conv_mma<0><<<dim3(NB/2,1),512,CONV_SMEM>>>((const float*)ph,
        (const uint4*)a0h,(const uint4*)a0l,(const uint4*)a0h,(const uint4*)a0l,
        nullptr, ln0_w, ln0_b, (float*)py0);
    conv_mma<1><<<dim3(NB/2,2),512,CONV_SMEM>>>((const float*)py0,
        (const uint4*)a1h,(const uint4*)a1l,(const uint4*)d1h,(const uint4*)d1l,
        ds1_b, ln1_w, ln1_b, (float*)py1);
    conv_mma<2><<<dim3(NB/2,1),512,CONV_SMEM>>>((const float*)py1,
        (const uint4*)a2h,(const uint4*)a2l,(const uint4*)d2h,(const uint4*)d2l,
        ds2_b, ln2_w, ln2_b, (float*)pz);

    fc1_mma<<<dim3(16,2,SKF),512,FC1_SMEM>>>((const float*)pz, (const uint4*)fh, (const uint4*)fl);
    fc1red_kernel<<<(1024*512)/256,256>>>(fc1_b);

    gemm_kernel<<<dim3(256/64, NB/64),256>>>((const float*)pz1, fc2_w, fc2_b, (float*)pz2, NB, 256, 512, 1);
    gemm_kernel<<<dim3((144+63)/64, NB/64),256>>>((const float*)pz2, fc3_w, fc3_b, out, NB, 144, 256, 0);

    if (out_size >= EI_OFF + EI_LEN)
        ei_kernel<<<(ET+255)/256,256>>>(edge, out);
}

// round 14
// speedup vs baseline: 1.3310x; 1.0095x over previous
#include <cuda_runtime.h>
#include <cuda_bf16.h>
#include <cstdint>

#define NN   30
#define HH   4
#define CC   64
#define HC   256
#define FIN  64
#define NB   1024
#define EPG  240
#define NE   (NB*EPG)
#define NL   (NB*NN)
#define ET   (NE+NL)
#define EG   (EPG+NN)
#define OUT_LEN   (NB*144)
#define ALPHA_OFF OUT_LEN
#define ALPHA_LEN (ET*HH)
#define EI_OFF    (ALPHA_OFF+ALPHA_LEN)
#define EI_LEN    (2*ET)
#define LN_EPS 1e-5f
#define NSLOPE 0.2f
#define RS 40

typedef unsigned long long u64;

__device__ __forceinline__ void mma16816(float c[4], uint4 a, uint32_t b0, uint32_t b1){
    asm volatile("mma.sync.aligned.m16n8k16.row.col.f32.bf16.bf16.f32 "
        "{%0,%1,%2,%3},{%4,%5,%6,%7},{%8,%9},{%0,%1,%2,%3};"
        : "+f"(c[0]),"+f"(c[1]),"+f"(c[2]),"+f"(c[3])
        : "r"(a.x),"r"(a.y),"r"(a.z),"r"(a.w),"r"(b0),"r"(b1));
}

// ---------------- device scratch ----------------
__device__ float g_WlT[FIN*HC];
__device__ float g_WrT[FIN*HC];
__device__ float g_xl[NL*HC];
__device__ float g_xr[NL*HC];
__device__ float g_h [(size_t)NB*HC*RS];
__device__ float g_y0[(size_t)NB*256*RS];
__device__ float g_y1[(size_t)NB*512*RS];
__device__ float g_z [NB*HC*NN];
__device__ float g_z1[NB*512];
__device__ float g_z2[NB*256];
#define SKF 8
__device__ float g_p1[SKF*1024*512];

// A-fragment-packed weights (uint4 per lane per fragment), k-permuted for LDS.64 B loads
__device__ uint4 g_A0H[24576], g_A0L[24576];
__device__ uint4 g_A1H[49152], g_A1L[49152];
__device__ uint4 g_D1H[16384], g_D1L[16384];
__device__ uint4 g_A2H[49152], g_A2L[49152];
__device__ uint4 g_D2H[16384], g_D2L[16384];
__device__ uint4 g_FH[491520], g_FL[491520];   // fc1: 480 ksteps * 32 mtiles * 32 lanes

__device__ __forceinline__ uint32_t packbf(float v0, float v1, int lo){
    __nv_bfloat16 h0=__float2bfloat16(v0), h1=__float2bfloat16(v1);
    if (lo){ h0=__float2bfloat16(v0-__bfloat162float(h0)); h1=__float2bfloat16(v1-__bfloat162float(h1)); }
    return (uint32_t)__bfloat16_as_ushort(h0) | ((uint32_t)__bfloat16_as_ushort(h1)<<16);
}

__device__ void fill_convA(uint32_t* H, uint32_t* L, const float* w, int Cin, int MT, int nslots,
                           int t0, int stride)
{
    for (int i=t0;i<nslots;i+=stride){
        int q=i&3, lane=(i>>2)&31, mtg=(i>>7)%MT, kstep=i/(MT*128);
        int g=lane>>2, tc=lane&3;
        int m=mtg*16 + g + (q&1)*8;
        int kk=kstep*16 + tc*4 + (q>>1)*2;
        int t=kk/Cin, cin=kk-t*Cin;
        float v0=w[(m*Cin+cin)*3+t], v1=w[(m*Cin+cin+1)*3+t];
        H[i]=packbf(v0,v1,0); L[i]=packbf(v0,v1,1);
    }
}
__device__ void fill_dsA(uint32_t* H, uint32_t* L, const float* w, int Cin, int MT, int nslots,
                         int t0, int stride)
{
    for (int i=t0;i<nslots;i+=stride){
        int q=i&3, lane=(i>>2)&31, mtg=(i>>7)%MT, kstep=i/(MT*128);
        int g=lane>>2, tc=lane&3;
        int m=mtg*16 + g + (q&1)*8;
        int cin=kstep*16 + tc*4 + (q>>1)*2;
        float v0=w[m*Cin+cin], v1=w[m*Cin+cin+1];
        H[i]=packbf(v0,v1,0); L[i]=packbf(v0,v1,1);
    }
}

__global__ void prep_kernel(const float* __restrict__ Wl, const float* __restrict__ Wr,
                            const float* __restrict__ w0, const float* __restrict__ w1,
                            const float* __restrict__ w2, const float* __restrict__ d1,
                            const float* __restrict__ d2, const float* __restrict__ f1)
{
    int t0 = blockIdx.x*blockDim.x + threadIdx.x;
    int stride = gridDim.x*blockDim.x;
    for (int i=t0;i<FIN*HC;i+=stride){ int j=i%HC,k=i/HC; g_WlT[i]=Wl[j*FIN+k]; g_WrT[i]=Wr[j*FIN+k]; }
    fill_convA((uint32_t*)g_A0H,(uint32_t*)g_A0L, w0, 256, 16,  98304, t0, stride);
    fill_convA((uint32_t*)g_A1H,(uint32_t*)g_A1L, w1, 256, 32, 196608, t0, stride);
    fill_convA((uint32_t*)g_A2H,(uint32_t*)g_A2L, w2, 512, 16, 196608, t0, stride);
    fill_dsA  ((uint32_t*)g_D1H,(uint32_t*)g_D1L, d1, 256, 32,  65536, t0, stride);
    fill_dsA  ((uint32_t*)g_D2H,(uint32_t*)g_D2L, d2, 512, 16,  65536, t0, stride);
    fill_dsA  ((uint32_t*)g_FH, (uint32_t*)g_FL,  f1, 7680, 32, 1966080, t0, stride);
}

__global__ void __launch_bounds__(256) xform_kernel(const float* __restrict__ x,
                                                    const float* __restrict__ bl,
                                                    const float* __restrict__ br)
{
    __shared__ float xs[32*FIN];
    const int base = blockIdx.x*32;
    const int tid = threadIdx.x;
    for (int i=tid;i<32*FIN;i+=256) xs[i]=x[base*FIN+i];
    __syncthreads();
    float accl[32], accr[32];
#pragma unroll
    for (int n=0;n<32;n++){ accl[n]=0.f; accr[n]=0.f; }
    const int j = tid;
    for (int k=0;k<FIN;k++){
        float wl=g_WlT[k*HC+j], wr=g_WrT[k*HC+j];
#pragma unroll
        for (int n=0;n<32;n++){ float xv=xs[n*FIN+k]; accl[n]=fmaf(wl,xv,accl[n]); accr[n]=fmaf(wr,xv,accr[n]); }
    }
    float blv=bl[j], brv=br[j];
#pragma unroll
    for (int n=0;n<32;n++){
        g_xl[(base+n)*HC+j]=accl[n]+blv;
        g_xr[(base+n)*HC+j]=accr[n]+brv;
    }
}

#define ATTN_SMEM_BYTES (18272*4 + 901*4 + 16)
__global__ void __launch_bounds__(256) attn_kernel(const int* __restrict__ eidx,
                                                   const float* __restrict__ att,
                                                   const float* __restrict__ gbias,
                                                   float* __restrict__ out,
                                                   int write_alpha)
{
    extern __shared__ char smemraw[];
    float* xl_s   = (float*)smemraw;
    float* xr_s   = xl_s + 7680;
    float* att_s  = xr_s + 7680;
    float* bias_s = att_s + 256;
    float* esc    = bias_s + 256;
    float* alp    = esc + 1080;
    float* mmax   = alp + 1080;
    float* ssum   = mmax + 120;
    int*   srcl   = (int*)(ssum + 120);
    int*   dstl   = srcl + 270;
    int*   deg    = dstl + 270;
    int*   off    = deg + 30;
    int*   pos    = off + 31;
    int*   order  = pos + 30;
    const int b = blockIdx.x, tid = threadIdx.x;
    const int lane = tid&31, wrp = tid>>5;

    for (int i=tid;i<7680;i+=256){ xl_s[i]=g_xl[b*7680+i]; xr_s[i]=g_xr[b*7680+i]; }
    for (int i=tid;i<256;i+=256){ att_s[i]=att[i]; bias_s[i]=gbias[i]; }
    if (tid<30) deg[tid]=0;
    __syncthreads();
    for (int e=tid;e<EG;e+=256){
        int s,d;
        if (e<EPG){ s=eidx[b*EPG+e]-b*NN; d=eidx[NE+b*EPG+e]-b*NN; }
        else      { s=e-EPG; d=e-EPG; }
        srcl[e]=s; dstl[e]=d;
        atomicAdd(&deg[d],1);
    }
    __syncthreads();
    if (tid==0){ off[0]=0; for (int n=0;n<NN;n++) off[n+1]=off[n]+deg[n]; }
    __syncthreads();
    if (tid<30) pos[tid]=off[tid];
    __syncthreads();
    for (int e=tid;e<EG;e+=256){ int slot=atomicAdd(&pos[dstl[e]],1); order[slot]=e; }
    __syncthreads();

    for (int p=wrp; p<EG*HH; p+=8){
        int e=p>>2, h=p&3;
        const float* ps=&xl_s[srcl[e]*HC + h*CC];
        const float* pd=&xr_s[dstl[e]*HC + h*CC];
        const float* pa=&att_s[h*CC];
        float acc=0.f;
#pragma unroll
        for (int cc=0; cc<2; cc++){
            int c = lane + cc*32;
            float v = ps[c]+pd[c];
            v = v>0.f ? v : NSLOPE*v;
            acc = fmaf(v, pa[c], acc);
        }
        acc += __shfl_xor_sync(0xffffffffu, acc, 16);
        acc += __shfl_xor_sync(0xffffffffu, acc, 8);
        acc += __shfl_xor_sync(0xffffffffu, acc, 4);
        acc += __shfl_xor_sync(0xffffffffu, acc, 2);
        acc += __shfl_xor_sync(0xffffffffu, acc, 1);
        if (lane==0) esc[p]=acc;
    }
    __syncthreads();

    for (int idx=tid; idx<NN*HH; idx+=256){
        int n=idx>>2, h=idx&3;
        float m=-1e30f;
        for (int i=off[n];i<off[n+1];i++) m=fmaxf(m, esc[order[i]*HH+h]);
        float s=0.f;
        for (int i=off[n];i<off[n+1];i++) s+=__expf(esc[order[i]*HH+h]-m);
        mmax[idx]=m; ssum[idx]=s;
    }
    __syncthreads();
    for (int idx=tid; idx<EG*HH; idx+=256){
        int e=idx>>2, h=idx&3;
        int d=dstl[e];
        float a=__expf(esc[idx]-mmax[d*HH+h])/ssum[d*HH+h];
        alp[idx]=a;
        if (write_alpha){
            int gid = (e<EPG) ? (b*EPG+e) : (NE + b*NN + (e-EPG));
            out[ALPHA_OFF + gid*HH + h]=a;
        }
    }
    __syncthreads();
    {
        const int j = tid;
        const int h = j>>6;
        for (int n=0;n<NN;n++){
            float acc=0.f;
            for (int i=off[n];i<off[n+1];i++){
                int e=order[i];
                acc = fmaf(alp[e*HH+h], xl_s[srcl[e]*HC+j], acc);
            }
            float v=acc+bias_s[j];
            xr_s[j*NN+n]=fmaxf(v,0.f);
        }
    }
    __syncthreads();
    for (int i=tid;i<256*RS;i+=256){
        int c=i/RS, col=i-c*RS;
        float v = (col>=4 && col<34) ? xr_s[c*NN + col-4] : 0.f;
        g_h[(size_t)b*256*RS + i]=v;
    }
}

// ================= conv layer 0: 256 threads, 4 mtiles/warp =================
#define CS 272
#define CONV_SMEM (2*2*40*CS*2)   // 87040B

__global__ void __launch_bounds__(256,2) conv0_mma(
    const float* __restrict__ in,
    const uint4* __restrict__ AH, const uint4* __restrict__ AL,
    const float* __restrict__ lnw, const float* __restrict__ lnb,
    float* __restrict__ outp)
{
    extern __shared__ __nv_bfloat16 sm_bf[];
    __nv_bfloat16* sH = sm_bf;
    __nv_bfloat16* sL = sm_bf + 2*40*CS;
    __shared__ float s_lnw[32], s_lnb[32];

    const int tid=threadIdx.x, lane=tid&31, wid=tid>>5;
    const int g=lane>>2, tc=lane&3;
    const int b0=blockIdx.x*2;
    const int nhalf = wid&1;
    const int mtp   = wid>>1;       // 0..3, 4 mtiles each

    if (tid<30){ s_lnw[tid]=lnw[tid]; s_lnb[tid]=lnb[tid]; }

    for (int idx=tid; idx<2*256*RS; idx+=256){
        int gr = idx/(256*RS);
        int r  = idx - gr*256*RS;
        int c  = r/RS;
        int l  = r - c*RS;
        float v = in[(((size_t)(b0+gr))*256 + c)*RS + l];
        __nv_bfloat16 h=__float2bfloat16(v);
        int sidx=(gr*40+l)*CS+c;
        sH[sidx]=h;
        sL[sidx]=__float2bfloat16(v-__bfloat162float(h));
    }
    __syncthreads();

    float acc[4][4][4];
#pragma unroll
    for (int i=0;i<4;i++)
#pragma unroll
        for (int f=0;f<4;f++)
#pragma unroll
            for (int q=0;q<4;q++) acc[i][f][q]=0.f;

    const int sb0 = (nhalf*40 + 4 + g)*CS + tc*4;
    int abase = (mtp*4)*32 + lane;
    uint4 ah[4];
#pragma unroll
    for (int i=0;i<4;i++) ah[i]=AH[abase+32*i];

#pragma unroll
    for (int t=0;t<3;t++){
        const int srow = sb0 + (t-1)*CS;
        for (int ch=0; ch<16; ch++){
            uint4 al4[4];
#pragma unroll
            for (int i=0;i<4;i++) al4[i]=AL[abase+32*i];
            uint2 BH[4], BL[4];
#pragma unroll
            for (int f=0;f<4;f++){
                BH[f]=*(const uint2*)(sH + srow + f*(8*CS) + ch*16);
                BL[f]=*(const uint2*)(sL + srow + f*(8*CS) + ch*16);
            }
            // wave 1: ah x BH
#pragma unroll
            for (int f=0;f<4;f++)
#pragma unroll
                for (int i=0;i<4;i++) mma16816(acc[i][f], ah[i], BH[f].x,BH[f].y);
            // wave 3: ah x BL
#pragma unroll
            for (int f=0;f<4;f++)
#pragma unroll
                for (int i=0;i<4;i++) mma16816(acc[i][f], ah[i], BL[f].x,BL[f].y);
            // advance + reload ah for next kstep (covered by wave 2)
            abase += ((t*16+ch)<47)? 512 : 0;
#pragma unroll
            for (int i=0;i<4;i++) ah[i]=AH[abase+32*i];
            // wave 2: al x BH
#pragma unroll
            for (int f=0;f<4;f++)
#pragma unroll
                for (int i=0;i<4;i++) mma16816(acc[i][f], al4[i], BH[f].x,BH[f].y);
        }
    }

    // ---- epilogue ----
    const int gr = nhalf;
#pragma unroll
    for (int mt=0; mt<4; mt++){
#pragma unroll
        for (int half=0; half<2; half++){
            const int mrow = (mtp*4+mt)*16 + g + half*8;
            float s=0.f;
#pragma unroll
            for (int f=0; f<4; f++)
#pragma unroll
                for (int i=0;i<2;i++){
                    int l=f*8+tc*2+i;
                    if (l<30) s+=acc[mt][f][half*2+i];
                }
            s += __shfl_xor_sync(0xffffffffu,s,1);
            s += __shfl_xor_sync(0xffffffffu,s,2);
            float mean = s*(1.f/30.f);
            float qv=0.f;
#pragma unroll
            for (int f=0; f<4; f++)
#pragma unroll
                for (int i=0;i<2;i++){
                    int l=f*8+tc*2+i;
                    if (l<30){ float d=acc[mt][f][half*2+i]-mean; qv=fmaf(d,d,qv); }
                }
            qv += __shfl_xor_sync(0xffffffffu,qv,1);
            qv += __shfl_xor_sync(0xffffffffu,qv,2);
            float rsn = rsqrtf(qv*(1.f/30.f)+LN_EPS);

            size_t rb = (((size_t)(b0+gr))*256 + mrow)*(size_t)RS;
#pragma unroll
            for (int f=0; f<4; f++){
                int l0=f*8+tc*2;
                if (l0>=30) continue;
                float v=(acc[mt][f][half*2+0]-mean)*rsn*s_lnw[l0]+s_lnb[l0];
                float o0=fmaxf(v,0.f);
                v=(acc[mt][f][half*2+1]-mean)*rsn*s_lnw[l0+1]+s_lnb[l0+1];
                float o1=fmaxf(v,0.f);
                float2 res=*(const float2*)&in[(((size_t)(b0+gr))*256 + mrow)*RS + 4 + l0];
                o0+=res.x; o1+=res.y;
                *(float2*)&outp[rb+4+l0] = make_float2(o0,o1);
            }
            if (tc==0) *(float4*)&outp[rb] = make_float4(0.f,0.f,0.f,0.f);
            if (tc==3){
                *(float2*)&outp[rb+34]=make_float2(0.f,0.f);
                *(float4*)&outp[rb+36]=make_float4(0.f,0.f,0.f,0.f);
            }
        }
    }
}

// ================= mma.sync TCN conv layers 1/2 (512 thr) =================
template<int MODE>
__global__ void __launch_bounds__(512,1) conv_mma(
    const float* __restrict__ in,
    const uint4* __restrict__ AH, const uint4* __restrict__ AL,
    const uint4* __restrict__ DH, const uint4* __restrict__ DL,
    const float* __restrict__ db,
    const float* __restrict__ lnw, const float* __restrict__ lnb,
    float* __restrict__ outp)
{
    constexpr int Cin   = (MODE==2)?512:256;
    constexpr int COUT  = (MODE==1)?512:256;
    constexpr int MT    = (MODE==1)?32:16;
    constexpr int PH    = (MODE==2)?2:1;
    constexpr int DIL   = (MODE==1)?2:4;
    constexpr int KS_T  = Cin/16;

    extern __shared__ __nv_bfloat16 sm_bf[];
    __nv_bfloat16* sH = sm_bf;
    __nv_bfloat16* sL = sm_bf + 2*40*CS;
    __shared__ float s_lnw[32], s_lnb[32];

    const int tid=threadIdx.x, lane=tid&31, wid=tid>>5;
    const int g=lane>>2, tc=lane&3;
    const int b0=blockIdx.x*2;
    const int mp=blockIdx.y;
    const int nhalf = wid&1;
    const int mtp   = wid>>1;

    if (tid<30){ s_lnw[tid]=lnw[tid]; s_lnb[tid]=lnb[tid]; }

    float acc[2][4][4];
    float dsacc[2][4][4];
#pragma unroll
    for (int a=0;a<2;a++)
#pragma unroll
        for (int f=0;f<4;f++)
#pragma unroll
            for (int q=0;q<4;q++){ acc[a][f][q]=0.f; dsacc[a][f][q]=0.f; }

    for (int ph=0; ph<PH; ph++){
        if (ph>0) __syncthreads();
        for (int idx=tid; idx<2*256*RS; idx+=512){
            int gr = idx/(256*RS);
            int r  = idx - gr*256*RS;
            int c  = r/RS;
            int l  = r - c*RS;
            float v = in[(((size_t)(b0+gr))*Cin + ph*256 + c)*RS + l];
            __nv_bfloat16 h=__float2bfloat16(v);
            int sidx=(gr*40+l)*CS+c;
            sH[sidx]=h;
            sL[sidx]=__float2bfloat16(v-__bfloat162float(h));
        }
        __syncthreads();

        const int mtile0 = mp*16 + mtp*2;
        const int sb0 = (nhalf*40 + 4 + g)*CS + tc*4;

#pragma unroll
        for (int t=0;t<3;t++){
            int abase = ((t*KS_T + ph*16)*MT + mtile0)*32 + lane;
            const int srow = sb0 + DIL*(t-1)*CS;
            if (t==1){
                int dbase = ((ph*16)*MT + mtile0)*32 + lane;
                for (int ch=0; ch<16; ch++){
                    uint4 ah0=AH[abase], ah1=AH[abase+32], al0=AL[abase], al1=AL[abase+32];
                    uint4 dh0=DH[dbase], dh1=DH[dbase+32], dl0=DL[dbase], dl1=DL[dbase+32];
                    uint2 BH[4], BL[4];
#pragma unroll
                    for (int f=0;f<4;f++){
                        BH[f]=*(const uint2*)(sH + srow + f*(8*CS) + ch*16);
                        BL[f]=*(const uint2*)(sL + srow + f*(8*CS) + ch*16);
                    }
#pragma unroll
                    for (int f=0;f<4;f++){
                        mma16816(acc[0][f], ah0, BH[f].x,BH[f].y);
                        mma16816(acc[1][f], ah1, BH[f].x,BH[f].y);
                    }
#pragma unroll
                    for (int f=0;f<4;f++){
                        mma16816(dsacc[0][f], dh0, BH[f].x,BH[f].y);
                        mma16816(dsacc[1][f], dh1, BH[f].x,BH[f].y);
                    }
#pragma unroll
                    for (int f=0;f<4;f++){
                        mma16816(acc[0][f], al0, BH[f].x,BH[f].y);
                        mma16816(acc[1][f], al1, BH[f].x,BH[f].y);
                    }
#pragma unroll
                    for (int f=0;f<4;f++){
                        mma16816(dsacc[0][f], dl0, BH[f].x,BH[f].y);
                        mma16816(dsacc[1][f], dl1, BH[f].x,BH[f].y);
                    }
#pragma unroll
                    for (int f=0;f<4;f++){
                        mma16816(acc[0][f], ah0, BL[f].x,BL[f].y);
                        mma16816(acc[1][f], ah1, BL[f].x,BL[f].y);
                    }
#pragma unroll
                    for (int f=0;f<4;f++){
                        mma16816(dsacc[0][f], dh0, BL[f].x,BL[f].y);
                        mma16816(dsacc[1][f], dh1, BL[f].x,BL[f].y);
                    }
                    abase += MT*32; dbase += MT*32;
                }
            } else {
                uint4 ah0=AH[abase], ah1=AH[abase+32], al0=AL[abase], al1=AL[abase+32];
                for (int ch=0; ch<16; ch++){
                    uint2 BH[4], BL[4];
#pragma unroll
                    for (int f=0;f<4;f++){
                        BH[f]=*(const uint2*)(sH + srow + f*(8*CS) + ch*16);
                        BL[f]=*(const uint2*)(sL + srow + f*(8*CS) + ch*16);
                    }
                    int nbase = abase + ((ch<15)? MT*32 : 0);
                    uint4 nh0=AH[nbase], nh1=AH[nbase+32], nl0=AL[nbase], nl1=AL[nbase+32];
#pragma unroll
                    for (int f=0;f<4;f++){
                        mma16816(acc[0][f], ah0, BH[f].x,BH[f].y);
                        mma16816(acc[1][f], ah1, BH[f].x,BH[f].y);
                    }
#pragma unroll
                    for (int f=0;f<4;f++){
                        mma16816(acc[0][f], al0, BH[f].x,BH[f].y);
                        mma16816(acc[1][f], al1, BH[f].x,BH[f].y);
                    }
#pragma unroll
                    for (int f=0;f<4;f++){
                        mma16816(acc[0][f], ah0, BL[f].x,BL[f].y);
                        mma16816(acc[1][f], ah1, BL[f].x,BL[f].y);
                    }
                    abase=nbase; ah0=nh0; ah1=nh1; al0=nl0; al1=nl1;
                }
            }
        }
    }

    // ---- epilogue ----
    const int gr = nhalf;
#pragma unroll
    for (int mt=0; mt<2; mt++){
        const int mrow0 = mp*256 + (mtp*2+mt)*16 + g;
#pragma unroll
        for (int half=0; half<2; half++){
            const int mrow = mrow0 + half*8;
            float dbv = __ldg(&db[mrow]);
            float s=0.f;
#pragma unroll
            for (int f=0; f<4; f++)
#pragma unroll
                for (int i=0;i<2;i++){
                    int l=f*8+tc*2+i;
                    if (l<30) s+=acc[mt][f][half*2+i];
                }
            s += __shfl_xor_sync(0xffffffffu,s,1);
            s += __shfl_xor_sync(0xffffffffu,s,2);
            float mean = s*(1.f/30.f);
            float qv=0.f;
#pragma unroll
            for (int f=0; f<4; f++)
#pragma unroll
                for (int i=0;i<2;i++){
                    int l=f*8+tc*2+i;
                    if (l<30){ float d=acc[mt][f][half*2+i]-mean; qv=fmaf(d,d,qv); }
                }
            qv += __shfl_xor_sync(0xffffffffu,qv,1);
            qv += __shfl_xor_sync(0xffffffffu,qv,2);
            float rsn = rsqrtf(qv*(1.f/30.f)+LN_EPS);

            size_t rb;
            if constexpr(MODE==2) rb = (((size_t)(b0+gr))*256 + mrow)*(size_t)NN;
            else                  rb = (((size_t)(b0+gr))*COUT + mrow)*(size_t)RS;
#pragma unroll
            for (int f=0; f<4; f++){
                int l0=f*8+tc*2;
                if (l0>=30) continue;
                float v=(acc[mt][f][half*2+0]-mean)*rsn*s_lnw[l0]+s_lnb[l0];
                float o0=fmaxf(v,0.f);
                v=(acc[mt][f][half*2+1]-mean)*rsn*s_lnw[l0+1]+s_lnb[l0+1];
                float o1=fmaxf(v,0.f);
                o0 += dsacc[mt][f][half*2+0] + dbv;
                o1 += dsacc[mt][f][half*2+1] + dbv;
                if constexpr(MODE==2) *(float2*)&outp[rb+l0]   = make_float2(o0,o1);
                else                  *(float2*)&outp[rb+4+l0] = make_float2(o0,o1);
            }
            if constexpr(MODE!=2){
                if (tc==0) *(float4*)&outp[rb] = make_float4(0.f,0.f,0.f,0.f);
                if (tc==3){
                    *(float2*)&outp[rb+34]=make_float2(0.f,0.f);
                    *(float4*)&outp[rb+36]=make_float4(0.f,0.f,0.f,0.f);
                }
            }
        }
    }
}

// ================= fc1: bf16 hi/lo mma GEMM, split-K=8 =================
#define FC1_SMEM (2*64*240*2)   // 61440B
__global__ void __launch_bounds__(512,1) fc1_mma(
    const float* __restrict__ Z,
    const uint4* __restrict__ FH, const uint4* __restrict__ FL)
{
    extern __shared__ __nv_bfloat16 sm[];
    __nv_bfloat16* sH = sm;
    __nv_bfloat16* sL = sm + 64*240;
    const int tid=threadIdx.x, lane=tid&31, wid=tid>>5;
    const int g=lane>>2, tc=lane&3;
    const int nb0 = blockIdx.x*64;
    const int cb0 = blockIdx.y*256;
    const int kz  = blockIdx.z;
    const int nhalf = wid&1, mtp = wid>>1;
    const int mtile0 = (cb0>>4) + mtp*2;

    float acc[2][4][4];
#pragma unroll
    for (int a=0;a<2;a++)
#pragma unroll
        for (int f=0;f<4;f++)
#pragma unroll
            for (int q=0;q<4;q++) acc[a][f][q]=0.f;

    for (int chunk=0; chunk<4; chunk++){
        if (chunk>0) __syncthreads();
        for (int idx=tid; idx<3840; idx+=512){
            int row = idx/60, c4 = idx-row*60;
            float4 v = *(const float4*)&Z[(size_t)(nb0+row)*7680 + kz*960 + chunk*240 + c4*4];
            __nv_bfloat16 h0=__float2bfloat16(v.x), h1=__float2bfloat16(v.y);
            __nv_bfloat16 h2=__float2bfloat16(v.z), h3=__float2bfloat16(v.w);
            __nv_bfloat16* ph = sH + row*240 + c4*4;
            __nv_bfloat16* pl = sL + row*240 + c4*4;
            ph[0]=h0; ph[1]=h1; ph[2]=h2; ph[3]=h3;
            pl[0]=__float2bfloat16(v.x-__bfloat162float(h0));
            pl[1]=__float2bfloat16(v.y-__bfloat162float(h1));
            pl[2]=__float2bfloat16(v.z-__bfloat162float(h2));
            pl[3]=__float2bfloat16(v.w-__bfloat162float(h3));
        }
        __syncthreads();

        int abase = ((kz*60 + chunk*15)*32 + mtile0)*32 + lane;
        uint4 ah0=FH[abase], ah1=FH[abase+32], al0=FL[abase], al1=FL[abase+32];
        const int sb0 = (nhalf*32 + g)*240 + tc*4;
        for (int ch=0; ch<15; ch++){
            uint2 BH[4], BL[4];
#pragma unroll
            for (int f=0;f<4;f++){
                BH[f]=*(const uint2*)(sH + sb0 + f*(8*240) + ch*16);
                BL[f]=*(const uint2*)(sL + sb0 + f*(8*240) + ch*16);
            }
            int nbase = abase + ((ch<14)? 1024 : 0);
            uint4 nh0=FH[nbase], nh1=FH[nbase+32], nl0=FL[nbase], nl1=FL[nbase+32];
#pragma unroll
            for (int f=0;f<4;f++){
                mma16816(acc[0][f], ah0, BH[f].x,BH[f].y);
                mma16816(acc[1][f], ah1, BH[f].x,BH[f].y);
            }
#pragma unroll
            for (int f=0;f<4;f++){
                mma16816(acc[0][f], al0, BH[f].x,BH[f].y);
                mma16816(acc[1][f], al1, BH[f].x,BH[f].y);
            }
#pragma unroll
            for (int f=0;f<4;f++){
                mma16816(acc[0][f], ah0, BL[f].x,BL[f].y);
                mma16816(acc[1][f], ah1, BL[f].x,BL[f].y);
            }
            abase=nbase; ah0=nh0; ah1=nh1; al0=nl0; al1=nl1;
        }
    }

    float* dst = &g_p1[(size_t)kz*1024*512];
#pragma unroll
    for (int mt=0; mt<2; mt++){
        const int co = cb0 + (mtp*2+mt)*16 + g;
#pragma unroll
        for (int f=0; f<4; f++){
            const int bc = nb0 + nhalf*32 + f*8 + tc*2;
            dst[(size_t)bc*512 + co]       = acc[mt][f][0];
            dst[(size_t)(bc+1)*512 + co]   = acc[mt][f][1];
            dst[(size_t)bc*512 + co + 8]   = acc[mt][f][2];
            dst[(size_t)(bc+1)*512 + co+8] = acc[mt][f][3];
        }
    }
}

__global__ void fc1red_kernel(const float* __restrict__ bias)
{
    int i=blockIdx.x*blockDim.x+threadIdx.x;
    float s=0.f;
#pragma unroll
    for (int k=0;k<SKF;k++) s+=g_p1[(size_t)k*524288 + i];
    s+=bias[i&511];
    g_z1[i]=fmaxf(s,0.f);
}

__global__ void __launch_bounds__(256) gemm_kernel(const float* __restrict__ A,
                                                   const float* __restrict__ W,
                                                   const float* __restrict__ bias,
                                                   float* __restrict__ C,
                                                   int M, int N, int K, int relu)
{
    __shared__ float sA[64][17];
    __shared__ float sW[64][17];
    const int tid=threadIdx.x;
    const int m0=blockIdx.y*64, n0=blockIdx.x*64;
    const int tr=(tid/16)*4, tc=(tid%16)*4;
    float acc[4][4];
#pragma unroll
    for (int i=0;i<4;i++)
#pragma unroll
        for (int j=0;j<4;j++) acc[i][j]=0.f;
    for (int k0=0;k0<K;k0+=16){
        for (int i=tid;i<1024;i+=256){
            int k=i&15, r=i>>4;
            int gm=m0+r, gk=k0+k;
            sA[r][k]=(gm<M && gk<K)? A[gm*K+gk] : 0.f;
            int gn=n0+r;
            sW[r][k]=(gn<N && gk<K)? W[gn*K+gk] : 0.f;
        }
        __syncthreads();
#pragma unroll
        for (int k=0;k<16;k++){
            float a[4], w[4];
#pragma unroll
            for (int i=0;i<4;i++) a[i]=sA[tr+i][k];
#pragma unroll
            for (int j=0;j<4;j++) w[j]=sW[tc+j][k];
#pragma unroll
            for (int i=0;i<4;i++)
#pragma unroll
                for (int j=0;j<4;j++) acc[i][j]=fmaf(a[i],w[j],acc[i][j]);
        }
        __syncthreads();
    }
#pragma unroll
    for (int i=0;i<4;i++){
        int gm=m0+tr+i;
        if (gm>=M) continue;
#pragma unroll
        for (int j=0;j<4;j++){
            int gn=n0+tc+j;
            if (gn>=N) continue;
            float v=acc[i][j]+bias[gn];
            if (relu) v=fmaxf(v,0.f);
            C[gm*N+gn]=v;
        }
    }
}

__global__ void ei_kernel(const int* __restrict__ eidx, float* __restrict__ out)
{
    int e=blockIdx.x*blockDim.x+threadIdx.x;
    if (e>=ET) return;
    int s,d;
    if (e<NE){ s=eidx[e]; d=eidx[NE+e]; }
    else { s=e-NE; d=e-NE; }
    out[EI_OFF+e]    =(float)s;
    out[EI_OFF+ET+e] =(float)d;
}

extern "C" void kernel_launch(void* const* d_in, const int* in_sizes, int n_in,
                              void* d_out, int out_size)
{
    const float* x      =(const float*)d_in[0];
    const float* gat_Wl =(const float*)d_in[1];
    const float* gat_bl =(const float*)d_in[2];
    const float* gat_Wr =(const float*)d_in[3];
    const float* gat_br =(const float*)d_in[4];
    const float* gat_att=(const float*)d_in[5];
    const float* gat_bias=(const float*)d_in[6];
    const float* tcn0_w =(const float*)d_in[7];
    const float* ln0_w  =(const float*)d_in[9];
    const float* ln0_b  =(const float*)d_in[10];
    const float* tcn1_w =(const float*)d_in[11];
    const float* ln1_w  =(const float*)d_in[13];
    const float* ln1_b  =(const float*)d_in[14];
    const float* ds1_w  =(const float*)d_in[15];
    const float* ds1_b  =(const float*)d_in[16];
    const float* tcn2_w =(const float*)d_in[17];
    const float* ln2_w  =(const float*)d_in[19];
    const float* ln2_b  =(const float*)d_in[20];
    const float* ds2_w  =(const float*)d_in[21];
    const float* ds2_b  =(const float*)d_in[22];
    const float* fc1_w  =(const float*)d_in[23];
    const float* fc1_b  =(const float*)d_in[24];
    const float* fc2_w  =(const float*)d_in[25];
    const float* fc2_b  =(const float*)d_in[26];
    const float* fc3_w  =(const float*)d_in[27];
    const float* fc3_b  =(const float*)d_in[28];
    const int*   edge   =(const int*)d_in[29];
    float* out=(float*)d_out;

    cudaFuncSetAttribute(attn_kernel, cudaFuncAttributeMaxDynamicSharedMemorySize, ATTN_SMEM_BYTES);
    cudaFuncSetAttribute(conv0_mma,   cudaFuncAttributeMaxDynamicSharedMemorySize, CONV_SMEM);
    cudaFuncSetAttribute(conv_mma<1>, cudaFuncAttributeMaxDynamicSharedMemorySize, CONV_SMEM);
    cudaFuncSetAttribute(conv_mma<2>, cudaFuncAttributeMaxDynamicSharedMemorySize, CONV_SMEM);
    cudaFuncSetAttribute(fc1_mma,     cudaFuncAttributeMaxDynamicSharedMemorySize, FC1_SMEM);

    prep_kernel<<<1024,256>>>(gat_Wl, gat_Wr, tcn0_w, tcn1_w, tcn2_w, ds1_w, ds2_w, fc1_w);
    xform_kernel<<<NL/32,256>>>(x, gat_bl, gat_br);

    int write_alpha = (out_size >= ALPHA_OFF + ALPHA_LEN) ? 1 : 0;
    attn_kernel<<<NB,256,ATTN_SMEM_BYTES>>>(edge, gat_att, gat_bias, out, write_alpha);

    void *ph=nullptr,*py0=nullptr,*py1=nullptr,*pz=nullptr,*pz1=nullptr,*pz2=nullptr;
    void *a0h,*a0l,*a1h,*a1l,*a2h,*a2l,*d1h,*d1l,*d2h,*d2l,*fh,*fl;
    cudaGetSymbolAddress(&ph,  g_h);  cudaGetSymbolAddress(&py0, g_y0);
    cudaGetSymbolAddress(&py1, g_y1); cudaGetSymbolAddress(&pz,  g_z);
    cudaGetSymbolAddress(&pz1, g_z1); cudaGetSymbolAddress(&pz2, g_z2);
    cudaGetSymbolAddress(&a0h, g_A0H); cudaGetSymbolAddress(&a0l, g_A0L);
    cudaGetSymbolAddress(&a1h, g_A1H); cudaGetSymbolAddress(&a1l, g_A1L);
    cudaGetSymbolAddress(&a2h, g_A2H); cudaGetSymbolAddress(&a2l, g_A2L);
    cudaGetSymbolAddress(&d1h, g_D1H); cudaGetSymbolAddress(&d1l, g_D1L);
    cudaGetSymbolAddress(&d2h, g_D2H); cudaGetSymbolAddress(&d2l, g_D2L);
    cudaGetSymbolAddress(&fh,  g_FH); cudaGetSymbolAddress(&fl,  g_FL);

    conv0_mma<<<NB/2,256,CONV_SMEM>>>((const float*)ph,
        (const uint4*)a0h,(const uint4*)a0l, ln0_w, ln0_b, (float*)py0);
    conv_mma<1><<<dim3(NB/2,2),512,CONV_SMEM>>>((const float*)py0,
        (const uint4*)a1h,(const uint4*)a1l,(const uint4*)d1h,(const uint4*)d1l,
        ds1_b, ln1_w, ln1_b, (float*)py1);
    conv_mma<2><<<dim3(NB/2,1),512,CONV_SMEM>>>((const float*)py1,
        (const uint4*)a2h,(const uint4*)a2l,(const uint4*)d2h,(const uint4*)d2l,
        ds2_b, ln2_w, ln2_b, (float*)pz);

    fc1_mma<<<dim3(16,2,SKF),512,FC1_SMEM>>>((const float*)pz, (const uint4*)fh, (const uint4*)fl);
    fc1red_kernel<<<(1024*512)/256,256>>>(fc1_b);

    gemm_kernel<<<dim3(256/64, NB/64),256>>>((const float*)pz1, fc2_w, fc2_b, (float*)pz2, NB, 256, 512, 1);
    gemm_kernel<<<dim3((144+63)/64, NB/64),256>>>((const float*)pz2, fc3_w, fc3_b, out, NB, 144, 256, 0);

    if (out_size >= EI_OFF + EI_LEN)
        ei_kernel<<<(ET+255)/256,256>>>(edge, out);
}